// round 1
// baseline (speedup 1.0000x reference)
#include <cuda_runtime.h>
#include <cuda_bf16.h>
#include <math.h>

// Problem constants
#define BATCH 4
#define SEQ 2048
#define DMODEL 1024
#define NHEADS 16
#define HDIM 64
#define NROWS (BATCH * SEQ)          // 8192
#define QKV_N (3 * DMODEL)           // 3072

// Scratch (device globals — no dynamic allocation allowed)
__device__ float g_Q[BATCH * NHEADS * SEQ * HDIM];     // [b][h][s][d]
__device__ float g_K[BATCH * NHEADS * SEQ * HDIM];
__device__ float g_V[BATCH * NHEADS * SEQ * HDIM];
__device__ float g_attn[NROWS * DMODEL];               // [b*s][h*HDIM]
__device__ float g_rope_cos[SEQ * 32];
__device__ float g_rope_sin[SEQ * 32];

// ---------------------------------------------------------------------------
// Kernel 0: RoPE table precompute. ang(s,i) = s * 10000^(-i/32), i in [0,32)
// ---------------------------------------------------------------------------
__global__ void rope_table_kernel() {
    int idx = blockIdx.x * blockDim.x + threadIdx.x;
    if (idx >= SEQ * 32) return;
    int s = idx >> 5;
    int i = idx & 31;
    float inv_freq = powf(10000.0f, -(float)i / 32.0f);
    float ang = (float)s * inv_freq;
    float sn, cs;
    sincosf(ang, &sn, &cs);
    g_rope_cos[idx] = cs;
    g_rope_sin[idx] = sn;
}

// ---------------------------------------------------------------------------
// Kernel 1: QKV GEMM (NT: C[m,n] = sum_k X[m,k] * W[n,k] + b[n]), fused RoPE
// epilogue + scatter into g_Q/g_K/g_V ([B,H,S,Dh]).
// Tile: BM=128, BN=64 (exactly one head slice of one of q/k/v), BK=16.
// 256 threads, 8x4 register microtile.
// ---------------------------------------------------------------------------
#define GBM 128
#define GBN 64
#define GBK 16

__global__ __launch_bounds__(256) void qkv_gemm_kernel(
    const float* __restrict__ X, const float* __restrict__ W,
    const float* __restrict__ bias)
{
    __shared__ float As[GBK][GBM + 4];
    __shared__ float Bs[GBK][GBN + 4];

    int tid = threadIdx.x;
    int tx = tid & 15;       // n direction: 4 cols
    int ty = tid >> 4;       // m direction: 8 rows
    int m0 = blockIdx.x * GBM;
    int n0 = blockIdx.y * GBN;

    // Global load mapping
    int a_r = tid >> 1;              // 0..127
    int a_c = (tid & 1) * 8;         // 0 or 8
    int b_r = tid >> 2;              // 0..63
    int b_c = (tid & 3) * 4;         // 0,4,8,12

    const float* Aptr = X + (size_t)(m0 + a_r) * DMODEL + a_c;
    const float* Bptr = W + (size_t)(n0 + b_r) * DMODEL + b_c;

    float acc[8][4];
#pragma unroll
    for (int i = 0; i < 8; i++)
#pragma unroll
        for (int j = 0; j < 4; j++) acc[i][j] = 0.f;

    for (int k0 = 0; k0 < DMODEL; k0 += GBK) {
        float4 av0 = *(const float4*)(Aptr + k0);
        float4 av1 = *(const float4*)(Aptr + k0 + 4);
        float4 bv  = *(const float4*)(Bptr + k0);
        __syncthreads();
        As[a_c + 0][a_r] = av0.x; As[a_c + 1][a_r] = av0.y;
        As[a_c + 2][a_r] = av0.z; As[a_c + 3][a_r] = av0.w;
        As[a_c + 4][a_r] = av1.x; As[a_c + 5][a_r] = av1.y;
        As[a_c + 6][a_r] = av1.z; As[a_c + 7][a_r] = av1.w;
        Bs[b_c + 0][b_r] = bv.x;  Bs[b_c + 1][b_r] = bv.y;
        Bs[b_c + 2][b_r] = bv.z;  Bs[b_c + 3][b_r] = bv.w;
        __syncthreads();
#pragma unroll
        for (int kk = 0; kk < GBK; kk++) {
            float a[8], b[4];
            *(float4*)(a)     = *(const float4*)&As[kk][ty * 8];
            *(float4*)(a + 4) = *(const float4*)&As[kk][ty * 8 + 4];
            *(float4*)(b)     = *(const float4*)&Bs[kk][tx * 4];
#pragma unroll
            for (int i = 0; i < 8; i++)
#pragma unroll
                for (int j = 0; j < 4; j++) acc[i][j] += a[i] * b[j];
        }
    }

    // Epilogue: bias + (optional) RoPE + scatter
    int which = n0 / DMODEL;         // 0=q,1=k,2=v
    int rem   = n0 % DMODEL;
    int h     = rem / HDIM;          // head
    // column within head: d = tx*4 + j (n0 is HDIM-aligned)
    float bvals[4];
#pragma unroll
    for (int j = 0; j < 4; j++) bvals[j] = bias[n0 + tx * 4 + j];

    if (which == 2) {
#pragma unroll
        for (int i = 0; i < 8; i++) {
            int mrow = m0 + ty * 8 + i;
            int b = mrow >> 11;        // /2048
            int s = mrow & 2047;
            float4 w;
            w.x = acc[i][0] + bvals[0];
            w.y = acc[i][1] + bvals[1];
            w.z = acc[i][2] + bvals[2];
            w.w = acc[i][3] + bvals[3];
            float* dst = g_V + ((size_t)((b * NHEADS + h) * SEQ + s) << 6) + tx * 4;
            *(float4*)dst = w;
        }
    } else {
        float* base = (which == 0) ? g_Q : g_K;
        bool lower = (tx < 8);       // d < 32
#pragma unroll
        for (int i = 0; i < 8; i++) {
            int mrow = m0 + ty * 8 + i;
            int b = mrow >> 11;
            int s = mrow & 2047;
            float out[4];
#pragma unroll
            for (int j = 0; j < 4; j++) {
                float val = acc[i][j] + bvals[j];
                float prt = __shfl_xor_sync(0xffffffffu, val, 8);
                int ifq = ((tx & 7) << 2) + j;       // d % 32
                float cs = g_rope_cos[s * 32 + ifq];
                float sn = g_rope_sin[s * 32 + ifq];
                float rot = lower ? -prt : prt;
                out[j] = val * cs + rot * sn;
            }
            float* dst = base + ((size_t)((b * NHEADS + h) * SEQ + s) << 6) + tx * 4;
            *(float4*)dst = *(float4*)out;
        }
    }
}

// ---------------------------------------------------------------------------
// Kernel 2: flash attention. Grid (SEQ/128, B*H). 128 threads; each thread
// owns one query row entirely (q[64], o[64] in registers). KV tiles of 64
// rows staged in SMEM; broadcast vec4 reads.
// ---------------------------------------------------------------------------
__global__ __launch_bounds__(128) void attn_kernel()
{
    __shared__ float Ks[64][64];
    __shared__ float Vs[64][64];

    int bh  = blockIdx.y;                        // 0..63
    int row = blockIdx.x * 128 + threadIdx.x;    // 0..2047

    const float* qptr = g_Q + ((size_t)bh * SEQ + row) * HDIM;
    float q[64];
#pragma unroll
    for (int d = 0; d < 64; d += 4)
        *(float4*)&q[d] = *(const float4*)(qptr + d);
#pragma unroll
    for (int d = 0; d < 64; d++) q[d] *= 0.125f;   // 1/sqrt(64)

    float o[64];
#pragma unroll
    for (int d = 0; d < 64; d++) o[d] = 0.f;
    float m = -1e30f, l = 0.f;

    const float* kbase = g_K + (size_t)bh * SEQ * HDIM;
    const float* vbase = g_V + (size_t)bh * SEQ * HDIM;

    for (int t = 0; t < SEQ; t += 64) {
        __syncthreads();
        const float4* ksrc = (const float4*)(kbase + (size_t)t * HDIM);
        const float4* vsrc = (const float4*)(vbase + (size_t)t * HDIM);
        float4* kdst = (float4*)Ks;
        float4* vdst = (float4*)Vs;
#pragma unroll
        for (int u = 0; u < 8; u++) {
            int idx = u * 128 + threadIdx.x;
            kdst[idx] = ksrc[idx];
            vdst[idx] = vsrc[idx];
        }
        __syncthreads();

#pragma unroll 2
        for (int j = 0; j < 64; j++) {
            float s0 = 0.f, s1 = 0.f, s2 = 0.f, s3 = 0.f;
#pragma unroll
            for (int d = 0; d < 64; d += 4) {
                float4 kv = *(const float4*)&Ks[j][d];
                s0 += q[d]     * kv.x;
                s1 += q[d + 1] * kv.y;
                s2 += q[d + 2] * kv.z;
                s3 += q[d + 3] * kv.w;
            }
            float s = (s0 + s1) + (s2 + s3);
            if (s <= m) {
                float p = __expf(s - m);
                l += p;
#pragma unroll
                for (int d = 0; d < 64; d += 4) {
                    float4 vv = *(const float4*)&Vs[j][d];
                    o[d]     += p * vv.x;
                    o[d + 1] += p * vv.y;
                    o[d + 2] += p * vv.z;
                    o[d + 3] += p * vv.w;
                }
            } else {
                float corr = __expf(m - s);
                m = s;
                l = l * corr + 1.f;
#pragma unroll
                for (int d = 0; d < 64; d += 4) {
                    float4 vv = *(const float4*)&Vs[j][d];
                    o[d]     = o[d]     * corr + vv.x;
                    o[d + 1] = o[d + 1] * corr + vv.y;
                    o[d + 2] = o[d + 2] * corr + vv.z;
                    o[d + 3] = o[d + 3] * corr + vv.w;
                }
            }
        }
    }

    float inv = 1.f / l;
    int b = bh >> 4, h = bh & 15;
    float* op = g_attn + ((size_t)(b * SEQ + row)) * DMODEL + h * HDIM;
#pragma unroll
    for (int d = 0; d < 64; d += 4) {
        float4 w;
        w.x = o[d] * inv; w.y = o[d + 1] * inv;
        w.z = o[d + 2] * inv; w.w = o[d + 3] * inv;
        *(float4*)(op + d) = w;
    }
}

// ---------------------------------------------------------------------------
// Kernel 3: output projection. C[m,n] = sum_k attn[m,k] * W_out[n,k] + b_out[n]
// Same tiling as kernel 1, plain epilogue into d_out.
// ---------------------------------------------------------------------------
__global__ __launch_bounds__(256) void out_gemm_kernel(
    const float* __restrict__ W, const float* __restrict__ bias,
    float* __restrict__ out)
{
    __shared__ float As[GBK][GBM + 4];
    __shared__ float Bs[GBK][GBN + 4];

    int tid = threadIdx.x;
    int tx = tid & 15;
    int ty = tid >> 4;
    int m0 = blockIdx.x * GBM;
    int n0 = blockIdx.y * GBN;

    int a_r = tid >> 1;
    int a_c = (tid & 1) * 8;
    int b_r = tid >> 2;
    int b_c = (tid & 3) * 4;

    const float* Aptr = g_attn + (size_t)(m0 + a_r) * DMODEL + a_c;
    const float* Bptr = W + (size_t)(n0 + b_r) * DMODEL + b_c;

    float acc[8][4];
#pragma unroll
    for (int i = 0; i < 8; i++)
#pragma unroll
        for (int j = 0; j < 4; j++) acc[i][j] = 0.f;

    for (int k0 = 0; k0 < DMODEL; k0 += GBK) {
        float4 av0 = *(const float4*)(Aptr + k0);
        float4 av1 = *(const float4*)(Aptr + k0 + 4);
        float4 bv  = *(const float4*)(Bptr + k0);
        __syncthreads();
        As[a_c + 0][a_r] = av0.x; As[a_c + 1][a_r] = av0.y;
        As[a_c + 2][a_r] = av0.z; As[a_c + 3][a_r] = av0.w;
        As[a_c + 4][a_r] = av1.x; As[a_c + 5][a_r] = av1.y;
        As[a_c + 6][a_r] = av1.z; As[a_c + 7][a_r] = av1.w;
        Bs[b_c + 0][b_r] = bv.x;  Bs[b_c + 1][b_r] = bv.y;
        Bs[b_c + 2][b_r] = bv.z;  Bs[b_c + 3][b_r] = bv.w;
        __syncthreads();
#pragma unroll
        for (int kk = 0; kk < GBK; kk++) {
            float a[8], b[4];
            *(float4*)(a)     = *(const float4*)&As[kk][ty * 8];
            *(float4*)(a + 4) = *(const float4*)&As[kk][ty * 8 + 4];
            *(float4*)(b)     = *(const float4*)&Bs[kk][tx * 4];
#pragma unroll
            for (int i = 0; i < 8; i++)
#pragma unroll
                for (int j = 0; j < 4; j++) acc[i][j] += a[i] * b[j];
        }
    }

    float bvals[4];
#pragma unroll
    for (int j = 0; j < 4; j++) bvals[j] = bias[n0 + tx * 4 + j];
#pragma unroll
    for (int i = 0; i < 8; i++) {
        int mrow = m0 + ty * 8 + i;
        float4 w;
        w.x = acc[i][0] + bvals[0];
        w.y = acc[i][1] + bvals[1];
        w.z = acc[i][2] + bvals[2];
        w.w = acc[i][3] + bvals[3];
        *(float4*)(out + (size_t)mrow * DMODEL + n0 + tx * 4) = w;
    }
}

// ---------------------------------------------------------------------------
extern "C" void kernel_launch(void* const* d_in, const int* in_sizes, int n_in,
                              void* d_out, int out_size)
{
    const float* query = (const float*)d_in[0];   // [4,2048,1024]
    const float* W_qkv = (const float*)d_in[1];   // [3072,1024]
    const float* b_qkv = (const float*)d_in[2];   // [3072]
    const float* W_out = (const float*)d_in[3];   // [1024,1024]
    const float* b_out = (const float*)d_in[4];   // [1024]
    float* out = (float*)d_out;

    // 0: rope tables
    rope_table_kernel<<<(SEQ * 32 + 255) / 256, 256>>>();

    // 1: qkv projection + rope + scatter
    {
        dim3 grid(NROWS / GBM, QKV_N / GBN);   // 64 x 48
        qkv_gemm_kernel<<<grid, 256>>>(query, W_qkv, b_qkv);
    }

    // 2: attention
    {
        dim3 grid(SEQ / 128, BATCH * NHEADS);  // 16 x 64
        attn_kernel<<<grid, 128>>>();
    }

    // 3: output projection
    {
        dim3 grid(NROWS / GBM, DMODEL / GBN);  // 64 x 16
        out_gemm_kernel<<<grid, 256>>>(W_out, b_out, out);
    }
}

// round 3
// speedup vs baseline: 2.6292x; 2.6292x over previous
#include <cuda_runtime.h>
#include <cuda_bf16.h>
#include <math.h>
#include <stdint.h>

#define BATCH 4
#define SEQ 2048
#define DMODEL 1024
#define NHEADS 16
#define HDIM 64
#define NROWS (BATCH * SEQ)          // 8192
#define QKV_N (3 * DMODEL)           // 3072

// ---------------------------------------------------------------------------
// mma.sync bf16 helper (sm_80+ PTX, valid at sm_103 target)
// D(16x8,f32) += A(16x16,bf16 row) * B(16x8,bf16 col)
// ---------------------------------------------------------------------------
__device__ __forceinline__ void mma_bf16(float* d, const uint32_t* a,
                                         uint32_t b0, uint32_t b1) {
    asm volatile(
        "mma.sync.aligned.m16n8k16.row.col.f32.bf16.bf16.f32 "
        "{%0,%1,%2,%3}, {%4,%5,%6,%7}, {%8,%9}, {%0,%1,%2,%3};"
        : "+f"(d[0]), "+f"(d[1]), "+f"(d[2]), "+f"(d[3])
        : "r"(a[0]), "r"(a[1]), "r"(a[2]), "r"(a[3]), "r"(b0), "r"(b1));
}

__device__ __forceinline__ uint32_t pack_bf16x2(float lo, float hi) {
    uint32_t r;
    asm("cvt.rn.bf16x2.f32 %0, %1, %2;" : "=r"(r) : "f"(hi), "f"(lo));
    return r;
}

// split v into bf16 hi + residual
__device__ __forceinline__ void split_bf16(float v, float& hi_f, float& lo_f) {
    __nv_bfloat16 hb = __float2bfloat16(v);
    hi_f = __bfloat162float(hb);
    lo_f = v - hi_f;
}

// ---------------------------------------------------------------------------
// Scratch (device globals)
// ---------------------------------------------------------------------------
__device__ float g_rope_cos[SEQ * 32];
__device__ float g_rope_sin[SEQ * 32];

__device__ __nv_bfloat16 g_Xh[NROWS * DMODEL];
__device__ __nv_bfloat16 g_Xl[NROWS * DMODEL];
__device__ __nv_bfloat16 g_Wqkv_h[QKV_N * DMODEL];
__device__ __nv_bfloat16 g_Wqkv_l[QKV_N * DMODEL];
__device__ __nv_bfloat16 g_Wout_h[DMODEL * DMODEL];
__device__ __nv_bfloat16 g_Wout_l[DMODEL * DMODEL];

// Q,K: [bh][s][64]; V transposed: [bh][d][s]
__device__ __nv_bfloat16 g_Qh[64 * SEQ * HDIM];
__device__ __nv_bfloat16 g_Ql[64 * SEQ * HDIM];
__device__ __nv_bfloat16 g_Kh[64 * SEQ * HDIM];
__device__ __nv_bfloat16 g_Kl[64 * SEQ * HDIM];
__device__ __nv_bfloat16 g_Vth[64 * HDIM * SEQ];
__device__ __nv_bfloat16 g_Vtl[64 * HDIM * SEQ];

__device__ __nv_bfloat16 g_attn_h[NROWS * DMODEL];
__device__ __nv_bfloat16 g_attn_l[NROWS * DMODEL];

// ---------------------------------------------------------------------------
// RoPE tables
// ---------------------------------------------------------------------------
__global__ void rope_table_kernel() {
    int idx = blockIdx.x * blockDim.x + threadIdx.x;
    if (idx >= SEQ * 32) return;
    int s = idx >> 5;
    int i = idx & 31;
    float inv_freq = powf(10000.0f, -(float)i / 32.0f);
    float ang = (float)s * inv_freq;
    float sn, cs;
    sincosf(ang, &sn, &cs);
    g_rope_cos[idx] = cs;
    g_rope_sin[idx] = sn;
}

// ---------------------------------------------------------------------------
// Split fp32 -> bf16 hi/lo.  SEL: 0=X, 1=W_qkv, 2=W_out
// ---------------------------------------------------------------------------
template <int SEL>
__global__ void split_kernel(const float* __restrict__ src) {
    constexpr int N = (SEL == 0) ? NROWS * DMODEL : (SEL == 1) ? QKV_N * DMODEL : DMODEL * DMODEL;
    __nv_bfloat16* hp = (SEL == 0) ? g_Xh : (SEL == 1) ? g_Wqkv_h : g_Wout_h;
    __nv_bfloat16* lp = (SEL == 0) ? g_Xl : (SEL == 1) ? g_Wqkv_l : g_Wout_l;
    int i = (blockIdx.x * blockDim.x + threadIdx.x) * 4;
    if (i >= N) return;
    float4 v = *(const float4*)(src + i);
    float vv[4] = {v.x, v.y, v.z, v.w};
#pragma unroll
    for (int j = 0; j < 4; j++) {
        __nv_bfloat16 hb = __float2bfloat16(vv[j]);
        hp[i + j] = hb;
        lp[i + j] = __float2bfloat16(vv[j] - __bfloat162float(hb));
    }
}

// ---------------------------------------------------------------------------
// GEMM: C[m,n] = sum_k A[m,k]*B[n,k] (+bias), bf16x3 on mma.sync
// BM=128 BN=128 BK=32; 256 threads (8 warps: 4 warp-rows x 2 warp-cols)
// MODE 0: A=X, B=W_qkv; epilogue bias+RoPE -> g_Q/g_K (hi/lo), g_Vt (hi/lo)
// MODE 1: A=attn, B=W_out; epilogue bias -> out (fp32)
// ---------------------------------------------------------------------------
#define SA 40                          // smem stride (halves) for [row][k32]
static constexpr uint32_t OFF_AH = 0, OFF_AL = 10240, OFF_BH = 20480, OFF_BL = 30720;
static constexpr uint32_t BUFSZ = 40960;
static constexpr uint32_t OFF_BIAS = 81920;
static constexpr uint32_t GEMM_SMEM = 82432;

template <int MODE>
__global__ __launch_bounds__(256, 1) void mma_gemm_kernel(
    const float* __restrict__ bias, float* __restrict__ outp)
{
    extern __shared__ char smch[];
    int tid = threadIdx.x;
    int wid = tid >> 5;
    int lane = tid & 31;
    int g = lane >> 2;
    int t2 = (lane & 3) * 2;
    int warp_m = wid >> 1;           // 0..3  -> 32 rows each
    int warp_n = wid & 1;            // 0..1  -> 64 cols each
    int m0 = blockIdx.x * 128;
    int n0 = blockIdx.y * 128;

    const __nv_bfloat16* Ah = (MODE == 0) ? g_Xh : g_attn_h;
    const __nv_bfloat16* Al = (MODE == 0) ? g_Xl : g_attn_l;
    const __nv_bfloat16* Bh = (MODE == 0) ? g_Wqkv_h : g_Wout_h;
    const __nv_bfloat16* Bl = (MODE == 0) ? g_Wqkv_l : g_Wout_l;

    float* sbias = (float*)(smch + OFF_BIAS);
    if (tid < 128) sbias[tid] = bias[n0 + tid];

    // global load mapping: row = tid>>1 (0..127), two uint4 (c8 = (tid&1)*2+i)
    int lrow = tid >> 1;
    int lc8 = (tid & 1) * 2;
    const __nv_bfloat16* pAh = Ah + (size_t)(m0 + lrow) * DMODEL + lc8 * 8;
    const __nv_bfloat16* pAl = Al + (size_t)(m0 + lrow) * DMODEL + lc8 * 8;
    const __nv_bfloat16* pBh = Bh + (size_t)(n0 + lrow) * DMODEL + lc8 * 8;
    const __nv_bfloat16* pBl = Bl + (size_t)(n0 + lrow) * DMODEL + lc8 * 8;

    float acc[2][8][4];
#pragma unroll
    for (int mt = 0; mt < 2; mt++)
#pragma unroll
        for (int nt = 0; nt < 8; nt++)
#pragma unroll
            for (int r = 0; r < 4; r++) acc[mt][nt][r] = 0.f;

    uint4 rAh[2], rAl[2], rBh[2], rBl[2];
#pragma unroll
    for (int i = 0; i < 2; i++) {
        rAh[i] = *(const uint4*)(pAh + i * 8);
        rAl[i] = *(const uint4*)(pAl + i * 8);
        rBh[i] = *(const uint4*)(pBh + i * 8);
        rBl[i] = *(const uint4*)(pBl + i * 8);
    }

#pragma unroll 1
    for (int ck = 0; ck < 32; ck++) {
        char* buf = smch + (ck & 1) * BUFSZ;
        // STS
#pragma unroll
        for (int i = 0; i < 2; i++) {
            uint32_t off = (uint32_t)lrow * (SA * 2) + (lc8 + i) * 16;
            *(uint4*)(buf + OFF_AH + off) = rAh[i];
            *(uint4*)(buf + OFF_AL + off) = rAl[i];
            *(uint4*)(buf + OFF_BH + off) = rBh[i];
            *(uint4*)(buf + OFF_BL + off) = rBl[i];
        }
        __syncthreads();
        if (ck < 31) {
            int k0 = (ck + 1) * 32;
#pragma unroll
            for (int i = 0; i < 2; i++) {
                rAh[i] = *(const uint4*)(pAh + k0 + i * 8);
                rAl[i] = *(const uint4*)(pAl + k0 + i * 8);
                rBh[i] = *(const uint4*)(pBh + k0 + i * 8);
                rBl[i] = *(const uint4*)(pBl + k0 + i * 8);
            }
        }
        // compute from buf
#pragma unroll
        for (int ks = 0; ks < 2; ks++) {
            uint32_t fah[2][4], fal[2][4];
#pragma unroll
            for (int mt = 0; mt < 2; mt++) {
                int rb = warp_m * 32 + mt * 16;
                uint32_t o00 = ((rb + g) * SA + ks * 16 + t2) * 2;
                uint32_t o10 = ((rb + g + 8) * SA + ks * 16 + t2) * 2;
                fah[mt][0] = *(const uint32_t*)(buf + OFF_AH + o00);
                fah[mt][1] = *(const uint32_t*)(buf + OFF_AH + o10);
                fah[mt][2] = *(const uint32_t*)(buf + OFF_AH + o00 + 16);
                fah[mt][3] = *(const uint32_t*)(buf + OFF_AH + o10 + 16);
                fal[mt][0] = *(const uint32_t*)(buf + OFF_AL + o00);
                fal[mt][1] = *(const uint32_t*)(buf + OFF_AL + o10);
                fal[mt][2] = *(const uint32_t*)(buf + OFF_AL + o00 + 16);
                fal[mt][3] = *(const uint32_t*)(buf + OFF_AL + o10 + 16);
            }
#pragma unroll
            for (int nt = 0; nt < 8; nt++) {
                int nr = warp_n * 64 + nt * 8 + g;
                uint32_t ob = ((uint32_t)nr * SA + ks * 16 + t2) * 2;
                uint32_t b0h = *(const uint32_t*)(buf + OFF_BH + ob);
                uint32_t b1h = *(const uint32_t*)(buf + OFF_BH + ob + 16);
                uint32_t b0l = *(const uint32_t*)(buf + OFF_BL + ob);
                uint32_t b1l = *(const uint32_t*)(buf + OFF_BL + ob + 16);
#pragma unroll
                for (int mt = 0; mt < 2; mt++) {
                    mma_bf16(acc[mt][nt], fah[mt], b0h, b1h);
                    mma_bf16(acc[mt][nt], fah[mt], b0l, b1l);
                    mma_bf16(acc[mt][nt], fal[mt], b0h, b1h);
                }
            }
        }
    }
    __syncthreads();

    // ----- epilogue -----
    // C fragment: c0=(g,2c) c1=(g,2c+1) c2=(g+8,2c) c3=(g+8,2c+1), cols + nt*8,
    // rows + warp_m*32 + mt*16; warp cols base warp_n*64.
    int nwb = n0 + warp_n * 64;
    if (MODE == 1) {
#pragma unroll
        for (int mt = 0; mt < 2; mt++) {
            int r0 = m0 + warp_m * 32 + mt * 16 + g;
#pragma unroll
            for (int nt = 0; nt < 8; nt++) {
                int ncol = nwb + nt * 8 + t2;
                float b0 = sbias[warp_n * 64 + nt * 8 + t2];
                float b1 = sbias[warp_n * 64 + nt * 8 + t2 + 1];
                float2 w0 = make_float2(acc[mt][nt][0] + b0, acc[mt][nt][1] + b1);
                float2 w1 = make_float2(acc[mt][nt][2] + b0, acc[mt][nt][3] + b1);
                *(float2*)(outp + (size_t)r0 * DMODEL + ncol) = w0;
                *(float2*)(outp + (size_t)(r0 + 8) * DMODEL + ncol) = w1;
            }
        }
    } else {
        int which = nwb >> 10;                 // 0=q,1=k,2=v
        int h = (nwb & 1023) >> 6;
#pragma unroll
        for (int mt = 0; mt < 2; mt++) {
            int m_g = m0 + warp_m * 32 + mt * 16 + g;
#pragma unroll
            for (int rr = 0; rr < 2; rr++) {
                int mrow = m_g + rr * 8;
                int b = mrow >> 11;
                int s = mrow & 2047;
                int bh = b * NHEADS + h;
                if (which == 2) {
#pragma unroll
                    for (int nt = 0; nt < 8; nt++) {
#pragma unroll
                        for (int dd = 0; dd < 2; dd++) {
                            int d = nt * 8 + t2 + dd;
                            float v = acc[mt][nt][rr * 2 + dd] + sbias[warp_n * 64 + d];
                            float vh, vl;
                            split_bf16(v, vh, vl);
                            size_t adr = ((size_t)bh * 64 + d) * SEQ + s;
                            g_Vth[adr] = __float2bfloat16(vh);
                            g_Vtl[adr] = __float2bfloat16(vl);
                        }
                    }
                } else {
                    __nv_bfloat16* dh = (which == 0) ? g_Qh : g_Kh;
                    __nv_bfloat16* dl = (which == 0) ? g_Ql : g_Kl;
                    size_t rowbase = ((size_t)bh * SEQ + s) * 64;
                    float qs = (which == 0) ? 0.125f : 1.0f;
#pragma unroll
                    for (int nt = 0; nt < 4; nt++) {
#pragma unroll
                        for (int dd = 0; dd < 2; dd++) {
                            int d = nt * 8 + t2 + dd;   // 0..31
                            float x1 = acc[mt][nt][rr * 2 + dd]     + sbias[warp_n * 64 + d];
                            float x2 = acc[mt][nt + 4][rr * 2 + dd] + sbias[warp_n * 64 + d + 32];
                            float cs = g_rope_cos[s * 32 + d];
                            float sn = g_rope_sin[s * 32 + d];
                            float y1 = (x1 * cs - x2 * sn) * qs;
                            float y2 = (x2 * cs + x1 * sn) * qs;
                            float h1, l1, h2, l2;
                            split_bf16(y1, h1, l1);
                            split_bf16(y2, h2, l2);
                            dh[rowbase + d] = __float2bfloat16(h1);
                            dl[rowbase + d] = __float2bfloat16(l1);
                            dh[rowbase + d + 32] = __float2bfloat16(h2);
                            dl[rowbase + d + 32] = __float2bfloat16(l2);
                        }
                    }
                }
            }
        }
    }
}

// ---------------------------------------------------------------------------
// Flash attention on mma.sync, bf16x3.
// Grid (32 qtiles, 64 bh), 128 threads (4 warps x 16 query rows).
// ---------------------------------------------------------------------------
#define SR 144    // smem row stride bytes (72 halves)
static constexpr uint32_t AQH = 0, AQL = 9216, AKH = 18432, AKL = 27648,
                          AVH = 36864, AVL = 46080;
static constexpr uint32_t ATTN_SMEM = 55296;

__global__ __launch_bounds__(128, 2) void attn_mma_kernel()
{
    extern __shared__ char smch[];
    int tid = threadIdx.x;
    int wid = tid >> 5;
    int lane = tid & 31;
    int g = lane >> 2;
    int t2 = (lane & 3) * 2;
    int bh = blockIdx.y;
    int qt = blockIdx.x;

    // load Q tile (64x64 h/l)
#pragma unroll
    for (int i = 0; i < 4; i++) {
        int idx = i * 128 + tid;          // 0..511
        int row = idx >> 3;
        int c8 = idx & 7;
        size_t src = ((size_t)bh * SEQ + qt * 64 + row) * 64 + c8 * 8;
        uint32_t dst = row * SR + c8 * 16;
        *(uint4*)(smch + AQH + dst) = *(const uint4*)(g_Qh + src);
        *(uint4*)(smch + AQL + dst) = *(const uint4*)(g_Ql + src);
    }
    __syncthreads();

    // preload Q fragments (warp rows wid*16)
    uint32_t qfh[4][4], qfl[4][4];
    {
        int rb = wid * 16;
#pragma unroll
        for (int ks = 0; ks < 4; ks++) {
            uint32_t o00 = (rb + g) * SR + (ks * 16 + t2) * 2;
            uint32_t o10 = (rb + g + 8) * SR + (ks * 16 + t2) * 2;
            qfh[ks][0] = *(const uint32_t*)(smch + AQH + o00);
            qfh[ks][1] = *(const uint32_t*)(smch + AQH + o10);
            qfh[ks][2] = *(const uint32_t*)(smch + AQH + o00 + 16);
            qfh[ks][3] = *(const uint32_t*)(smch + AQH + o10 + 16);
            qfl[ks][0] = *(const uint32_t*)(smch + AQL + o00);
            qfl[ks][1] = *(const uint32_t*)(smch + AQL + o10);
            qfl[ks][2] = *(const uint32_t*)(smch + AQL + o00 + 16);
            qfl[ks][3] = *(const uint32_t*)(smch + AQL + o10 + 16);
        }
    }

    float o[8][4];
#pragma unroll
    for (int nt = 0; nt < 8; nt++)
#pragma unroll
        for (int r = 0; r < 4; r++) o[nt][r] = 0.f;
    float mrow0 = -1e30f, mrow1 = -1e30f, lrow0 = 0.f, lrow1 = 0.f;

#pragma unroll 1
    for (int kt = 0; kt < 32; kt++) {
        __syncthreads();
        // fill K (h/l) and Vt (h/l)
#pragma unroll
        for (int i = 0; i < 4; i++) {
            int idx = i * 128 + tid;
            int row = idx >> 3;
            int c8 = idx & 7;
            uint32_t dst = row * SR + c8 * 16;
            size_t ksrc = ((size_t)bh * SEQ + kt * 64 + row) * 64 + c8 * 8;
            *(uint4*)(smch + AKH + dst) = *(const uint4*)(g_Kh + ksrc);
            *(uint4*)(smch + AKL + dst) = *(const uint4*)(g_Kl + ksrc);
            size_t vsrc = ((size_t)bh * 64 + row) * SEQ + kt * 64 + c8 * 8;
            *(uint4*)(smch + AVH + dst) = *(const uint4*)(g_Vth + vsrc);
            *(uint4*)(smch + AVL + dst) = *(const uint4*)(g_Vtl + vsrc);
        }
        __syncthreads();

        // scores S = Q K^T (16x64 per warp)
        float sacc[8][4];
#pragma unroll
        for (int nt = 0; nt < 8; nt++)
#pragma unroll
            for (int r = 0; r < 4; r++) sacc[nt][r] = 0.f;
#pragma unroll
        for (int ks = 0; ks < 4; ks++) {
#pragma unroll
            for (int nt = 0; nt < 8; nt++) {
                uint32_t ob = (nt * 8 + g) * SR + (ks * 16 + t2) * 2;
                uint32_t b0h = *(const uint32_t*)(smch + AKH + ob);
                uint32_t b1h = *(const uint32_t*)(smch + AKH + ob + 16);
                uint32_t b0l = *(const uint32_t*)(smch + AKL + ob);
                uint32_t b1l = *(const uint32_t*)(smch + AKL + ob + 16);
                mma_bf16(sacc[nt], qfh[ks], b0h, b1h);
                mma_bf16(sacc[nt], qfh[ks], b0l, b1l);
                mma_bf16(sacc[nt], qfl[ks], b0h, b1h);
            }
        }

        // online softmax (rows g and g+8 of this warp's 16)
        float mx0 = sacc[0][0], mx1 = sacc[0][2];
#pragma unroll
        for (int nt = 0; nt < 8; nt++) {
            mx0 = fmaxf(mx0, fmaxf(sacc[nt][0], sacc[nt][1]));
            mx1 = fmaxf(mx1, fmaxf(sacc[nt][2], sacc[nt][3]));
        }
        mx0 = fmaxf(mx0, __shfl_xor_sync(0xffffffffu, mx0, 1));
        mx0 = fmaxf(mx0, __shfl_xor_sync(0xffffffffu, mx0, 2));
        mx1 = fmaxf(mx1, __shfl_xor_sync(0xffffffffu, mx1, 1));
        mx1 = fmaxf(mx1, __shfl_xor_sync(0xffffffffu, mx1, 2));
        float mn0 = fmaxf(mrow0, mx0);
        float mn1 = fmaxf(mrow1, mx1);
        float cr0 = __expf(mrow0 - mn0);
        float cr1 = __expf(mrow1 - mn1);
        mrow0 = mn0; mrow1 = mn1;

        uint32_t ph[8][2], pl[8][2];
        float ps0 = 0.f, ps1 = 0.f;
#pragma unroll
        for (int nt = 0; nt < 8; nt++) {
            float p0 = __expf(sacc[nt][0] - mn0);
            float p1 = __expf(sacc[nt][1] - mn0);
            float p2 = __expf(sacc[nt][2] - mn1);
            float p3 = __expf(sacc[nt][3] - mn1);
            ps0 += p0 + p1;
            ps1 += p2 + p3;
            float h0, l0, h1, l1, h2, l2, h3, l3;
            split_bf16(p0, h0, l0); split_bf16(p1, h1, l1);
            split_bf16(p2, h2, l2); split_bf16(p3, h3, l3);
            ph[nt][0] = pack_bf16x2(h0, h1);
            ph[nt][1] = pack_bf16x2(h2, h3);
            pl[nt][0] = pack_bf16x2(l0, l1);
            pl[nt][1] = pack_bf16x2(l2, l3);
        }
        ps0 += __shfl_xor_sync(0xffffffffu, ps0, 1);
        ps0 += __shfl_xor_sync(0xffffffffu, ps0, 2);
        ps1 += __shfl_xor_sync(0xffffffffu, ps1, 1);
        ps1 += __shfl_xor_sync(0xffffffffu, ps1, 2);
        lrow0 = lrow0 * cr0 + ps0;
        lrow1 = lrow1 * cr1 + ps1;
#pragma unroll
        for (int nt = 0; nt < 8; nt++) {
            o[nt][0] *= cr0; o[nt][1] *= cr0;
            o[nt][2] *= cr1; o[nt][3] *= cr1;
        }

        // O += P V : A = P fragments (k=keys), B = Vt [d][j]
#pragma unroll
        for (int ks = 0; ks < 4; ks++) {
            uint32_t aPh[4] = {ph[2 * ks][0], ph[2 * ks][1], ph[2 * ks + 1][0], ph[2 * ks + 1][1]};
            uint32_t aPl[4] = {pl[2 * ks][0], pl[2 * ks][1], pl[2 * ks + 1][0], pl[2 * ks + 1][1]};
#pragma unroll
            for (int nt = 0; nt < 8; nt++) {
                uint32_t ob = (nt * 8 + g) * SR + (ks * 16 + t2) * 2;
                uint32_t v0h = *(const uint32_t*)(smch + AVH + ob);
                uint32_t v1h = *(const uint32_t*)(smch + AVH + ob + 16);
                uint32_t v0l = *(const uint32_t*)(smch + AVL + ob);
                uint32_t v1l = *(const uint32_t*)(smch + AVL + ob + 16);
                mma_bf16(o[nt], aPh, v0h, v1h);
                mma_bf16(o[nt], aPh, v0l, v1l);
                mma_bf16(o[nt], aPl, v0h, v1h);
            }
        }
    }

    // epilogue: normalize and store hi/lo bf16 to g_attn
    float inv0 = 1.f / lrow0;
    float inv1 = 1.f / lrow1;
    int b = bh >> 4, h = bh & 15;
    int s0 = qt * 64 + wid * 16 + g;
    int s1 = s0 + 8;
    size_t r0 = ((size_t)b * SEQ + s0) * DMODEL + h * 64;
    size_t r1 = ((size_t)b * SEQ + s1) * DMODEL + h * 64;
#pragma unroll
    for (int nt = 0; nt < 8; nt++) {
        int d0 = nt * 8 + t2;
        float v0 = o[nt][0] * inv0, v1 = o[nt][1] * inv0;
        float v2 = o[nt][2] * inv1, v3 = o[nt][3] * inv1;
        float h0, l0, h1, l1, h2, l2, h3, l3;
        split_bf16(v0, h0, l0); split_bf16(v1, h1, l1);
        split_bf16(v2, h2, l2); split_bf16(v3, h3, l3);
        *(uint32_t*)(g_attn_h + r0 + d0) = pack_bf16x2(h0, h1);
        *(uint32_t*)(g_attn_l + r0 + d0) = pack_bf16x2(l0, l1);
        *(uint32_t*)(g_attn_h + r1 + d0) = pack_bf16x2(h2, h3);
        *(uint32_t*)(g_attn_l + r1 + d0) = pack_bf16x2(l2, l3);
    }
}

// ---------------------------------------------------------------------------
extern "C" void kernel_launch(void* const* d_in, const int* in_sizes, int n_in,
                              void* d_out, int out_size)
{
    const float* query = (const float*)d_in[0];
    const float* W_qkv = (const float*)d_in[1];
    const float* b_qkv = (const float*)d_in[2];
    const float* W_out = (const float*)d_in[3];
    const float* b_out = (const float*)d_in[4];
    float* out = (float*)d_out;

    cudaFuncSetAttribute(mma_gemm_kernel<0>, cudaFuncAttributeMaxDynamicSharedMemorySize, GEMM_SMEM);
    cudaFuncSetAttribute(mma_gemm_kernel<1>, cudaFuncAttributeMaxDynamicSharedMemorySize, GEMM_SMEM);
    cudaFuncSetAttribute(attn_mma_kernel, cudaFuncAttributeMaxDynamicSharedMemorySize, ATTN_SMEM);

    rope_table_kernel<<<(SEQ * 32 + 255) / 256, 256>>>();
    split_kernel<0><<<(NROWS * DMODEL / 4 + 255) / 256, 256>>>(query);
    split_kernel<1><<<(QKV_N * DMODEL / 4 + 255) / 256, 256>>>(W_qkv);
    split_kernel<2><<<(DMODEL * DMODEL / 4 + 255) / 256, 256>>>(W_out);

    {
        dim3 grid(NROWS / 128, QKV_N / 128);   // 64 x 24
        mma_gemm_kernel<0><<<grid, 256, GEMM_SMEM>>>(b_qkv, nullptr);
    }
    {
        dim3 grid(SEQ / 64, BATCH * NHEADS);   // 32 x 64
        attn_mma_kernel<<<grid, 128, ATTN_SMEM>>>();
    }
    {
        dim3 grid(NROWS / 128, DMODEL / 128);  // 64 x 8
        mma_gemm_kernel<1><<<grid, 256, GEMM_SMEM>>>(b_out, out);
    }
}

// round 4
// speedup vs baseline: 3.7873x; 1.4405x over previous
#include <cuda_runtime.h>
#include <cuda_fp16.h>
#include <math.h>
#include <stdint.h>

#define BATCH 4
#define SEQ 2048
#define DMODEL 1024
#define NHEADS 16
#define HDIM 64
#define NROWS (BATCH * SEQ)          // 8192
#define QKV_N (3 * DMODEL)           // 3072

// ---------------------------------------------------------------------------
// PTX helpers
// ---------------------------------------------------------------------------
__device__ __forceinline__ uint32_t smem_to_u32(const void* p) {
    uint32_t a;
    asm("{ .reg .u64 t; cvta.to.shared.u64 t, %1; cvt.u32.u64 %0, t; }" : "=r"(a) : "l"(p));
    return a;
}

// D(16x8,f32) += A(16x16,f16 row) * B(16x8,f16 col)
__device__ __forceinline__ void mma_f16(float* d, const uint32_t* a,
                                        uint32_t b0, uint32_t b1) {
    asm volatile(
        "mma.sync.aligned.m16n8k16.row.col.f32.f16.f16.f32 "
        "{%0,%1,%2,%3}, {%4,%5,%6,%7}, {%8,%9}, {%0,%1,%2,%3};"
        : "+f"(d[0]), "+f"(d[1]), "+f"(d[2]), "+f"(d[3])
        : "r"(a[0]), "r"(a[1]), "r"(a[2]), "r"(a[3]), "r"(b0), "r"(b1));
}

__device__ __forceinline__ void ldsm_x4(uint32_t* r, uint32_t addr) {
    asm volatile("ldmatrix.sync.aligned.m8n8.x4.shared.b16 {%0,%1,%2,%3}, [%4];"
                 : "=r"(r[0]), "=r"(r[1]), "=r"(r[2]), "=r"(r[3]) : "r"(addr));
}

#define CP_ASYNC16(dst, src) \
    asm volatile("cp.async.cg.shared.global [%0], [%1], 16;" :: "r"(dst), "l"(src))
#define CP_COMMIT() asm volatile("cp.async.commit_group;" ::: "memory")
#define CP_WAIT1()  asm volatile("cp.async.wait_group 1;" ::: "memory")
#define CP_WAIT0()  asm volatile("cp.async.wait_group 0;" ::: "memory")

// pack two floats -> f16x2 (lo in low half)
__device__ __forceinline__ uint32_t pack_h2(float lo, float hi) {
    __half2 h = __floats2half2_rn(lo, hi);
    return *(uint32_t*)&h;
}
// split v into f16 hi + residual (both as float)
__device__ __forceinline__ void split_f16(float v, float& hf, float& lf) {
    __half h = __float2half_rn(v);
    hf = __half2float(h);
    lf = v - hf;
}

// ---------------------------------------------------------------------------
// Scratch
// ---------------------------------------------------------------------------
__device__ float g_rope_cos[SEQ * 32];
__device__ float g_rope_sin[SEQ * 32];

__device__ __half g_X[NROWS * DMODEL];            // fp16(query), single
__device__ __half g_Wqkv_h[QKV_N * DMODEL];
__device__ __half g_Wqkv_l[QKV_N * DMODEL];
__device__ __half g_Wout_h[DMODEL * DMODEL];
__device__ __half g_Wout_l[DMODEL * DMODEL];

// Q,K: [bh][s][64] hi/lo; V transposed: [bh][d][s] hi/lo
__device__ __half g_Qh[64 * SEQ * HDIM];
__device__ __half g_Ql[64 * SEQ * HDIM];
__device__ __half g_Kh[64 * SEQ * HDIM];
__device__ __half g_Kl[64 * SEQ * HDIM];
__device__ __half g_Vth[64 * HDIM * SEQ];
__device__ __half g_Vtl[64 * HDIM * SEQ];

__device__ __half g_attn[NROWS * DMODEL];         // fp16 single

// ---------------------------------------------------------------------------
// RoPE tables
// ---------------------------------------------------------------------------
__global__ void rope_table_kernel() {
    int idx = blockIdx.x * blockDim.x + threadIdx.x;
    if (idx >= SEQ * 32) return;
    int s = idx >> 5;
    int i = idx & 31;
    float inv_freq = powf(10000.0f, -(float)i / 32.0f);
    float ang = (float)s * inv_freq;
    float sn, cs;
    sincosf(ang, &sn, &cs);
    g_rope_cos[idx] = cs;
    g_rope_sin[idx] = sn;
}

// ---------------------------------------------------------------------------
// Convert kernels
// ---------------------------------------------------------------------------
__global__ void conv_x_kernel(const float* __restrict__ src) {
    int i = (blockIdx.x * blockDim.x + threadIdx.x) * 4;
    if (i >= NROWS * DMODEL) return;
    float4 v = *(const float4*)(src + i);
    uint2 w;
    w.x = pack_h2(v.x, v.y);
    w.y = pack_h2(v.z, v.w);
    *(uint2*)(g_X + i) = w;
}

template <int SEL>   // 0 = W_qkv, 1 = W_out
__global__ void conv_w_kernel(const float* __restrict__ src) {
    constexpr int N = (SEL == 0) ? QKV_N * DMODEL : DMODEL * DMODEL;
    __half* hp = (SEL == 0) ? g_Wqkv_h : g_Wout_h;
    __half* lp = (SEL == 0) ? g_Wqkv_l : g_Wout_l;
    int i = (blockIdx.x * blockDim.x + threadIdx.x) * 4;
    if (i >= N) return;
    float4 v = *(const float4*)(src + i);
    float vv[4] = {v.x, v.y, v.z, v.w};
    float hh[4], ll[4];
#pragma unroll
    for (int j = 0; j < 4; j++) split_f16(vv[j], hh[j], ll[j]);
    uint2 wh, wl;
    wh.x = pack_h2(hh[0], hh[1]); wh.y = pack_h2(hh[2], hh[3]);
    wl.x = pack_h2(ll[0], ll[1]); wl.y = pack_h2(ll[2], ll[3]);
    *(uint2*)(hp + i) = wh;
    *(uint2*)(lp + i) = wl;
}

// ---------------------------------------------------------------------------
// GEMM: C[m,n] = sum_k A[m,k]*B[n,k] (+bias); A fp16 single, B = Bh+Bl fp16.
// BM=128 BN=128 BK=64; 256 threads (8 warps, 4x2); cp.async double buffer;
// ldmatrix fragment loads.
// MODE 0: A=g_X, B=W_qkv; epilogue bias+RoPE -> Q/K (h/l), Vt (h/l)
// MODE 1: A=g_attn, B=W_out; epilogue bias -> out (fp32)
// ---------------------------------------------------------------------------
#define SAB 144    // smem row stride bytes (72 halves)
static constexpr uint32_t GOFF_A = 0, GOFF_BH = 18432, GOFF_BL = 36864;
static constexpr uint32_t GBUFSZ = 55296;
static constexpr uint32_t GOFF_BIAS = 110592;
static constexpr uint32_t GEMM_SMEM = 111104;

template <int MODE>
__global__ __launch_bounds__(256, 1) void mma_gemm_kernel(
    const float* __restrict__ bias, float* __restrict__ outp)
{
    extern __shared__ char smch[];
    uint32_t sb = smem_to_u32(smch);
    int tid = threadIdx.x;
    int wid = tid >> 5;
    int lane = tid & 31;
    int g = lane >> 2;
    int t2 = (lane & 3) * 2;
    int warp_m = wid >> 1;
    int warp_n = wid & 1;
    int m0 = blockIdx.x * 128;
    int n0 = blockIdx.y * 128;

    const __half* A  = (MODE == 0) ? g_X : g_attn;
    const __half* Bh = (MODE == 0) ? g_Wqkv_h : g_Wout_h;
    const __half* Bl = (MODE == 0) ? g_Wqkv_l : g_Wout_l;

    float* sbias = (float*)(smch + GOFF_BIAS);
    if (tid < 128) sbias[tid] = bias[n0 + tid];

    float acc[2][8][4];
#pragma unroll
    for (int mt = 0; mt < 2; mt++)
#pragma unroll
        for (int nt = 0; nt < 8; nt++)
#pragma unroll
            for (int r = 0; r < 4; r++) acc[mt][nt][r] = 0.f;

    // tile fill via cp.async: chunk c = i*256+tid -> row=c>>3, c8=c&7
    auto fill = [&](int buf, int k0) {
        uint32_t bofs = sb + (uint32_t)buf * GBUFSZ;
#pragma unroll
        for (int i = 0; i < 4; i++) {
            int c = i * 256 + tid;
            int row = c >> 3;
            int c8 = c & 7;
            uint32_t doff = (uint32_t)row * SAB + c8 * 16;
            const __half* pa = A + (size_t)(m0 + row) * DMODEL + k0 + c8 * 8;
            CP_ASYNC16(bofs + GOFF_A + doff, pa);
            const __half* pbh = Bh + (size_t)(n0 + row) * DMODEL + k0 + c8 * 8;
            CP_ASYNC16(bofs + GOFF_BH + doff, pbh);
            const __half* pbl = Bl + (size_t)(n0 + row) * DMODEL + k0 + c8 * 8;
            CP_ASYNC16(bofs + GOFF_BL + doff, pbl);
        }
    };

    fill(0, 0);
    CP_COMMIT();

#pragma unroll 1
    for (int ck = 0; ck < 16; ck++) {
        if (ck < 15) {
            fill((ck + 1) & 1, (ck + 1) * 64);
            CP_COMMIT();
            CP_WAIT1();
        } else {
            CP_WAIT0();
        }
        __syncthreads();

        uint32_t bb = sb + (uint32_t)(ck & 1) * GBUFSZ;
#pragma unroll
        for (int kh = 0; kh < 2; kh++) {
            uint32_t af[2][2][4];
#pragma unroll
            for (int mt = 0; mt < 2; mt++)
#pragma unroll
                for (int kss = 0; kss < 2; kss++) {
                    uint32_t addr = bb + GOFF_A
                        + (uint32_t)(warp_m * 32 + mt * 16 + (lane & 15)) * SAB
                        + (uint32_t)(kh * 32 + kss * 16 + (lane >> 4) * 8) * 2;
                    ldsm_x4(af[mt][kss], addr);
                }
#pragma unroll
            for (int nt = 0; nt < 8; nt++) {
                uint32_t boff = (uint32_t)(warp_n * 64 + nt * 8 + (lane & 7)) * SAB
                              + (uint32_t)(kh * 32 + ((lane >> 3) & 3) * 8) * 2;
                uint32_t bfh[4], bfl[4];
                ldsm_x4(bfh, bb + GOFF_BH + boff);
                ldsm_x4(bfl, bb + GOFF_BL + boff);
#pragma unroll
                for (int kss = 0; kss < 2; kss++)
#pragma unroll
                    for (int mt = 0; mt < 2; mt++) {
                        mma_f16(acc[mt][nt], af[mt][kss], bfh[kss * 2], bfh[kss * 2 + 1]);
                        mma_f16(acc[mt][nt], af[mt][kss], bfl[kss * 2], bfl[kss * 2 + 1]);
                    }
            }
        }
        __syncthreads();
    }

    // ----- epilogue -----
    int nwb = n0 + warp_n * 64;
    if (MODE == 1) {
#pragma unroll
        for (int mt = 0; mt < 2; mt++) {
            int r0 = m0 + warp_m * 32 + mt * 16 + g;
#pragma unroll
            for (int nt = 0; nt < 8; nt++) {
                int ncol = nwb + nt * 8 + t2;
                float b0 = sbias[warp_n * 64 + nt * 8 + t2];
                float b1 = sbias[warp_n * 64 + nt * 8 + t2 + 1];
                float2 w0 = make_float2(acc[mt][nt][0] + b0, acc[mt][nt][1] + b1);
                float2 w1 = make_float2(acc[mt][nt][2] + b0, acc[mt][nt][3] + b1);
                *(float2*)(outp + (size_t)r0 * DMODEL + ncol) = w0;
                *(float2*)(outp + (size_t)(r0 + 8) * DMODEL + ncol) = w1;
            }
        }
    } else {
        int which = nwb >> 10;                 // 0=q,1=k,2=v
        int h = (nwb & 1023) >> 6;
#pragma unroll
        for (int mt = 0; mt < 2; mt++) {
            int m_g = m0 + warp_m * 32 + mt * 16 + g;
#pragma unroll
            for (int rr = 0; rr < 2; rr++) {
                int mrow = m_g + rr * 8;
                int b = mrow >> 11;
                int s = mrow & 2047;
                int bh = b * NHEADS + h;
                if (which == 2) {
#pragma unroll
                    for (int nt = 0; nt < 8; nt++) {
#pragma unroll
                        for (int dd = 0; dd < 2; dd++) {
                            int d = nt * 8 + t2 + dd;
                            float v = acc[mt][nt][rr * 2 + dd] + sbias[warp_n * 64 + d];
                            float vh, vl;
                            split_f16(v, vh, vl);
                            size_t adr = ((size_t)bh * 64 + d) * SEQ + s;
                            g_Vth[adr] = __float2half_rn(vh);
                            g_Vtl[adr] = __float2half_rn(vl);
                        }
                    }
                } else {
                    __half* dh = (which == 0) ? g_Qh : g_Kh;
                    __half* dl = (which == 0) ? g_Ql : g_Kl;
                    size_t rowbase = ((size_t)bh * SEQ + s) * 64;
                    float qs = (which == 0) ? 0.125f : 1.0f;
#pragma unroll
                    for (int nt = 0; nt < 4; nt++) {
#pragma unroll
                        for (int dd = 0; dd < 2; dd++) {
                            int d = nt * 8 + t2 + dd;   // 0..31
                            float x1 = acc[mt][nt][rr * 2 + dd]     + sbias[warp_n * 64 + d];
                            float x2 = acc[mt][nt + 4][rr * 2 + dd] + sbias[warp_n * 64 + d + 32];
                            float cs = g_rope_cos[s * 32 + d];
                            float sn = g_rope_sin[s * 32 + d];
                            float y1 = (x1 * cs - x2 * sn) * qs;
                            float y2 = (x2 * cs + x1 * sn) * qs;
                            float h1, l1, h2, l2;
                            split_f16(y1, h1, l1);
                            split_f16(y2, h2, l2);
                            dh[rowbase + d] = __float2half_rn(h1);
                            dl[rowbase + d] = __float2half_rn(l1);
                            dh[rowbase + d + 32] = __float2half_rn(h2);
                            dl[rowbase + d + 32] = __float2half_rn(l2);
                        }
                    }
                }
            }
        }
    }
}

// ---------------------------------------------------------------------------
// Flash attention, fp16 x3, ldmatrix + cp.async double-buffered KV.
// Grid (32 qtiles, 64 bh), 128 threads (4 warps x 16 q-rows).
// smem: QH 0, QL 9216; KV buffers at 18432, stride 36864:
//       +0 KH, +9216 KL, +18432 VH, +27648 VL.  Total 92160.
// ---------------------------------------------------------------------------
#define SR 144
static constexpr uint32_t AQH = 0, AQL = 9216, AKV = 18432, KVSZ = 36864;
static constexpr uint32_t ATTN_SMEM = 92160;

__global__ __launch_bounds__(128, 2) void attn_mma_kernel()
{
    extern __shared__ char smch[];
    uint32_t sb = smem_to_u32(smch);
    int tid = threadIdx.x;
    int wid = tid >> 5;
    int lane = tid & 31;
    int g = lane >> 2;
    int t2 = (lane & 3) * 2;
    int bh = blockIdx.y;
    int qt = blockIdx.x;

    auto kv_fill = [&](int buf, int kt) {
        uint32_t kb = sb + AKV + (uint32_t)buf * KVSZ;
#pragma unroll
        for (int i = 0; i < 4; i++) {
            int c = i * 128 + tid;
            int row = c >> 3;
            int c8 = c & 7;
            uint32_t doff = (uint32_t)row * SR + c8 * 16;
            size_t ks = ((size_t)bh * SEQ + kt * 64 + row) * 64 + c8 * 8;
            CP_ASYNC16(kb + doff, g_Kh + ks);
            CP_ASYNC16(kb + 9216 + doff, g_Kl + ks);
            size_t vs = ((size_t)bh * 64 + row) * SEQ + kt * 64 + c8 * 8;
            CP_ASYNC16(kb + 18432 + doff, g_Vth + vs);
            CP_ASYNC16(kb + 27648 + doff, g_Vtl + vs);
        }
    };

    // Q fill (group 0)
#pragma unroll
    for (int i = 0; i < 4; i++) {
        int c = i * 128 + tid;
        int row = c >> 3;
        int c8 = c & 7;
        uint32_t doff = (uint32_t)row * SR + c8 * 16;
        size_t qs = ((size_t)bh * SEQ + qt * 64 + row) * 64 + c8 * 8;
        CP_ASYNC16(sb + AQH + doff, g_Qh + qs);
        CP_ASYNC16(sb + AQL + doff, g_Ql + qs);
    }
    CP_COMMIT();
    kv_fill(0, 0);
    CP_COMMIT();
    CP_WAIT1();          // Q group done
    __syncthreads();

    // preload Q fragments
    uint32_t qfh[4][4], qfl[4][4];
    {
        int rb = wid * 16;
#pragma unroll
        for (int ks = 0; ks < 4; ks++) {
            uint32_t addr = sb + (uint32_t)(rb + (lane & 15)) * SR
                          + (uint32_t)(ks * 16 + (lane >> 4) * 8) * 2;
            ldsm_x4(qfh[ks], addr + AQH);
            ldsm_x4(qfl[ks], addr + AQL);
        }
    }

    float o[8][4];
#pragma unroll
    for (int nt = 0; nt < 8; nt++)
#pragma unroll
        for (int r = 0; r < 4; r++) o[nt][r] = 0.f;
    float mrow0 = -1e30f, mrow1 = -1e30f, lrow0 = 0.f, lrow1 = 0.f;

#pragma unroll 1
    for (int kt = 0; kt < 32; kt++) {
        if (kt < 31) {
            kv_fill((kt + 1) & 1, kt + 1);
            CP_COMMIT();
            CP_WAIT1();
        } else {
            CP_WAIT0();
        }
        __syncthreads();

        uint32_t kb = sb + AKV + (uint32_t)(kt & 1) * KVSZ;

        // scores S = Q K^T (16x64 per warp), fp16 x3
        float sacc[8][4];
#pragma unroll
        for (int nt = 0; nt < 8; nt++)
#pragma unroll
            for (int r = 0; r < 4; r++) sacc[nt][r] = 0.f;
#pragma unroll
        for (int kh = 0; kh < 2; kh++) {
#pragma unroll
            for (int nt = 0; nt < 8; nt++) {
                uint32_t boff = (uint32_t)(nt * 8 + (lane & 7)) * SR
                              + (uint32_t)(kh * 32 + ((lane >> 3) & 3) * 8) * 2;
                uint32_t bfh[4], bfl[4];
                ldsm_x4(bfh, kb + boff);
                ldsm_x4(bfl, kb + 9216 + boff);
#pragma unroll
                for (int kss = 0; kss < 2; kss++) {
                    int ks = kh * 2 + kss;
                    mma_f16(sacc[nt], qfh[ks], bfh[kss * 2], bfh[kss * 2 + 1]);
                    mma_f16(sacc[nt], qfh[ks], bfl[kss * 2], bfl[kss * 2 + 1]);
                    mma_f16(sacc[nt], qfl[ks], bfh[kss * 2], bfh[kss * 2 + 1]);
                }
            }
        }

        // online softmax (rows g and g+8)
        float mx0 = sacc[0][0], mx1 = sacc[0][2];
#pragma unroll
        for (int nt = 0; nt < 8; nt++) {
            mx0 = fmaxf(mx0, fmaxf(sacc[nt][0], sacc[nt][1]));
            mx1 = fmaxf(mx1, fmaxf(sacc[nt][2], sacc[nt][3]));
        }
        mx0 = fmaxf(mx0, __shfl_xor_sync(0xffffffffu, mx0, 1));
        mx0 = fmaxf(mx0, __shfl_xor_sync(0xffffffffu, mx0, 2));
        mx1 = fmaxf(mx1, __shfl_xor_sync(0xffffffffu, mx1, 1));
        mx1 = fmaxf(mx1, __shfl_xor_sync(0xffffffffu, mx1, 2));
        float mn0 = fmaxf(mrow0, mx0);
        float mn1 = fmaxf(mrow1, mx1);
        float cr0 = __expf(mrow0 - mn0);
        float cr1 = __expf(mrow1 - mn1);
        mrow0 = mn0; mrow1 = mn1;

        uint32_t ph[8][2], pl[8][2];
        float ps0 = 0.f, ps1 = 0.f;
#pragma unroll
        for (int nt = 0; nt < 8; nt++) {
            float p0 = __expf(sacc[nt][0] - mn0);
            float p1 = __expf(sacc[nt][1] - mn0);
            float p2 = __expf(sacc[nt][2] - mn1);
            float p3 = __expf(sacc[nt][3] - mn1);
            ps0 += p0 + p1;
            ps1 += p2 + p3;
            float h0, l0, h1, l1, h2, l2, h3, l3;
            split_f16(p0, h0, l0); split_f16(p1, h1, l1);
            split_f16(p2, h2, l2); split_f16(p3, h3, l3);
            ph[nt][0] = pack_h2(h0, h1);
            ph[nt][1] = pack_h2(h2, h3);
            pl[nt][0] = pack_h2(l0, l1);
            pl[nt][1] = pack_h2(l2, l3);
        }
        ps0 += __shfl_xor_sync(0xffffffffu, ps0, 1);
        ps0 += __shfl_xor_sync(0xffffffffu, ps0, 2);
        ps1 += __shfl_xor_sync(0xffffffffu, ps1, 1);
        ps1 += __shfl_xor_sync(0xffffffffu, ps1, 2);
        lrow0 = lrow0 * cr0 + ps0;
        lrow1 = lrow1 * cr1 + ps1;
#pragma unroll
        for (int nt = 0; nt < 8; nt++) {
            o[nt][0] *= cr0; o[nt][1] *= cr0;
            o[nt][2] *= cr1; o[nt][3] *= cr1;
        }

        // O += P V, fp16 x3; B = Vt [d][s]
#pragma unroll
        for (int kh = 0; kh < 2; kh++) {
#pragma unroll
            for (int nt = 0; nt < 8; nt++) {
                uint32_t boff = (uint32_t)(nt * 8 + (lane & 7)) * SR
                              + (uint32_t)(kh * 32 + ((lane >> 3) & 3) * 8) * 2;
                uint32_t vfh[4], vfl[4];
                ldsm_x4(vfh, kb + 18432 + boff);
                ldsm_x4(vfl, kb + 27648 + boff);
#pragma unroll
                for (int kss = 0; kss < 2; kss++) {
                    int ks = kh * 2 + kss;
                    uint32_t aPh[4] = {ph[2 * ks][0], ph[2 * ks][1],
                                       ph[2 * ks + 1][0], ph[2 * ks + 1][1]};
                    uint32_t aPl[4] = {pl[2 * ks][0], pl[2 * ks][1],
                                       pl[2 * ks + 1][0], pl[2 * ks + 1][1]};
                    mma_f16(o[nt], aPh, vfh[kss * 2], vfh[kss * 2 + 1]);
                    mma_f16(o[nt], aPh, vfl[kss * 2], vfl[kss * 2 + 1]);
                    mma_f16(o[nt], aPl, vfh[kss * 2], vfh[kss * 2 + 1]);
                }
            }
        }
        __syncthreads();
    }

    // epilogue: normalize, store fp16 single
    float inv0 = 1.f / lrow0;
    float inv1 = 1.f / lrow1;
    int b = bh >> 4, h = bh & 15;
    int s0 = qt * 64 + wid * 16 + g;
    int s1 = s0 + 8;
    size_t r0 = ((size_t)b * SEQ + s0) * DMODEL + h * 64;
    size_t r1 = ((size_t)b * SEQ + s1) * DMODEL + h * 64;
#pragma unroll
    for (int nt = 0; nt < 8; nt++) {
        int d0 = nt * 8 + t2;
        *(uint32_t*)(g_attn + r0 + d0) = pack_h2(o[nt][0] * inv0, o[nt][1] * inv0);
        *(uint32_t*)(g_attn + r1 + d0) = pack_h2(o[nt][2] * inv1, o[nt][3] * inv1);
    }
}

// ---------------------------------------------------------------------------
extern "C" void kernel_launch(void* const* d_in, const int* in_sizes, int n_in,
                              void* d_out, int out_size)
{
    const float* query = (const float*)d_in[0];
    const float* W_qkv = (const float*)d_in[1];
    const float* b_qkv = (const float*)d_in[2];
    const float* W_out = (const float*)d_in[3];
    const float* b_out = (const float*)d_in[4];
    float* out = (float*)d_out;

    cudaFuncSetAttribute(mma_gemm_kernel<0>, cudaFuncAttributeMaxDynamicSharedMemorySize, GEMM_SMEM);
    cudaFuncSetAttribute(mma_gemm_kernel<1>, cudaFuncAttributeMaxDynamicSharedMemorySize, GEMM_SMEM);
    cudaFuncSetAttribute(attn_mma_kernel, cudaFuncAttributeMaxDynamicSharedMemorySize, ATTN_SMEM);

    rope_table_kernel<<<(SEQ * 32 + 255) / 256, 256>>>();
    conv_x_kernel<<<(NROWS * DMODEL / 4 + 255) / 256, 256>>>(query);
    conv_w_kernel<0><<<(QKV_N * DMODEL / 4 + 255) / 256, 256>>>(W_qkv);
    conv_w_kernel<1><<<(DMODEL * DMODEL / 4 + 255) / 256, 256>>>(W_out);

    {
        dim3 grid(NROWS / 128, QKV_N / 128);   // 64 x 24
        mma_gemm_kernel<0><<<grid, 256, GEMM_SMEM>>>(b_qkv, nullptr);
    }
    {
        dim3 grid(SEQ / 64, BATCH * NHEADS);   // 32 x 64
        attn_mma_kernel<<<grid, 128, ATTN_SMEM>>>();
    }
    {
        dim3 grid(NROWS / 128, DMODEL / 128);  // 64 x 8
        mma_gemm_kernel<1><<<grid, 256, GEMM_SMEM>>>(b_out, out);
    }
}

// round 6
// speedup vs baseline: 4.8392x; 1.2777x over previous
#include <cuda_runtime.h>
#include <cuda_fp16.h>
#include <math.h>
#include <stdint.h>

#define BATCH 4
#define SEQ 2048
#define DMODEL 1024
#define NHEADS 16
#define HDIM 64
#define NROWS (BATCH * SEQ)          // 8192
#define QKV_N (3 * DMODEL)           // 3072
#define LOG2E 1.4426950408889634f

// ---------------------------------------------------------------------------
// PTX helpers
// ---------------------------------------------------------------------------
__device__ __forceinline__ uint32_t smem_to_u32(const void* p) {
    uint32_t a;
    asm("{ .reg .u64 t; cvta.to.shared.u64 t, %1; cvt.u32.u64 %0, t; }" : "=r"(a) : "l"(p));
    return a;
}

__device__ __forceinline__ void mma_f16(float* d, const uint32_t* a,
                                        uint32_t b0, uint32_t b1) {
    asm volatile(
        "mma.sync.aligned.m16n8k16.row.col.f32.f16.f16.f32 "
        "{%0,%1,%2,%3}, {%4,%5,%6,%7}, {%8,%9}, {%0,%1,%2,%3};"
        : "+f"(d[0]), "+f"(d[1]), "+f"(d[2]), "+f"(d[3])
        : "r"(a[0]), "r"(a[1]), "r"(a[2]), "r"(a[3]), "r"(b0), "r"(b1));
}

__device__ __forceinline__ void ldsm_x4(uint32_t* r, uint32_t addr) {
    asm volatile("ldmatrix.sync.aligned.m8n8.x4.shared.b16 {%0,%1,%2,%3}, [%4];"
                 : "=r"(r[0]), "=r"(r[1]), "=r"(r[2]), "=r"(r[3]) : "r"(addr));
}

#define CP_ASYNC16(dst, src) \
    asm volatile("cp.async.cg.shared.global [%0], [%1], 16;" :: "r"(dst), "l"(src))
#define CP_COMMIT() asm volatile("cp.async.commit_group;" ::: "memory")
#define CP_WAIT1()  asm volatile("cp.async.wait_group 1;" ::: "memory")
#define CP_WAIT0()  asm volatile("cp.async.wait_group 0;" ::: "memory")

__device__ __forceinline__ uint32_t pack_h2(float lo, float hi) {
    __half2 h = __floats2half2_rn(lo, hi);
    return *(uint32_t*)&h;
}
__device__ __forceinline__ void split_f16(float v, float& hf, float& lf) {
    __half h = __float2half_rn(v);
    hf = __half2float(h);
    lf = v - hf;
}

// ---------------------------------------------------------------------------
// Scratch
// ---------------------------------------------------------------------------
__device__ float g_rope_cos[SEQ * 32];
__device__ float g_rope_sin[SEQ * 32];

__device__ __half g_X[NROWS * DMODEL];            // fp16(query)
__device__ __half g_Wqkv_h[QKV_N * DMODEL];
__device__ __half g_Wqkv_l[QKV_N * DMODEL];
__device__ __half g_Wout_h[DMODEL * DMODEL];
__device__ __half g_Wout_l[DMODEL * DMODEL];

// Q hi/lo: [bh][s][64]; K single: [bh][s][64]; V single transposed: [bh][d][s]
__device__ __half g_Qh[64 * SEQ * HDIM];
__device__ __half g_Ql[64 * SEQ * HDIM];
__device__ __half g_K[64 * SEQ * HDIM];
__device__ __half g_Vt[64 * HDIM * SEQ];

__device__ __half g_attn[NROWS * DMODEL];         // fp16 single

// ---------------------------------------------------------------------------
// RoPE tables
// ---------------------------------------------------------------------------
__global__ void rope_table_kernel() {
    int idx = blockIdx.x * blockDim.x + threadIdx.x;
    if (idx >= SEQ * 32) return;
    int s = idx >> 5;
    int i = idx & 31;
    float inv_freq = powf(10000.0f, -(float)i / 32.0f);
    float ang = (float)s * inv_freq;
    float sn, cs;
    sincosf(ang, &sn, &cs);
    g_rope_cos[idx] = cs;
    g_rope_sin[idx] = sn;
}

// ---------------------------------------------------------------------------
// Convert kernels
// ---------------------------------------------------------------------------
__global__ void conv_x_kernel(const float* __restrict__ src) {
    int i = (blockIdx.x * blockDim.x + threadIdx.x) * 4;
    if (i >= NROWS * DMODEL) return;
    float4 v = *(const float4*)(src + i);
    uint2 w;
    w.x = pack_h2(v.x, v.y);
    w.y = pack_h2(v.z, v.w);
    *(uint2*)(g_X + i) = w;
}

template <int SEL>   // 0 = W_qkv, 1 = W_out
__global__ void conv_w_kernel(const float* __restrict__ src) {
    constexpr int N = (SEL == 0) ? QKV_N * DMODEL : DMODEL * DMODEL;
    __half* hp = (SEL == 0) ? g_Wqkv_h : g_Wout_h;
    __half* lp = (SEL == 0) ? g_Wqkv_l : g_Wout_l;
    int i = (blockIdx.x * blockDim.x + threadIdx.x) * 4;
    if (i >= N) return;
    float4 v = *(const float4*)(src + i);
    float vv[4] = {v.x, v.y, v.z, v.w};
    float hh[4], ll[4];
#pragma unroll
    for (int j = 0; j < 4; j++) split_f16(vv[j], hh[j], ll[j]);
    uint2 wh, wl;
    wh.x = pack_h2(hh[0], hh[1]); wh.y = pack_h2(hh[2], hh[3]);
    wl.x = pack_h2(ll[0], ll[1]); wl.y = pack_h2(ll[2], ll[3]);
    *(uint2*)(hp + i) = wh;
    *(uint2*)(lp + i) = wl;
}

// ---------------------------------------------------------------------------
// GEMM: C[m,n] = sum_k A[m,k]*B[n,k] (+bias); A single fp16, B = Bh+Bl.
// BM=128 BN=128 BK=32; 256 threads (8 warps 4x2); 3-stage cp.async ring;
// one __syncthreads per chunk.  launch_bounds(256,2) -> occupancy 2.
// MODE 0: A=g_X, B=W_qkv; epilogue bias+RoPE -> Qh/Ql, K, Vt
// MODE 1: A=g_attn, B=W_out; epilogue bias -> out fp32
// ---------------------------------------------------------------------------
#define SAB 80     // smem row stride bytes (40 halves = 32 + 8 pad)
static constexpr uint32_t GOFF_A = 0, GOFF_BH = 10240, GOFF_BL = 20480;
static constexpr uint32_t GBUFSZ = 30720;
static constexpr uint32_t GOFF_BIAS = 92160;
static constexpr uint32_t GEMM_SMEM = 92672;

template <int MODE>
__global__ __launch_bounds__(256, 2) void mma_gemm_kernel(
    const float* __restrict__ bias, float* __restrict__ outp)
{
    extern __shared__ char smch[];
    uint32_t sb = smem_to_u32(smch);
    int tid = threadIdx.x;
    int wid = tid >> 5;
    int lane = tid & 31;
    int g = lane >> 2;
    int t2 = (lane & 3) * 2;
    int warp_m = wid >> 1;
    int warp_n = wid & 1;
    int m0 = blockIdx.x * 128;
    int n0 = blockIdx.y * 128;

    const __half* A  = (MODE == 0) ? g_X : g_attn;
    const __half* Bh = (MODE == 0) ? g_Wqkv_h : g_Wout_h;
    const __half* Bl = (MODE == 0) ? g_Wqkv_l : g_Wout_l;

    float* sbias = (float*)(smch + GOFF_BIAS);
    if (tid < 128) sbias[tid] = bias[n0 + tid];

    float acc[2][8][4];
#pragma unroll
    for (int mt = 0; mt < 2; mt++)
#pragma unroll
        for (int nt = 0; nt < 8; nt++)
#pragma unroll
            for (int r = 0; r < 4; r++) acc[mt][nt][r] = 0.f;

    // fill one stage: 512 16B-chunks per array / 256 threads = 2 per array
    auto fill = [&](int stage, int k0) {
        uint32_t bofs = sb + (uint32_t)stage * GBUFSZ;
#pragma unroll
        for (int i = 0; i < 2; i++) {
            int c = i * 256 + tid;
            int row = c >> 2;
            int c8 = c & 3;
            uint32_t doff = (uint32_t)row * SAB + c8 * 16;
            CP_ASYNC16(bofs + GOFF_A  + doff, A  + (size_t)(m0 + row) * DMODEL + k0 + c8 * 8);
            CP_ASYNC16(bofs + GOFF_BH + doff, Bh + (size_t)(n0 + row) * DMODEL + k0 + c8 * 8);
            CP_ASYNC16(bofs + GOFF_BL + doff, Bl + (size_t)(n0 + row) * DMODEL + k0 + c8 * 8);
        }
    };

    fill(0, 0);  CP_COMMIT();
    fill(1, 32); CP_COMMIT();

#pragma unroll 1
    for (int ck = 0; ck < 32; ck++) {
        if (ck < 31) CP_WAIT1(); else CP_WAIT0();
        __syncthreads();
        if (ck < 30) {
            fill((ck + 2) % 3, (ck + 2) * 32);
            CP_COMMIT();
        }

        uint32_t bb = sb + (uint32_t)(ck % 3) * GBUFSZ;
        uint32_t af[2][2][4];
#pragma unroll
        for (int mt = 0; mt < 2; mt++)
#pragma unroll
            for (int kss = 0; kss < 2; kss++) {
                uint32_t addr = bb + GOFF_A
                    + (uint32_t)(warp_m * 32 + mt * 16 + (lane & 15)) * SAB
                    + (uint32_t)(kss * 16 + (lane >> 4) * 8) * 2;
                ldsm_x4(af[mt][kss], addr);
            }
#pragma unroll
        for (int nt = 0; nt < 8; nt++) {
            uint32_t boff = (uint32_t)(warp_n * 64 + nt * 8 + (lane & 7)) * SAB
                          + (uint32_t)(((lane >> 3) & 3) * 8) * 2;
            uint32_t bfh[4], bfl[4];
            ldsm_x4(bfh, bb + GOFF_BH + boff);
            ldsm_x4(bfl, bb + GOFF_BL + boff);
#pragma unroll
            for (int kss = 0; kss < 2; kss++)
#pragma unroll
                for (int mt = 0; mt < 2; mt++) {
                    mma_f16(acc[mt][nt], af[mt][kss], bfh[kss * 2], bfh[kss * 2 + 1]);
                    mma_f16(acc[mt][nt], af[mt][kss], bfl[kss * 2], bfl[kss * 2 + 1]);
                }
        }
    }

    // ----- epilogue -----
    int nwb = n0 + warp_n * 64;
    if (MODE == 1) {
#pragma unroll
        for (int mt = 0; mt < 2; mt++) {
            int r0 = m0 + warp_m * 32 + mt * 16 + g;
#pragma unroll
            for (int nt = 0; nt < 8; nt++) {
                int ncol = nwb + nt * 8 + t2;
                float b0 = sbias[warp_n * 64 + nt * 8 + t2];
                float b1 = sbias[warp_n * 64 + nt * 8 + t2 + 1];
                float2 w0 = make_float2(acc[mt][nt][0] + b0, acc[mt][nt][1] + b1);
                float2 w1 = make_float2(acc[mt][nt][2] + b0, acc[mt][nt][3] + b1);
                *(float2*)(outp + (size_t)r0 * DMODEL + ncol) = w0;
                *(float2*)(outp + (size_t)(r0 + 8) * DMODEL + ncol) = w1;
            }
        }
    } else {
        int which = nwb >> 10;                 // 0=q,1=k,2=v
        int h = (nwb & 1023) >> 6;
#pragma unroll
        for (int mt = 0; mt < 2; mt++) {
            int m_g = m0 + warp_m * 32 + mt * 16 + g;
#pragma unroll
            for (int rr = 0; rr < 2; rr++) {
                int mrow = m_g + rr * 8;
                int b = mrow >> 11;
                int s = mrow & 2047;
                int bh = b * NHEADS + h;
                if (which == 2) {
#pragma unroll
                    for (int nt = 0; nt < 8; nt++) {
#pragma unroll
                        for (int dd = 0; dd < 2; dd++) {
                            int d = nt * 8 + t2 + dd;
                            float v = acc[mt][nt][rr * 2 + dd] + sbias[warp_n * 64 + d];
                            g_Vt[((size_t)bh * 64 + d) * SEQ + s] = __float2half_rn(v);
                        }
                    }
                } else {
                    size_t rowbase = ((size_t)bh * SEQ + s) * 64;
                    // Q gets 1/8 * log2(e) folded in; K plain.
                    float qs = (which == 0) ? (0.125f * LOG2E) : 1.0f;
#pragma unroll
                    for (int nt = 0; nt < 4; nt++) {
#pragma unroll
                        for (int dd = 0; dd < 2; dd++) {
                            int d = nt * 8 + t2 + dd;   // 0..31
                            float x1 = acc[mt][nt][rr * 2 + dd]     + sbias[warp_n * 64 + d];
                            float x2 = acc[mt][nt + 4][rr * 2 + dd] + sbias[warp_n * 64 + d + 32];
                            float cs = g_rope_cos[s * 32 + d];
                            float sn = g_rope_sin[s * 32 + d];
                            float y1 = (x1 * cs - x2 * sn) * qs;
                            float y2 = (x2 * cs + x1 * sn) * qs;
                            if (which == 0) {
                                float h1, l1, h2, l2;
                                split_f16(y1, h1, l1);
                                split_f16(y2, h2, l2);
                                g_Qh[rowbase + d]      = __float2half_rn(h1);
                                g_Ql[rowbase + d]      = __float2half_rn(l1);
                                g_Qh[rowbase + d + 32] = __float2half_rn(h2);
                                g_Ql[rowbase + d + 32] = __float2half_rn(l2);
                            } else {
                                g_K[rowbase + d]      = __float2half_rn(y1);
                                g_K[rowbase + d + 32] = __float2half_rn(y2);
                            }
                        }
                    }
                }
            }
        }
    }
}

// ---------------------------------------------------------------------------
// Flash attention: scores = (Qh+Ql)·K, PV = (Ph+Pl)·V; exp2 softmax.
// Grid (32 qtiles, 64 bh), 128 threads (4 warps x 16 q-rows).
// smem: QH 0, QL 9216; KV stages at 18432 (K +0, V +9216), stride 18432.
// ---------------------------------------------------------------------------
#define SR 144
static constexpr uint32_t AQH = 0, AQL = 9216, AKV = 18432, KVSZ = 18432;
static constexpr uint32_t ATTN_SMEM = 55296;

__global__ __launch_bounds__(128, 3) void attn_mma_kernel()
{
    extern __shared__ char smch[];
    uint32_t sb = smem_to_u32(smch);
    int tid = threadIdx.x;
    int wid = tid >> 5;
    int lane = tid & 31;
    int g = lane >> 2;
    int t2 = (lane & 3) * 2;
    int bh = blockIdx.y;
    int qt = blockIdx.x;

    auto kv_fill = [&](int buf, int kt) {
        uint32_t kb = sb + AKV + (uint32_t)buf * KVSZ;
#pragma unroll
        for (int i = 0; i < 4; i++) {
            int c = i * 128 + tid;
            int row = c >> 3;
            int c8 = c & 7;
            uint32_t doff = (uint32_t)row * SR + c8 * 16;
            CP_ASYNC16(kb + doff, g_K + ((size_t)bh * SEQ + kt * 64 + row) * 64 + c8 * 8);
            CP_ASYNC16(kb + 9216 + doff,
                       g_Vt + ((size_t)bh * 64 + row) * SEQ + kt * 64 + c8 * 8);
        }
    };

    // Q fill (group 0)
#pragma unroll
    for (int i = 0; i < 4; i++) {
        int c = i * 128 + tid;
        int row = c >> 3;
        int c8 = c & 7;
        uint32_t doff = (uint32_t)row * SR + c8 * 16;
        size_t qs = ((size_t)bh * SEQ + qt * 64 + row) * 64 + c8 * 8;
        CP_ASYNC16(sb + AQH + doff, g_Qh + qs);
        CP_ASYNC16(sb + AQL + doff, g_Ql + qs);
    }
    CP_COMMIT();
    kv_fill(0, 0);
    CP_COMMIT();
    CP_WAIT1();          // Q done
    __syncthreads();

    uint32_t qfh[4][4], qfl[4][4];
    {
        int rb = wid * 16;
#pragma unroll
        for (int ks = 0; ks < 4; ks++) {
            uint32_t addr = sb + (uint32_t)(rb + (lane & 15)) * SR
                          + (uint32_t)(ks * 16 + (lane >> 4) * 8) * 2;
            ldsm_x4(qfh[ks], addr + AQH);
            ldsm_x4(qfl[ks], addr + AQL);
        }
    }

    float o[8][4];
#pragma unroll
    for (int nt = 0; nt < 8; nt++)
#pragma unroll
        for (int r = 0; r < 4; r++) o[nt][r] = 0.f;
    float mrow0 = -1e30f, mrow1 = -1e30f, lrow0 = 0.f, lrow1 = 0.f;

#pragma unroll 1
    for (int kt = 0; kt < 32; kt++) {
        if (kt < 31) {
            kv_fill((kt + 1) & 1, kt + 1);
            CP_COMMIT();
            CP_WAIT1();
        } else {
            CP_WAIT0();
        }
        __syncthreads();

        uint32_t kb = sb + AKV + (uint32_t)(kt & 1) * KVSZ;

        // scores: (Qh + Ql) x K
        float sacc[8][4];
#pragma unroll
        for (int nt = 0; nt < 8; nt++)
#pragma unroll
            for (int r = 0; r < 4; r++) sacc[nt][r] = 0.f;
#pragma unroll
        for (int kh = 0; kh < 2; kh++) {
#pragma unroll
            for (int nt = 0; nt < 8; nt++) {
                uint32_t boff = (uint32_t)(nt * 8 + (lane & 7)) * SR
                              + (uint32_t)(kh * 32 + ((lane >> 3) & 3) * 8) * 2;
                uint32_t bf[4];
                ldsm_x4(bf, kb + boff);
#pragma unroll
                for (int kss = 0; kss < 2; kss++) {
                    int ks = kh * 2 + kss;
                    mma_f16(sacc[nt], qfh[ks], bf[kss * 2], bf[kss * 2 + 1]);
                    mma_f16(sacc[nt], qfl[ks], bf[kss * 2], bf[kss * 2 + 1]);
                }
            }
        }

        // online softmax in log2 domain (rows g, g+8)
        float mx0 = sacc[0][0], mx1 = sacc[0][2];
#pragma unroll
        for (int nt = 0; nt < 8; nt++) {
            mx0 = fmaxf(mx0, fmaxf(sacc[nt][0], sacc[nt][1]));
            mx1 = fmaxf(mx1, fmaxf(sacc[nt][2], sacc[nt][3]));
        }
        mx0 = fmaxf(mx0, __shfl_xor_sync(0xffffffffu, mx0, 1));
        mx0 = fmaxf(mx0, __shfl_xor_sync(0xffffffffu, mx0, 2));
        mx1 = fmaxf(mx1, __shfl_xor_sync(0xffffffffu, mx1, 1));
        mx1 = fmaxf(mx1, __shfl_xor_sync(0xffffffffu, mx1, 2));
        float mn0 = fmaxf(mrow0, mx0);
        float mn1 = fmaxf(mrow1, mx1);
        float cr0 = exp2f(mrow0 - mn0);
        float cr1 = exp2f(mrow1 - mn1);
        mrow0 = mn0; mrow1 = mn1;

        uint32_t ph[8][2], pl[8][2];
        float ps0 = 0.f, ps1 = 0.f;
#pragma unroll
        for (int nt = 0; nt < 8; nt++) {
            float p0 = exp2f(sacc[nt][0] - mn0);
            float p1 = exp2f(sacc[nt][1] - mn0);
            float p2 = exp2f(sacc[nt][2] - mn1);
            float p3 = exp2f(sacc[nt][3] - mn1);
            ps0 += p0 + p1;
            ps1 += p2 + p3;
            float h0, l0, h1, l1, h2, l2, h3, l3;
            split_f16(p0, h0, l0); split_f16(p1, h1, l1);
            split_f16(p2, h2, l2); split_f16(p3, h3, l3);
            ph[nt][0] = pack_h2(h0, h1);
            ph[nt][1] = pack_h2(h2, h3);
            pl[nt][0] = pack_h2(l0, l1);
            pl[nt][1] = pack_h2(l2, l3);
        }
        ps0 += __shfl_xor_sync(0xffffffffu, ps0, 1);
        ps0 += __shfl_xor_sync(0xffffffffu, ps0, 2);
        ps1 += __shfl_xor_sync(0xffffffffu, ps1, 1);
        ps1 += __shfl_xor_sync(0xffffffffu, ps1, 2);
        lrow0 = lrow0 * cr0 + ps0;
        lrow1 = lrow1 * cr1 + ps1;
#pragma unroll
        for (int nt = 0; nt < 8; nt++) {
            o[nt][0] *= cr0; o[nt][1] *= cr0;
            o[nt][2] *= cr1; o[nt][3] *= cr1;
        }

        // O += (Ph + Pl) x V
#pragma unroll
        for (int kh = 0; kh < 2; kh++) {
#pragma unroll
            for (int nt = 0; nt < 8; nt++) {
                uint32_t boff = (uint32_t)(nt * 8 + (lane & 7)) * SR
                              + (uint32_t)(kh * 32 + ((lane >> 3) & 3) * 8) * 2;
                uint32_t vf[4];
                ldsm_x4(vf, kb + 9216 + boff);
#pragma unroll
                for (int kss = 0; kss < 2; kss++) {
                    int ks = kh * 2 + kss;
                    uint32_t aPh[4] = {ph[2 * ks][0], ph[2 * ks][1],
                                       ph[2 * ks + 1][0], ph[2 * ks + 1][1]};
                    uint32_t aPl[4] = {pl[2 * ks][0], pl[2 * ks][1],
                                       pl[2 * ks + 1][0], pl[2 * ks + 1][1]};
                    mma_f16(o[nt], aPh, vf[kss * 2], vf[kss * 2 + 1]);
                    mma_f16(o[nt], aPl, vf[kss * 2], vf[kss * 2 + 1]);
                }
            }
        }
        __syncthreads();
    }

    // epilogue
    float inv0 = 1.f / lrow0;
    float inv1 = 1.f / lrow1;
    int b = bh >> 4, h = bh & 15;
    int s0 = qt * 64 + wid * 16 + g;
    int s1 = s0 + 8;
    size_t r0 = ((size_t)b * SEQ + s0) * DMODEL + h * 64;
    size_t r1 = ((size_t)b * SEQ + s1) * DMODEL + h * 64;
#pragma unroll
    for (int nt = 0; nt < 8; nt++) {
        int d0 = nt * 8 + t2;
        *(uint32_t*)(g_attn + r0 + d0) = pack_h2(o[nt][0] * inv0, o[nt][1] * inv0);
        *(uint32_t*)(g_attn + r1 + d0) = pack_h2(o[nt][2] * inv1, o[nt][3] * inv1);
    }
}

// ---------------------------------------------------------------------------
extern "C" void kernel_launch(void* const* d_in, const int* in_sizes, int n_in,
                              void* d_out, int out_size)
{
    const float* query = (const float*)d_in[0];
    const float* W_qkv = (const float*)d_in[1];
    const float* b_qkv = (const float*)d_in[2];
    const float* W_out = (const float*)d_in[3];
    const float* b_out = (const float*)d_in[4];
    float* out = (float*)d_out;

    cudaFuncSetAttribute(mma_gemm_kernel<0>, cudaFuncAttributeMaxDynamicSharedMemorySize, GEMM_SMEM);
    cudaFuncSetAttribute(mma_gemm_kernel<1>, cudaFuncAttributeMaxDynamicSharedMemorySize, GEMM_SMEM);
    cudaFuncSetAttribute(attn_mma_kernel, cudaFuncAttributeMaxDynamicSharedMemorySize, ATTN_SMEM);

    rope_table_kernel<<<(SEQ * 32 + 255) / 256, 256>>>();
    conv_x_kernel<<<(NROWS * DMODEL / 4 + 255) / 256, 256>>>(query);
    conv_w_kernel<0><<<(QKV_N * DMODEL / 4 + 255) / 256, 256>>>(W_qkv);
    conv_w_kernel<1><<<(DMODEL * DMODEL / 4 + 255) / 256, 256>>>(W_out);

    {
        dim3 grid(NROWS / 128, QKV_N / 128);   // 64 x 24
        mma_gemm_kernel<0><<<grid, 256, GEMM_SMEM>>>(b_qkv, nullptr);
    }
    {
        dim3 grid(SEQ / 64, BATCH * NHEADS);   // 32 x 64
        attn_mma_kernel<<<grid, 128, ATTN_SMEM>>>();
    }
    {
        dim3 grid(NROWS / 128, DMODEL / 128);  // 64 x 8
        mma_gemm_kernel<1><<<grid, 256, GEMM_SMEM>>>(b_out, out);
    }
}

// round 10
// speedup vs baseline: 5.2293x; 1.0806x over previous
#include <cuda_runtime.h>
#include <cuda_fp16.h>
#include <math.h>
#include <stdint.h>

#define BATCH 4
#define SEQ 2048
#define DMODEL 1024
#define NHEADS 16
#define HDIM 64
#define NROWS (BATCH * SEQ)          // 8192
#define QKV_N (3 * DMODEL)           // 3072
#define LOG2E 1.4426950408889634f

// ---------------------------------------------------------------------------
// PTX helpers
// ---------------------------------------------------------------------------
__device__ __forceinline__ uint32_t smem_to_u32(const void* p) {
    uint32_t a;
    asm("{ .reg .u64 t; cvta.to.shared.u64 t, %1; cvt.u32.u64 %0, t; }" : "=r"(a) : "l"(p));
    return a;
}

__device__ __forceinline__ void mma_f16(float* d, const uint32_t* a,
                                        uint32_t b0, uint32_t b1) {
    asm volatile(
        "mma.sync.aligned.m16n8k16.row.col.f32.f16.f16.f32 "
        "{%0,%1,%2,%3}, {%4,%5,%6,%7}, {%8,%9}, {%0,%1,%2,%3};"
        : "+f"(d[0]), "+f"(d[1]), "+f"(d[2]), "+f"(d[3])
        : "r"(a[0]), "r"(a[1]), "r"(a[2]), "r"(a[3]), "r"(b0), "r"(b1));
}

__device__ __forceinline__ void ldsm_x4(uint32_t* r, uint32_t addr) {
    asm volatile("ldmatrix.sync.aligned.m8n8.x4.shared.b16 {%0,%1,%2,%3}, [%4];"
                 : "=r"(r[0]), "=r"(r[1]), "=r"(r[2]), "=r"(r[3]) : "r"(addr));
}

#define CP_ASYNC16(dst, src) \
    asm volatile("cp.async.cg.shared.global [%0], [%1], 16;" :: "r"(dst), "l"(src))
#define CP_COMMIT() asm volatile("cp.async.commit_group;" ::: "memory")
#define CP_WAIT2()  asm volatile("cp.async.wait_group 2;" ::: "memory")
#define CP_WAIT1()  asm volatile("cp.async.wait_group 1;" ::: "memory")
#define CP_WAIT0()  asm volatile("cp.async.wait_group 0;" ::: "memory")

__device__ __forceinline__ uint32_t pack_h2(float lo, float hi) {
    __half2 h = __floats2half2_rn(lo, hi);
    return *(uint32_t*)&h;
}
// packed ex2.approx on two fp16 lanes
__device__ __forceinline__ uint32_t hexp2_x2(uint32_t x) {
    uint32_t r;
    asm("ex2.approx.f16x2 %0, %1;" : "=r"(r) : "r"(x));
    return r;
}
__device__ __forceinline__ void split_f16(float v, float& hf, float& lf) {
    __half h = __float2half_rn(v);
    hf = __half2float(h);
    lf = v - hf;
}

// ---------------------------------------------------------------------------
// Scratch
// ---------------------------------------------------------------------------
__device__ float g_rope_cos[SEQ * 32];
__device__ float g_rope_sin[SEQ * 32];

__device__ __half g_X[NROWS * DMODEL];            // fp16(query)
__device__ __half g_Wqkv_h[QKV_N * DMODEL];
__device__ __half g_Wqkv_l[QKV_N * DMODEL];
__device__ __half g_Wout_h[DMODEL * DMODEL];
__device__ __half g_Wout_l[DMODEL * DMODEL];

// Q hi/lo: [bh][s][64]; K single: [bh][s][64]; V single transposed: [bh][d][s]
__device__ __half g_Qh[64 * SEQ * HDIM];
__device__ __half g_Ql[64 * SEQ * HDIM];
__device__ __half g_K[64 * SEQ * HDIM];
__device__ __half g_Vt[64 * HDIM * SEQ];

__device__ __half g_attn[NROWS * DMODEL];         // fp16 single

// ---------------------------------------------------------------------------
// RoPE tables
// ---------------------------------------------------------------------------
__global__ void rope_table_kernel() {
    int idx = blockIdx.x * blockDim.x + threadIdx.x;
    if (idx >= SEQ * 32) return;
    int s = idx >> 5;
    int i = idx & 31;
    float inv_freq = powf(10000.0f, -(float)i / 32.0f);
    float ang = (float)s * inv_freq;
    float sn, cs;
    sincosf(ang, &sn, &cs);
    g_rope_cos[idx] = cs;
    g_rope_sin[idx] = sn;
}

// ---------------------------------------------------------------------------
// Convert kernels
// ---------------------------------------------------------------------------
__global__ void conv_x_kernel(const float* __restrict__ src) {
    int i = (blockIdx.x * blockDim.x + threadIdx.x) * 4;
    if (i >= NROWS * DMODEL) return;
    float4 v = *(const float4*)(src + i);
    uint2 w;
    w.x = pack_h2(v.x, v.y);
    w.y = pack_h2(v.z, v.w);
    *(uint2*)(g_X + i) = w;
}

template <int SEL>   // 0 = W_qkv, 1 = W_out
__global__ void conv_w_kernel(const float* __restrict__ src) {
    constexpr int N = (SEL == 0) ? QKV_N * DMODEL : DMODEL * DMODEL;
    __half* hp = (SEL == 0) ? g_Wqkv_h : g_Wout_h;
    __half* lp = (SEL == 0) ? g_Wqkv_l : g_Wout_l;
    int i = (blockIdx.x * blockDim.x + threadIdx.x) * 4;
    if (i >= N) return;
    float4 v = *(const float4*)(src + i);
    float vv[4] = {v.x, v.y, v.z, v.w};
    float hh[4], ll[4];
#pragma unroll
    for (int j = 0; j < 4; j++) split_f16(vv[j], hh[j], ll[j]);
    uint2 wh, wl;
    wh.x = pack_h2(hh[0], hh[1]); wh.y = pack_h2(hh[2], hh[3]);
    wl.x = pack_h2(ll[0], ll[1]); wl.y = pack_h2(ll[2], ll[3]);
    *(uint2*)(hp + i) = wh;
    *(uint2*)(lp + i) = wl;
}

// ---------------------------------------------------------------------------
// GEMM: C[m,n] = sum_k A[m,k]*B[n,k] (+bias); A single fp16, B = Bh+Bl.
// BM=128 BN=128 BK=32; 256 threads (8 warps 4x2); 3-stage cp.async ring.
// MODE 0: A=g_X, B=W_qkv; epilogue bias+RoPE -> Qh/Ql, K, Vt
// MODE 1: A=g_attn, B=W_out; epilogue bias -> out fp32
// ---------------------------------------------------------------------------
#define SAB 80     // smem row stride bytes (40 halves)
static constexpr uint32_t GOFF_A = 0, GOFF_BH = 10240, GOFF_BL = 20480;
static constexpr uint32_t GBUFSZ = 30720;
static constexpr uint32_t GOFF_BIAS = 92160;
static constexpr uint32_t GEMM_SMEM = 92672;

template <int MODE>
__global__ __launch_bounds__(256, 2) void mma_gemm_kernel(
    const float* __restrict__ bias, float* __restrict__ outp)
{
    extern __shared__ char smch[];
    uint32_t sb = smem_to_u32(smch);
    int tid = threadIdx.x;
    int wid = tid >> 5;
    int lane = tid & 31;
    int g = lane >> 2;
    int t2 = (lane & 3) * 2;
    int warp_m = wid >> 1;
    int warp_n = wid & 1;
    int m0 = blockIdx.x * 128;
    int n0 = blockIdx.y * 128;

    const __half* A  = (MODE == 0) ? g_X : g_attn;
    const __half* Bh = (MODE == 0) ? g_Wqkv_h : g_Wout_h;
    const __half* Bl = (MODE == 0) ? g_Wqkv_l : g_Wout_l;

    float* sbias = (float*)(smch + GOFF_BIAS);
    if (tid < 128) sbias[tid] = bias[n0 + tid];

    float acc[2][8][4];
#pragma unroll
    for (int mt = 0; mt < 2; mt++)
#pragma unroll
        for (int nt = 0; nt < 8; nt++)
#pragma unroll
            for (int r = 0; r < 4; r++) acc[mt][nt][r] = 0.f;

    auto fill = [&](int stage, int k0) {
        uint32_t bofs = sb + (uint32_t)stage * GBUFSZ;
#pragma unroll
        for (int i = 0; i < 2; i++) {
            int c = i * 256 + tid;
            int row = c >> 2;
            int c8 = c & 3;
            uint32_t doff = (uint32_t)row * SAB + c8 * 16;
            CP_ASYNC16(bofs + GOFF_A  + doff, A  + (size_t)(m0 + row) * DMODEL + k0 + c8 * 8);
            CP_ASYNC16(bofs + GOFF_BH + doff, Bh + (size_t)(n0 + row) * DMODEL + k0 + c8 * 8);
            CP_ASYNC16(bofs + GOFF_BL + doff, Bl + (size_t)(n0 + row) * DMODEL + k0 + c8 * 8);
        }
    };

    fill(0, 0);  CP_COMMIT();
    fill(1, 32); CP_COMMIT();

#pragma unroll 1
    for (int ck = 0; ck < 32; ck++) {
        if (ck < 31) CP_WAIT1(); else CP_WAIT0();
        __syncthreads();
        if (ck < 30) {
            fill((ck + 2) % 3, (ck + 2) * 32);
            CP_COMMIT();
        }

        uint32_t bb = sb + (uint32_t)(ck % 3) * GBUFSZ;
        uint32_t af[2][2][4];
#pragma unroll
        for (int mt = 0; mt < 2; mt++)
#pragma unroll
            for (int kss = 0; kss < 2; kss++) {
                uint32_t addr = bb + GOFF_A
                    + (uint32_t)(warp_m * 32 + mt * 16 + (lane & 15)) * SAB
                    + (uint32_t)(kss * 16 + (lane >> 4) * 8) * 2;
                ldsm_x4(af[mt][kss], addr);
            }
#pragma unroll
        for (int nt = 0; nt < 8; nt++) {
            uint32_t boff = (uint32_t)(warp_n * 64 + nt * 8 + (lane & 7)) * SAB
                          + (uint32_t)(((lane >> 3) & 3) * 8) * 2;
            uint32_t bfh[4], bfl[4];
            ldsm_x4(bfh, bb + GOFF_BH + boff);
            ldsm_x4(bfl, bb + GOFF_BL + boff);
#pragma unroll
            for (int kss = 0; kss < 2; kss++)
#pragma unroll
                for (int mt = 0; mt < 2; mt++) {
                    mma_f16(acc[mt][nt], af[mt][kss], bfh[kss * 2], bfh[kss * 2 + 1]);
                    mma_f16(acc[mt][nt], af[mt][kss], bfl[kss * 2], bfl[kss * 2 + 1]);
                }
        }
    }

    // ----- epilogue -----
    int nwb = n0 + warp_n * 64;
    if (MODE == 1) {
#pragma unroll
        for (int mt = 0; mt < 2; mt++) {
            int r0 = m0 + warp_m * 32 + mt * 16 + g;
#pragma unroll
            for (int nt = 0; nt < 8; nt++) {
                int ncol = nwb + nt * 8 + t2;
                float b0 = sbias[warp_n * 64 + nt * 8 + t2];
                float b1 = sbias[warp_n * 64 + nt * 8 + t2 + 1];
                float2 w0 = make_float2(acc[mt][nt][0] + b0, acc[mt][nt][1] + b1);
                float2 w1 = make_float2(acc[mt][nt][2] + b0, acc[mt][nt][3] + b1);
                *(float2*)(outp + (size_t)r0 * DMODEL + ncol) = w0;
                *(float2*)(outp + (size_t)(r0 + 8) * DMODEL + ncol) = w1;
            }
        }
    } else {
        int which = nwb >> 10;                 // 0=q,1=k,2=v
        int h = (nwb & 1023) >> 6;
#pragma unroll
        for (int mt = 0; mt < 2; mt++) {
            int m_g = m0 + warp_m * 32 + mt * 16 + g;
#pragma unroll
            for (int rr = 0; rr < 2; rr++) {
                int mrow = m_g + rr * 8;
                int b = mrow >> 11;
                int s = mrow & 2047;
                int bh = b * NHEADS + h;
                if (which == 2) {
#pragma unroll
                    for (int nt = 0; nt < 8; nt++) {
#pragma unroll
                        for (int dd = 0; dd < 2; dd++) {
                            int d = nt * 8 + t2 + dd;
                            float v = acc[mt][nt][rr * 2 + dd] + sbias[warp_n * 64 + d];
                            g_Vt[((size_t)bh * 64 + d) * SEQ + s] = __float2half_rn(v);
                        }
                    }
                } else {
                    size_t rowbase = ((size_t)bh * SEQ + s) * 64;
                    float qs = (which == 0) ? (0.125f * LOG2E) : 1.0f;
#pragma unroll
                    for (int nt = 0; nt < 4; nt++) {
#pragma unroll
                        for (int dd = 0; dd < 2; dd++) {
                            int d = nt * 8 + t2 + dd;   // 0..31
                            float x1 = acc[mt][nt][rr * 2 + dd]     + sbias[warp_n * 64 + d];
                            float x2 = acc[mt][nt + 4][rr * 2 + dd] + sbias[warp_n * 64 + d + 32];
                            float cs = g_rope_cos[s * 32 + d];
                            float sn = g_rope_sin[s * 32 + d];
                            float y1 = (x1 * cs - x2 * sn) * qs;
                            float y2 = (x2 * cs + x1 * sn) * qs;
                            if (which == 0) {
                                float h1, l1, h2, l2;
                                split_f16(y1, h1, l1);
                                split_f16(y2, h2, l2);
                                g_Qh[rowbase + d]      = __float2half_rn(h1);
                                g_Ql[rowbase + d]      = __float2half_rn(l1);
                                g_Qh[rowbase + d + 32] = __float2half_rn(h2);
                                g_Ql[rowbase + d + 32] = __float2half_rn(l2);
                            } else {
                                g_K[rowbase + d]      = __float2half_rn(y1);
                                g_K[rowbase + d + 32] = __float2half_rn(y2);
                            }
                        }
                    }
                }
            }
        }
    }
}

// ---------------------------------------------------------------------------
// Flash attention: scores = (Qh+Ql)·K (2 terms), PV = P·V (1 term, fp16 P via
// packed HEX2).  3-stage KV ring, one barrier per tile.
// Grid (32 qtiles, 64 bh), 128 threads (4 warps x 16 q-rows).
// smem: QH 0, QL 9216; KV stages at 18432 (K +0, V +9216), stride 18432 x3.
// ---------------------------------------------------------------------------
#define SR 144
static constexpr uint32_t AQH = 0, AQL = 9216, AKV = 18432, KVSZ = 18432;
static constexpr uint32_t ATTN_SMEM = AKV + 3 * KVSZ;   // 73728

__global__ __launch_bounds__(128, 3) void attn_mma_kernel()
{
    extern __shared__ char smch[];
    uint32_t sb = smem_to_u32(smch);
    int tid = threadIdx.x;
    int wid = tid >> 5;
    int lane = tid & 31;
    int g = lane >> 2;
    int t2 = (lane & 3) * 2;
    int bh = blockIdx.y;
    int qt = blockIdx.x;

    auto kv_fill = [&](int stage, int kt) {
        uint32_t kb = sb + AKV + (uint32_t)stage * KVSZ;
#pragma unroll
        for (int i = 0; i < 4; i++) {
            int c = i * 128 + tid;
            int row = c >> 3;
            int c8 = c & 7;
            uint32_t doff = (uint32_t)row * SR + c8 * 16;
            CP_ASYNC16(kb + doff, g_K + ((size_t)bh * SEQ + kt * 64 + row) * 64 + c8 * 8);
            CP_ASYNC16(kb + 9216 + doff,
                       g_Vt + ((size_t)bh * 64 + row) * SEQ + kt * 64 + c8 * 8);
        }
    };

    // Q fill (own group), then KV stages 0,1
#pragma unroll
    for (int i = 0; i < 4; i++) {
        int c = i * 128 + tid;
        int row = c >> 3;
        int c8 = c & 7;
        uint32_t doff = (uint32_t)row * SR + c8 * 16;
        size_t qs = ((size_t)bh * SEQ + qt * 64 + row) * 64 + c8 * 8;
        CP_ASYNC16(sb + AQH + doff, g_Qh + qs);
        CP_ASYNC16(sb + AQL + doff, g_Ql + qs);
    }
    CP_COMMIT();
    kv_fill(0, 0); CP_COMMIT();
    kv_fill(1, 1); CP_COMMIT();
    CP_WAIT2();          // Q done
    __syncthreads();

    uint32_t qfh[4][4], qfl[4][4];
    {
        int rb = wid * 16;
#pragma unroll
        for (int ks = 0; ks < 4; ks++) {
            uint32_t addr = sb + (uint32_t)(rb + (lane & 15)) * SR
                          + (uint32_t)(ks * 16 + (lane >> 4) * 8) * 2;
            ldsm_x4(qfh[ks], addr + AQH);
            ldsm_x4(qfl[ks], addr + AQL);
        }
    }

    float o[8][4];
#pragma unroll
    for (int nt = 0; nt < 8; nt++)
#pragma unroll
        for (int r = 0; r < 4; r++) o[nt][r] = 0.f;
    float mrow0 = -1e30f, mrow1 = -1e30f, lrow0 = 0.f, lrow1 = 0.f;

#pragma unroll 1
    for (int kt = 0; kt < 32; kt++) {
        if (kt < 31) CP_WAIT1(); else CP_WAIT0();
        __syncthreads();
        if (kt < 30) {
            kv_fill((kt + 2) % 3, kt + 2);
            CP_COMMIT();
        }

        uint32_t kb = sb + AKV + (uint32_t)(kt % 3) * KVSZ;

        // scores: (Qh + Ql) x K
        float sacc[8][4];
#pragma unroll
        for (int nt = 0; nt < 8; nt++)
#pragma unroll
            for (int r = 0; r < 4; r++) sacc[nt][r] = 0.f;
#pragma unroll
        for (int kh = 0; kh < 2; kh++) {
#pragma unroll
            for (int nt = 0; nt < 8; nt++) {
                uint32_t boff = (uint32_t)(nt * 8 + (lane & 7)) * SR
                              + (uint32_t)(kh * 32 + ((lane >> 3) & 3) * 8) * 2;
                uint32_t bf[4];
                ldsm_x4(bf, kb + boff);
#pragma unroll
                for (int kss = 0; kss < 2; kss++) {
                    int ks = kh * 2 + kss;
                    mma_f16(sacc[nt], qfh[ks], bf[kss * 2], bf[kss * 2 + 1]);
                    mma_f16(sacc[nt], qfl[ks], bf[kss * 2], bf[kss * 2 + 1]);
                }
            }
        }

        // online softmax in log2 domain (rows g, g+8)
        float mx0 = sacc[0][0], mx1 = sacc[0][2];
#pragma unroll
        for (int nt = 0; nt < 8; nt++) {
            mx0 = fmaxf(mx0, fmaxf(sacc[nt][0], sacc[nt][1]));
            mx1 = fmaxf(mx1, fmaxf(sacc[nt][2], sacc[nt][3]));
        }
        mx0 = fmaxf(mx0, __shfl_xor_sync(0xffffffffu, mx0, 1));
        mx0 = fmaxf(mx0, __shfl_xor_sync(0xffffffffu, mx0, 2));
        mx1 = fmaxf(mx1, __shfl_xor_sync(0xffffffffu, mx1, 1));
        mx1 = fmaxf(mx1, __shfl_xor_sync(0xffffffffu, mx1, 2));
        float mn0 = fmaxf(mrow0, mx0);
        float mn1 = fmaxf(mrow1, mx1);
        float cr0 = exp2f(mrow0 - mn0);
        float cr1 = exp2f(mrow1 - mn1);
        mrow0 = mn0; mrow1 = mn1;

        // P = exp2(s - m) computed in packed fp16 (directly the MMA fragment)
        uint32_t ph[8][2];
        float ps0 = 0.f, ps1 = 0.f;
#pragma unroll
        for (int nt = 0; nt < 8; nt++) {
            ph[nt][0] = hexp2_x2(pack_h2(sacc[nt][0] - mn0, sacc[nt][1] - mn0));
            ph[nt][1] = hexp2_x2(pack_h2(sacc[nt][2] - mn1, sacc[nt][3] - mn1));
            float2 f0 = __half22float2(*(__half2*)&ph[nt][0]);
            float2 f1 = __half22float2(*(__half2*)&ph[nt][1]);
            ps0 += f0.x + f0.y;
            ps1 += f1.x + f1.y;
        }
        ps0 += __shfl_xor_sync(0xffffffffu, ps0, 1);
        ps0 += __shfl_xor_sync(0xffffffffu, ps0, 2);
        ps1 += __shfl_xor_sync(0xffffffffu, ps1, 1);
        ps1 += __shfl_xor_sync(0xffffffffu, ps1, 2);
        lrow0 = lrow0 * cr0 + ps0;
        lrow1 = lrow1 * cr1 + ps1;
#pragma unroll
        for (int nt = 0; nt < 8; nt++) {
            o[nt][0] *= cr0; o[nt][1] *= cr0;
            o[nt][2] *= cr1; o[nt][3] *= cr1;
        }

        // O += P x V (single term)
#pragma unroll
        for (int kh = 0; kh < 2; kh++) {
#pragma unroll
            for (int nt = 0; nt < 8; nt++) {
                uint32_t boff = (uint32_t)(nt * 8 + (lane & 7)) * SR
                              + (uint32_t)(kh * 32 + ((lane >> 3) & 3) * 8) * 2;
                uint32_t vf[4];
                ldsm_x4(vf, kb + 9216 + boff);
#pragma unroll
                for (int kss = 0; kss < 2; kss++) {
                    int ks = kh * 2 + kss;
                    uint32_t aPh[4] = {ph[2 * ks][0], ph[2 * ks][1],
                                       ph[2 * ks + 1][0], ph[2 * ks + 1][1]};
                    mma_f16(o[nt], aPh, vf[kss * 2], vf[kss * 2 + 1]);
                }
            }
        }
    }

    // epilogue
    float inv0 = 1.f / lrow0;
    float inv1 = 1.f / lrow1;
    int b = bh >> 4, h = bh & 15;
    int s0 = qt * 64 + wid * 16 + g;
    int s1 = s0 + 8;
    size_t r0 = ((size_t)b * SEQ + s0) * DMODEL + h * 64;
    size_t r1 = ((size_t)b * SEQ + s1) * DMODEL + h * 64;
#pragma unroll
    for (int nt = 0; nt < 8; nt++) {
        int d0 = nt * 8 + t2;
        *(uint32_t*)(g_attn + r0 + d0) = pack_h2(o[nt][0] * inv0, o[nt][1] * inv0);
        *(uint32_t*)(g_attn + r1 + d0) = pack_h2(o[nt][2] * inv1, o[nt][3] * inv1);
    }
}

// ---------------------------------------------------------------------------
extern "C" void kernel_launch(void* const* d_in, const int* in_sizes, int n_in,
                              void* d_out, int out_size)
{
    const float* query = (const float*)d_in[0];
    const float* W_qkv = (const float*)d_in[1];
    const float* b_qkv = (const float*)d_in[2];
    const float* W_out = (const float*)d_in[3];
    const float* b_out = (const float*)d_in[4];
    float* out = (float*)d_out;

    cudaFuncSetAttribute(mma_gemm_kernel<0>, cudaFuncAttributeMaxDynamicSharedMemorySize, GEMM_SMEM);
    cudaFuncSetAttribute(mma_gemm_kernel<1>, cudaFuncAttributeMaxDynamicSharedMemorySize, GEMM_SMEM);
    cudaFuncSetAttribute(attn_mma_kernel, cudaFuncAttributeMaxDynamicSharedMemorySize, ATTN_SMEM);

    rope_table_kernel<<<(SEQ * 32 + 255) / 256, 256>>>();
    conv_x_kernel<<<(NROWS * DMODEL / 4 + 255) / 256, 256>>>(query);
    conv_w_kernel<0><<<(QKV_N * DMODEL / 4 + 255) / 256, 256>>>(W_qkv);
    conv_w_kernel<1><<<(DMODEL * DMODEL / 4 + 255) / 256, 256>>>(W_out);

    {
        dim3 grid(NROWS / 128, QKV_N / 128);   // 64 x 24
        mma_gemm_kernel<0><<<grid, 256, GEMM_SMEM>>>(b_qkv, nullptr);
    }
    {
        dim3 grid(SEQ / 64, BATCH * NHEADS);   // 32 x 64
        attn_mma_kernel<<<grid, 128, ATTN_SMEM>>>();
    }
    {
        dim3 grid(NROWS / 128, DMODEL / 128);  // 64 x 8
        mma_gemm_kernel<1><<<grid, 256, GEMM_SMEM>>>(b_out, out);
    }
}

// round 11
// speedup vs baseline: 5.4893x; 1.0497x over previous
#include <cuda_runtime.h>
#include <cuda_fp16.h>
#include <math.h>
#include <stdint.h>

#define BATCH 4
#define SEQ 2048
#define DMODEL 1024
#define NHEADS 16
#define HDIM 64
#define NROWS (BATCH * SEQ)          // 8192
#define QKV_N (3 * DMODEL)           // 3072
#define LOG2E 1.4426950408889634f

// ---------------------------------------------------------------------------
// PTX helpers
// ---------------------------------------------------------------------------
__device__ __forceinline__ uint32_t smem_to_u32(const void* p) {
    uint32_t a;
    asm("{ .reg .u64 t; cvta.to.shared.u64 t, %1; cvt.u32.u64 %0, t; }" : "=r"(a) : "l"(p));
    return a;
}

__device__ __forceinline__ void mma_f16(float* d, const uint32_t* a,
                                        uint32_t b0, uint32_t b1) {
    asm volatile(
        "mma.sync.aligned.m16n8k16.row.col.f32.f16.f16.f32 "
        "{%0,%1,%2,%3}, {%4,%5,%6,%7}, {%8,%9}, {%0,%1,%2,%3};"
        : "+f"(d[0]), "+f"(d[1]), "+f"(d[2]), "+f"(d[3])
        : "r"(a[0]), "r"(a[1]), "r"(a[2]), "r"(a[3]), "r"(b0), "r"(b1));
}

__device__ __forceinline__ void ldsm_x4(uint32_t* r, uint32_t addr) {
    asm volatile("ldmatrix.sync.aligned.m8n8.x4.shared.b16 {%0,%1,%2,%3}, [%4];"
                 : "=r"(r[0]), "=r"(r[1]), "=r"(r[2]), "=r"(r[3]) : "r"(addr));
}

#define CP_ASYNC16(dst, src) \
    asm volatile("cp.async.cg.shared.global [%0], [%1], 16;" :: "r"(dst), "l"(src))
#define CP_COMMIT() asm volatile("cp.async.commit_group;" ::: "memory")
#define CP_WAIT2()  asm volatile("cp.async.wait_group 2;" ::: "memory")
#define CP_WAIT1()  asm volatile("cp.async.wait_group 1;" ::: "memory")
#define CP_WAIT0()  asm volatile("cp.async.wait_group 0;" ::: "memory")

__device__ __forceinline__ uint32_t pack_h2(float lo, float hi) {
    __half2 h = __floats2half2_rn(lo, hi);
    return *(uint32_t*)&h;
}
__device__ __forceinline__ uint32_t hexp2_x2(uint32_t x) {
    uint32_t r;
    asm("ex2.approx.f16x2 %0, %1;" : "=r"(r) : "r"(x));
    return r;
}
__device__ __forceinline__ void split_f16(float v, float& hf, float& lf) {
    __half h = __float2half_rn(v);
    hf = __half2float(h);
    lf = v - hf;
}

// ---------------------------------------------------------------------------
// Scratch
// ---------------------------------------------------------------------------
__device__ float g_rope_cos[SEQ * 32];
__device__ float g_rope_sin[SEQ * 32];

__device__ __half g_X[NROWS * DMODEL];            // fp16(query)
__device__ __half g_Wqkv_h[QKV_N * DMODEL];
__device__ __half g_Wqkv_l[QKV_N * DMODEL];
__device__ __half g_Wout_h[DMODEL * DMODEL];
__device__ __half g_Wout_l[DMODEL * DMODEL];

// Q hi/lo: [bh][s][64]; K single: [bh][s][64]; V single transposed: [bh][d][s]
__device__ __half g_Qh[64 * SEQ * HDIM];
__device__ __half g_Ql[64 * SEQ * HDIM];
__device__ __half g_K[64 * SEQ * HDIM];
__device__ __half g_Vt[64 * HDIM * SEQ];

__device__ __half g_attn[NROWS * DMODEL];         // fp16 single

// ---------------------------------------------------------------------------
// prep_w: hi/lo split of BOTH weight matrices in one launch
// ---------------------------------------------------------------------------
static constexpr int WQKV_ELEMS = QKV_N * DMODEL;        // 3145728
static constexpr int WOUT_ELEMS = DMODEL * DMODEL;       // 1048576
static constexpr int PREPW_THREADS = (WQKV_ELEMS + WOUT_ELEMS) / 4;  // 1048576

__global__ void prep_w_kernel(const float* __restrict__ W_qkv,
                              const float* __restrict__ W_out) {
    int gid = blockIdx.x * blockDim.x + threadIdx.x;
    if (gid >= PREPW_THREADS) return;
    int i = gid * 4;
    const float* src;
    __half *hp, *lp;
    if (i < WQKV_ELEMS) {
        src = W_qkv + i; hp = g_Wqkv_h + i; lp = g_Wqkv_l + i;
    } else {
        int j = i - WQKV_ELEMS;
        src = W_out + j; hp = g_Wout_h + j; lp = g_Wout_l + j;
    }
    float4 v = *(const float4*)src;
    float vv[4] = {v.x, v.y, v.z, v.w};
    float hh[4], ll[4];
#pragma unroll
    for (int j = 0; j < 4; j++) split_f16(vv[j], hh[j], ll[j]);
    uint2 wh, wl;
    wh.x = pack_h2(hh[0], hh[1]); wh.y = pack_h2(hh[2], hh[3]);
    wl.x = pack_h2(ll[0], ll[1]); wl.y = pack_h2(ll[2], ll[3]);
    *(uint2*)hp = wh;
    *(uint2*)lp = wl;
}

// ---------------------------------------------------------------------------
// prep_x: X fp32->fp16 convert + RoPE table build, one launch
// ---------------------------------------------------------------------------
static constexpr int X_THREADS = NROWS * DMODEL / 4;     // 2097152
static constexpr int ROPE_ENTRIES = SEQ * 32;            // 65536

__global__ void prep_x_kernel(const float* __restrict__ src) {
    int gid = blockIdx.x * blockDim.x + threadIdx.x;
    if (gid < X_THREADS) {
        int i = gid * 4;
        float4 v = *(const float4*)(src + i);
        uint2 w;
        w.x = pack_h2(v.x, v.y);
        w.y = pack_h2(v.z, v.w);
        *(uint2*)(g_X + i) = w;
    } else {
        int idx = gid - X_THREADS;
        if (idx >= ROPE_ENTRIES) return;
        int s = idx >> 5;
        int i = idx & 31;
        float inv_freq = powf(10000.0f, -(float)i / 32.0f);
        float ang = (float)s * inv_freq;
        float sn, cs;
        sincosf(ang, &sn, &cs);
        g_rope_cos[idx] = cs;
        g_rope_sin[idx] = sn;
    }
}

// ---------------------------------------------------------------------------
// GEMM: C[m,n] = sum_k A[m,k]*B[n,k] (+bias); A single fp16, B = Bh+Bl.
// BM=128 BN=128 BK=32; 256 threads (8 warps 4x2); 3-stage cp.async ring.
// MODE 0: A=g_X, B=W_qkv; epilogue bias+RoPE -> Qh/Ql, K, Vt
// MODE 1: A=g_attn, B=W_out; epilogue bias -> out fp32
// ---------------------------------------------------------------------------
#define SAB 80     // smem row stride bytes (40 halves)
static constexpr uint32_t GOFF_A = 0, GOFF_BH = 10240, GOFF_BL = 20480;
static constexpr uint32_t GBUFSZ = 30720;
static constexpr uint32_t GOFF_BIAS = 92160;
static constexpr uint32_t GEMM_SMEM = 92672;

template <int MODE>
__global__ __launch_bounds__(256, 2) void mma_gemm_kernel(
    const float* __restrict__ bias, float* __restrict__ outp)
{
    extern __shared__ char smch[];
    uint32_t sb = smem_to_u32(smch);
    int tid = threadIdx.x;
    int wid = tid >> 5;
    int lane = tid & 31;
    int g = lane >> 2;
    int t2 = (lane & 3) * 2;
    int warp_m = wid >> 1;
    int warp_n = wid & 1;
    int m0 = blockIdx.x * 128;
    int n0 = blockIdx.y * 128;

    const __half* A  = (MODE == 0) ? g_X : g_attn;
    const __half* Bh = (MODE == 0) ? g_Wqkv_h : g_Wout_h;
    const __half* Bl = (MODE == 0) ? g_Wqkv_l : g_Wout_l;

    float* sbias = (float*)(smch + GOFF_BIAS);
    if (tid < 128) sbias[tid] = bias[n0 + tid];

    float acc[2][8][4];
#pragma unroll
    for (int mt = 0; mt < 2; mt++)
#pragma unroll
        for (int nt = 0; nt < 8; nt++)
#pragma unroll
            for (int r = 0; r < 4; r++) acc[mt][nt][r] = 0.f;

    auto fill = [&](int stage, int k0) {
        uint32_t bofs = sb + (uint32_t)stage * GBUFSZ;
#pragma unroll
        for (int i = 0; i < 2; i++) {
            int c = i * 256 + tid;
            int row = c >> 2;
            int c8 = c & 3;
            uint32_t doff = (uint32_t)row * SAB + c8 * 16;
            CP_ASYNC16(bofs + GOFF_A  + doff, A  + (size_t)(m0 + row) * DMODEL + k0 + c8 * 8);
            CP_ASYNC16(bofs + GOFF_BH + doff, Bh + (size_t)(n0 + row) * DMODEL + k0 + c8 * 8);
            CP_ASYNC16(bofs + GOFF_BL + doff, Bl + (size_t)(n0 + row) * DMODEL + k0 + c8 * 8);
        }
    };

    fill(0, 0);  CP_COMMIT();
    fill(1, 32); CP_COMMIT();

#pragma unroll 1
    for (int ck = 0; ck < 32; ck++) {
        if (ck < 31) CP_WAIT1(); else CP_WAIT0();
        __syncthreads();
        if (ck < 30) {
            fill((ck + 2) % 3, (ck + 2) * 32);
            CP_COMMIT();
        }

        uint32_t bb = sb + (uint32_t)(ck % 3) * GBUFSZ;
        uint32_t af[2][2][4];
#pragma unroll
        for (int mt = 0; mt < 2; mt++)
#pragma unroll
            for (int kss = 0; kss < 2; kss++) {
                uint32_t addr = bb + GOFF_A
                    + (uint32_t)(warp_m * 32 + mt * 16 + (lane & 15)) * SAB
                    + (uint32_t)(kss * 16 + (lane >> 4) * 8) * 2;
                ldsm_x4(af[mt][kss], addr);
            }
#pragma unroll
        for (int nt = 0; nt < 8; nt++) {
            uint32_t boff = (uint32_t)(warp_n * 64 + nt * 8 + (lane & 7)) * SAB
                          + (uint32_t)(((lane >> 3) & 3) * 8) * 2;
            uint32_t bfh[4], bfl[4];
            ldsm_x4(bfh, bb + GOFF_BH + boff);
            ldsm_x4(bfl, bb + GOFF_BL + boff);
#pragma unroll
            for (int kss = 0; kss < 2; kss++)
#pragma unroll
                for (int mt = 0; mt < 2; mt++) {
                    mma_f16(acc[mt][nt], af[mt][kss], bfh[kss * 2], bfh[kss * 2 + 1]);
                    mma_f16(acc[mt][nt], af[mt][kss], bfl[kss * 2], bfl[kss * 2 + 1]);
                }
        }
    }

    // ----- epilogue -----
    int nwb = n0 + warp_n * 64;
    if (MODE == 1) {
#pragma unroll
        for (int mt = 0; mt < 2; mt++) {
            int r0 = m0 + warp_m * 32 + mt * 16 + g;
#pragma unroll
            for (int nt = 0; nt < 8; nt++) {
                int ncol = nwb + nt * 8 + t2;
                float b0 = sbias[warp_n * 64 + nt * 8 + t2];
                float b1 = sbias[warp_n * 64 + nt * 8 + t2 + 1];
                float2 w0 = make_float2(acc[mt][nt][0] + b0, acc[mt][nt][1] + b1);
                float2 w1 = make_float2(acc[mt][nt][2] + b0, acc[mt][nt][3] + b1);
                *(float2*)(outp + (size_t)r0 * DMODEL + ncol) = w0;
                *(float2*)(outp + (size_t)(r0 + 8) * DMODEL + ncol) = w1;
            }
        }
    } else {
        int which = nwb >> 10;                 // 0=q,1=k,2=v
        int h = (nwb & 1023) >> 6;
#pragma unroll
        for (int mt = 0; mt < 2; mt++) {
            int m_g = m0 + warp_m * 32 + mt * 16 + g;
#pragma unroll
            for (int rr = 0; rr < 2; rr++) {
                int mrow = m_g + rr * 8;
                int b = mrow >> 11;
                int s = mrow & 2047;
                int bh = b * NHEADS + h;
                if (which == 2) {
#pragma unroll
                    for (int nt = 0; nt < 8; nt++) {
#pragma unroll
                        for (int dd = 0; dd < 2; dd++) {
                            int d = nt * 8 + t2 + dd;
                            float v = acc[mt][nt][rr * 2 + dd] + sbias[warp_n * 64 + d];
                            g_Vt[((size_t)bh * 64 + d) * SEQ + s] = __float2half_rn(v);
                        }
                    }
                } else {
                    size_t rowbase = ((size_t)bh * SEQ + s) * 64;
                    float qs = (which == 0) ? (0.125f * LOG2E) : 1.0f;
#pragma unroll
                    for (int nt = 0; nt < 4; nt++) {
                        int d = nt * 8 + t2;            // even, 0..30
                        float x1a = acc[mt][nt][rr * 2]         + sbias[warp_n * 64 + d];
                        float x1b = acc[mt][nt][rr * 2 + 1]     + sbias[warp_n * 64 + d + 1];
                        float x2a = acc[mt][nt + 4][rr * 2]     + sbias[warp_n * 64 + d + 32];
                        float x2b = acc[mt][nt + 4][rr * 2 + 1] + sbias[warp_n * 64 + d + 33];
                        float csa = g_rope_cos[s * 32 + d],   sna = g_rope_sin[s * 32 + d];
                        float csb = g_rope_cos[s * 32 + d+1], snb = g_rope_sin[s * 32 + d+1];
                        float y1a = (x1a * csa - x2a * sna) * qs;
                        float y1b = (x1b * csb - x2b * snb) * qs;
                        float y2a = (x2a * csa + x1a * sna) * qs;
                        float y2b = (x2b * csb + x1b * snb) * qs;
                        if (which == 0) {
                            float h1a, l1a, h1b, l1b, h2a, l2a, h2b, l2b;
                            split_f16(y1a, h1a, l1a); split_f16(y1b, h1b, l1b);
                            split_f16(y2a, h2a, l2a); split_f16(y2b, h2b, l2b);
                            *(uint32_t*)(g_Qh + rowbase + d)      = pack_h2(h1a, h1b);
                            *(uint32_t*)(g_Ql + rowbase + d)      = pack_h2(l1a, l1b);
                            *(uint32_t*)(g_Qh + rowbase + d + 32) = pack_h2(h2a, h2b);
                            *(uint32_t*)(g_Ql + rowbase + d + 32) = pack_h2(l2a, l2b);
                        } else {
                            *(uint32_t*)(g_K + rowbase + d)      = pack_h2(y1a, y1b);
                            *(uint32_t*)(g_K + rowbase + d + 32) = pack_h2(y2a, y2b);
                        }
                    }
                }
            }
        }
    }
}

// ---------------------------------------------------------------------------
// Flash attention: scores = (Qh+Ql)·K (2 terms), PV = P·V (fp16 P via packed
// HEX2).  3-stage KV ring, one barrier per tile.
// Grid (32 qtiles, 64 bh), 128 threads (4 warps x 16 q-rows).
// ---------------------------------------------------------------------------
#define SR 144
static constexpr uint32_t AQH = 0, AQL = 9216, AKV = 18432, KVSZ = 18432;
static constexpr uint32_t ATTN_SMEM = AKV + 3 * KVSZ;   // 73728

__global__ __launch_bounds__(128, 3) void attn_mma_kernel()
{
    extern __shared__ char smch[];
    uint32_t sb = smem_to_u32(smch);
    int tid = threadIdx.x;
    int wid = tid >> 5;
    int lane = tid & 31;
    int g = lane >> 2;
    int t2 = (lane & 3) * 2;
    int bh = blockIdx.y;
    int qt = blockIdx.x;

    auto kv_fill = [&](int stage, int kt) {
        uint32_t kb = sb + AKV + (uint32_t)stage * KVSZ;
#pragma unroll
        for (int i = 0; i < 4; i++) {
            int c = i * 128 + tid;
            int row = c >> 3;
            int c8 = c & 7;
            uint32_t doff = (uint32_t)row * SR + c8 * 16;
            CP_ASYNC16(kb + doff, g_K + ((size_t)bh * SEQ + kt * 64 + row) * 64 + c8 * 8);
            CP_ASYNC16(kb + 9216 + doff,
                       g_Vt + ((size_t)bh * 64 + row) * SEQ + kt * 64 + c8 * 8);
        }
    };

#pragma unroll
    for (int i = 0; i < 4; i++) {
        int c = i * 128 + tid;
        int row = c >> 3;
        int c8 = c & 7;
        uint32_t doff = (uint32_t)row * SR + c8 * 16;
        size_t qs = ((size_t)bh * SEQ + qt * 64 + row) * 64 + c8 * 8;
        CP_ASYNC16(sb + AQH + doff, g_Qh + qs);
        CP_ASYNC16(sb + AQL + doff, g_Ql + qs);
    }
    CP_COMMIT();
    kv_fill(0, 0); CP_COMMIT();
    kv_fill(1, 1); CP_COMMIT();
    CP_WAIT2();
    __syncthreads();

    uint32_t qfh[4][4], qfl[4][4];
    {
        int rb = wid * 16;
#pragma unroll
        for (int ks = 0; ks < 4; ks++) {
            uint32_t addr = sb + (uint32_t)(rb + (lane & 15)) * SR
                          + (uint32_t)(ks * 16 + (lane >> 4) * 8) * 2;
            ldsm_x4(qfh[ks], addr + AQH);
            ldsm_x4(qfl[ks], addr + AQL);
        }
    }

    float o[8][4];
#pragma unroll
    for (int nt = 0; nt < 8; nt++)
#pragma unroll
        for (int r = 0; r < 4; r++) o[nt][r] = 0.f;
    float mrow0 = -1e30f, mrow1 = -1e30f, lrow0 = 0.f, lrow1 = 0.f;

#pragma unroll 1
    for (int kt = 0; kt < 32; kt++) {
        if (kt < 31) CP_WAIT1(); else CP_WAIT0();
        __syncthreads();
        if (kt < 30) {
            kv_fill((kt + 2) % 3, kt + 2);
            CP_COMMIT();
        }

        uint32_t kb = sb + AKV + (uint32_t)(kt % 3) * KVSZ;

        float sacc[8][4];
#pragma unroll
        for (int nt = 0; nt < 8; nt++)
#pragma unroll
            for (int r = 0; r < 4; r++) sacc[nt][r] = 0.f;
#pragma unroll
        for (int kh = 0; kh < 2; kh++) {
#pragma unroll
            for (int nt = 0; nt < 8; nt++) {
                uint32_t boff = (uint32_t)(nt * 8 + (lane & 7)) * SR
                              + (uint32_t)(kh * 32 + ((lane >> 3) & 3) * 8) * 2;
                uint32_t bf[4];
                ldsm_x4(bf, kb + boff);
#pragma unroll
                for (int kss = 0; kss < 2; kss++) {
                    int ks = kh * 2 + kss;
                    mma_f16(sacc[nt], qfh[ks], bf[kss * 2], bf[kss * 2 + 1]);
                    mma_f16(sacc[nt], qfl[ks], bf[kss * 2], bf[kss * 2 + 1]);
                }
            }
        }

        float mx0 = sacc[0][0], mx1 = sacc[0][2];
#pragma unroll
        for (int nt = 0; nt < 8; nt++) {
            mx0 = fmaxf(mx0, fmaxf(sacc[nt][0], sacc[nt][1]));
            mx1 = fmaxf(mx1, fmaxf(sacc[nt][2], sacc[nt][3]));
        }
        mx0 = fmaxf(mx0, __shfl_xor_sync(0xffffffffu, mx0, 1));
        mx0 = fmaxf(mx0, __shfl_xor_sync(0xffffffffu, mx0, 2));
        mx1 = fmaxf(mx1, __shfl_xor_sync(0xffffffffu, mx1, 1));
        mx1 = fmaxf(mx1, __shfl_xor_sync(0xffffffffu, mx1, 2));
        float mn0 = fmaxf(mrow0, mx0);
        float mn1 = fmaxf(mrow1, mx1);
        float cr0 = exp2f(mrow0 - mn0);
        float cr1 = exp2f(mrow1 - mn1);
        mrow0 = mn0; mrow1 = mn1;

        uint32_t ph[8][2];
        float ps0 = 0.f, ps1 = 0.f;
#pragma unroll
        for (int nt = 0; nt < 8; nt++) {
            ph[nt][0] = hexp2_x2(pack_h2(sacc[nt][0] - mn0, sacc[nt][1] - mn0));
            ph[nt][1] = hexp2_x2(pack_h2(sacc[nt][2] - mn1, sacc[nt][3] - mn1));
            float2 f0 = __half22float2(*(__half2*)&ph[nt][0]);
            float2 f1 = __half22float2(*(__half2*)&ph[nt][1]);
            ps0 += f0.x + f0.y;
            ps1 += f1.x + f1.y;
        }
        ps0 += __shfl_xor_sync(0xffffffffu, ps0, 1);
        ps0 += __shfl_xor_sync(0xffffffffu, ps0, 2);
        ps1 += __shfl_xor_sync(0xffffffffu, ps1, 1);
        ps1 += __shfl_xor_sync(0xffffffffu, ps1, 2);
        lrow0 = lrow0 * cr0 + ps0;
        lrow1 = lrow1 * cr1 + ps1;
#pragma unroll
        for (int nt = 0; nt < 8; nt++) {
            o[nt][0] *= cr0; o[nt][1] *= cr0;
            o[nt][2] *= cr1; o[nt][3] *= cr1;
        }

#pragma unroll
        for (int kh = 0; kh < 2; kh++) {
#pragma unroll
            for (int nt = 0; nt < 8; nt++) {
                uint32_t boff = (uint32_t)(nt * 8 + (lane & 7)) * SR
                              + (uint32_t)(kh * 32 + ((lane >> 3) & 3) * 8) * 2;
                uint32_t vf[4];
                ldsm_x4(vf, kb + 9216 + boff);
#pragma unroll
                for (int kss = 0; kss < 2; kss++) {
                    int ks = kh * 2 + kss;
                    uint32_t aPh[4] = {ph[2 * ks][0], ph[2 * ks][1],
                                       ph[2 * ks + 1][0], ph[2 * ks + 1][1]};
                    mma_f16(o[nt], aPh, vf[kss * 2], vf[kss * 2 + 1]);
                }
            }
        }
    }

    float inv0 = 1.f / lrow0;
    float inv1 = 1.f / lrow1;
    int b = bh >> 4, h = bh & 15;
    int s0 = qt * 64 + wid * 16 + g;
    int s1 = s0 + 8;
    size_t r0 = ((size_t)b * SEQ + s0) * DMODEL + h * 64;
    size_t r1 = ((size_t)b * SEQ + s1) * DMODEL + h * 64;
#pragma unroll
    for (int nt = 0; nt < 8; nt++) {
        int d0 = nt * 8 + t2;
        *(uint32_t*)(g_attn + r0 + d0) = pack_h2(o[nt][0] * inv0, o[nt][1] * inv0);
        *(uint32_t*)(g_attn + r1 + d0) = pack_h2(o[nt][2] * inv1, o[nt][3] * inv1);
    }
}

// ---------------------------------------------------------------------------
extern "C" void kernel_launch(void* const* d_in, const int* in_sizes, int n_in,
                              void* d_out, int out_size)
{
    const float* query = (const float*)d_in[0];
    const float* W_qkv = (const float*)d_in[1];
    const float* b_qkv = (const float*)d_in[2];
    const float* W_out = (const float*)d_in[3];
    const float* b_out = (const float*)d_in[4];
    float* out = (float*)d_out;

    cudaFuncSetAttribute(mma_gemm_kernel<0>, cudaFuncAttributeMaxDynamicSharedMemorySize, GEMM_SMEM);
    cudaFuncSetAttribute(mma_gemm_kernel<1>, cudaFuncAttributeMaxDynamicSharedMemorySize, GEMM_SMEM);
    cudaFuncSetAttribute(attn_mma_kernel, cudaFuncAttributeMaxDynamicSharedMemorySize, ATTN_SMEM);

    // 1: weight splits (both matrices)
    prep_w_kernel<<<(PREPW_THREADS + 255) / 256, 256>>>(W_qkv, W_out);
    // 2: X convert + rope tables
    prep_x_kernel<<<(X_THREADS + ROPE_ENTRIES + 255) / 256, 256>>>(query);
    // 3: QKV projection + RoPE + scatter
    {
        dim3 grid(NROWS / 128, QKV_N / 128);   // 64 x 24
        mma_gemm_kernel<0><<<grid, 256, GEMM_SMEM>>>(b_qkv, nullptr);
    }
    // 4: attention  (<- ncu capture slot)
    {
        dim3 grid(SEQ / 64, BATCH * NHEADS);   // 32 x 64
        attn_mma_kernel<<<grid, 128, ATTN_SMEM>>>();
    }
    // 5: output projection
    {
        dim3 grid(NROWS / 128, DMODEL / 128);  // 64 x 8
        mma_gemm_kernel<1><<<grid, 256, GEMM_SMEM>>>(b_out, out);
    }
}

// round 12
// speedup vs baseline: 5.8865x; 1.0724x over previous
#include <cuda_runtime.h>
#include <cuda_fp16.h>
#include <math.h>
#include <stdint.h>

#define BATCH 4
#define SEQ 2048
#define DMODEL 1024
#define NHEADS 16
#define HDIM 64
#define NROWS (BATCH * SEQ)          // 8192
#define QKV_N (3 * DMODEL)           // 3072
#define LOG2E 1.4426950408889634f

// ---------------------------------------------------------------------------
// PTX helpers
// ---------------------------------------------------------------------------
__device__ __forceinline__ uint32_t smem_to_u32(const void* p) {
    uint32_t a;
    asm("{ .reg .u64 t; cvta.to.shared.u64 t, %1; cvt.u32.u64 %0, t; }" : "=r"(a) : "l"(p));
    return a;
}

__device__ __forceinline__ void mma_f16(float* d, const uint32_t* a,
                                        uint32_t b0, uint32_t b1) {
    asm volatile(
        "mma.sync.aligned.m16n8k16.row.col.f32.f16.f16.f32 "
        "{%0,%1,%2,%3}, {%4,%5,%6,%7}, {%8,%9}, {%0,%1,%2,%3};"
        : "+f"(d[0]), "+f"(d[1]), "+f"(d[2]), "+f"(d[3])
        : "r"(a[0]), "r"(a[1]), "r"(a[2]), "r"(a[3]), "r"(b0), "r"(b1));
}

__device__ __forceinline__ void ldsm_x4(uint32_t* r, uint32_t addr) {
    asm volatile("ldmatrix.sync.aligned.m8n8.x4.shared.b16 {%0,%1,%2,%3}, [%4];"
                 : "=r"(r[0]), "=r"(r[1]), "=r"(r[2]), "=r"(r[3]) : "r"(addr));
}

#define CP_ASYNC16(dst, src) \
    asm volatile("cp.async.cg.shared.global [%0], [%1], 16;" :: "r"(dst), "l"(src))
#define CP_COMMIT() asm volatile("cp.async.commit_group;" ::: "memory")
#define CP_WAIT2()  asm volatile("cp.async.wait_group 2;" ::: "memory")
#define CP_WAIT1()  asm volatile("cp.async.wait_group 1;" ::: "memory")
#define CP_WAIT0()  asm volatile("cp.async.wait_group 0;" ::: "memory")

__device__ __forceinline__ uint32_t pack_h2(float lo, float hi) {
    __half2 h = __floats2half2_rn(lo, hi);
    return *(uint32_t*)&h;
}
__device__ __forceinline__ uint32_t hexp2_x2(uint32_t x) {
    uint32_t r;
    asm("ex2.approx.f16x2 %0, %1;" : "=r"(r) : "r"(x));
    return r;
}
__device__ __forceinline__ void split_f16(float v, float& hf, float& lf) {
    __half h = __float2half_rn(v);
    hf = __half2float(h);
    lf = v - hf;
}

// ---------------------------------------------------------------------------
// Scratch
// ---------------------------------------------------------------------------
__device__ float g_rope_cos[SEQ * 32];
__device__ float g_rope_sin[SEQ * 32];

__device__ __half g_X[NROWS * DMODEL];            // fp16(query)
__device__ __half g_Wqkv_h[QKV_N * DMODEL];
__device__ __half g_Wqkv_l[QKV_N * DMODEL];
__device__ __half g_Wout_h[DMODEL * DMODEL];
__device__ __half g_Wout_l[DMODEL * DMODEL];

// Q single: [bh][s][64]; K single: [bh][s][64]; V single transposed: [bh][d][s]
__device__ __half g_Q[64 * SEQ * HDIM];
__device__ __half g_K[64 * SEQ * HDIM];
__device__ __half g_Vt[64 * HDIM * SEQ];

__device__ __half g_attn[NROWS * DMODEL];         // fp16 single

// ---------------------------------------------------------------------------
// prep_w: hi/lo split of BOTH weight matrices in one launch
// ---------------------------------------------------------------------------
static constexpr int WQKV_ELEMS = QKV_N * DMODEL;
static constexpr int WOUT_ELEMS = DMODEL * DMODEL;
static constexpr int PREPW_THREADS = (WQKV_ELEMS + WOUT_ELEMS) / 4;

__global__ void prep_w_kernel(const float* __restrict__ W_qkv,
                              const float* __restrict__ W_out) {
    int gid = blockIdx.x * blockDim.x + threadIdx.x;
    if (gid >= PREPW_THREADS) return;
    int i = gid * 4;
    const float* src;
    __half *hp, *lp;
    if (i < WQKV_ELEMS) {
        src = W_qkv + i; hp = g_Wqkv_h + i; lp = g_Wqkv_l + i;
    } else {
        int j = i - WQKV_ELEMS;
        src = W_out + j; hp = g_Wout_h + j; lp = g_Wout_l + j;
    }
    float4 v = *(const float4*)src;
    float vv[4] = {v.x, v.y, v.z, v.w};
    float hh[4], ll[4];
#pragma unroll
    for (int j = 0; j < 4; j++) split_f16(vv[j], hh[j], ll[j]);
    uint2 wh, wl;
    wh.x = pack_h2(hh[0], hh[1]); wh.y = pack_h2(hh[2], hh[3]);
    wl.x = pack_h2(ll[0], ll[1]); wl.y = pack_h2(ll[2], ll[3]);
    *(uint2*)hp = wh;
    *(uint2*)lp = wl;
}

// ---------------------------------------------------------------------------
// prep_x: X fp32->fp16 convert + RoPE table build
// ---------------------------------------------------------------------------
static constexpr int X_THREADS = NROWS * DMODEL / 4;
static constexpr int ROPE_ENTRIES = SEQ * 32;

__global__ void prep_x_kernel(const float* __restrict__ src) {
    int gid = blockIdx.x * blockDim.x + threadIdx.x;
    if (gid < X_THREADS) {
        int i = gid * 4;
        float4 v = *(const float4*)(src + i);
        uint2 w;
        w.x = pack_h2(v.x, v.y);
        w.y = pack_h2(v.z, v.w);
        *(uint2*)(g_X + i) = w;
    } else {
        int idx = gid - X_THREADS;
        if (idx >= ROPE_ENTRIES) return;
        int s = idx >> 5;
        int i = idx & 31;
        float inv_freq = powf(10000.0f, -(float)i / 32.0f);
        float ang = (float)s * inv_freq;
        float sn, cs;
        sincosf(ang, &sn, &cs);
        g_rope_cos[idx] = cs;
        g_rope_sin[idx] = sn;
    }
}

// ---------------------------------------------------------------------------
// GEMM: C[m,n] = sum_k A[m,k]*B[n,k] (+bias); A single fp16, B = Bh+Bl.
// BM=128 BN=128 BK=32; 256 threads; 3-stage cp.async ring.
// MODE 0: A=g_X, B=W_qkv; epilogue bias+RoPE -> Q, K, Vt (all single fp16)
// MODE 1: A=g_attn, B=W_out; epilogue bias -> out fp32
// ---------------------------------------------------------------------------
#define SAB 80     // smem row stride bytes (40 halves)
static constexpr uint32_t GOFF_A = 0, GOFF_BH = 10240, GOFF_BL = 20480;
static constexpr uint32_t GBUFSZ = 30720;
static constexpr uint32_t GOFF_BIAS = 92160;
static constexpr uint32_t GEMM_SMEM = 92672;

template <int MODE>
__global__ __launch_bounds__(256, 2) void mma_gemm_kernel(
    const float* __restrict__ bias, float* __restrict__ outp)
{
    extern __shared__ char smch[];
    uint32_t sb = smem_to_u32(smch);
    int tid = threadIdx.x;
    int wid = tid >> 5;
    int lane = tid & 31;
    int g = lane >> 2;
    int t2 = (lane & 3) * 2;
    int warp_m = wid >> 1;
    int warp_n = wid & 1;
    int m0 = blockIdx.x * 128;
    int n0 = blockIdx.y * 128;

    const __half* A  = (MODE == 0) ? g_X : g_attn;
    const __half* Bh = (MODE == 0) ? g_Wqkv_h : g_Wout_h;
    const __half* Bl = (MODE == 0) ? g_Wqkv_l : g_Wout_l;

    float* sbias = (float*)(smch + GOFF_BIAS);
    if (tid < 128) sbias[tid] = bias[n0 + tid];

    float acc[2][8][4];
#pragma unroll
    for (int mt = 0; mt < 2; mt++)
#pragma unroll
        for (int nt = 0; nt < 8; nt++)
#pragma unroll
            for (int r = 0; r < 4; r++) acc[mt][nt][r] = 0.f;

    auto fill = [&](int stage, int k0) {
        uint32_t bofs = sb + (uint32_t)stage * GBUFSZ;
#pragma unroll
        for (int i = 0; i < 2; i++) {
            int c = i * 256 + tid;
            int row = c >> 2;
            int c8 = c & 3;
            uint32_t doff = (uint32_t)row * SAB + c8 * 16;
            CP_ASYNC16(bofs + GOFF_A  + doff, A  + (size_t)(m0 + row) * DMODEL + k0 + c8 * 8);
            CP_ASYNC16(bofs + GOFF_BH + doff, Bh + (size_t)(n0 + row) * DMODEL + k0 + c8 * 8);
            CP_ASYNC16(bofs + GOFF_BL + doff, Bl + (size_t)(n0 + row) * DMODEL + k0 + c8 * 8);
        }
    };

    fill(0, 0);  CP_COMMIT();
    fill(1, 32); CP_COMMIT();

#pragma unroll 1
    for (int ck = 0; ck < 32; ck++) {
        if (ck < 31) CP_WAIT1(); else CP_WAIT0();
        __syncthreads();
        if (ck < 30) {
            fill((ck + 2) % 3, (ck + 2) * 32);
            CP_COMMIT();
        }

        uint32_t bb = sb + (uint32_t)(ck % 3) * GBUFSZ;
        uint32_t af[2][2][4];
#pragma unroll
        for (int mt = 0; mt < 2; mt++)
#pragma unroll
            for (int kss = 0; kss < 2; kss++) {
                uint32_t addr = bb + GOFF_A
                    + (uint32_t)(warp_m * 32 + mt * 16 + (lane & 15)) * SAB
                    + (uint32_t)(kss * 16 + (lane >> 4) * 8) * 2;
                ldsm_x4(af[mt][kss], addr);
            }
#pragma unroll
        for (int nt = 0; nt < 8; nt++) {
            uint32_t boff = (uint32_t)(warp_n * 64 + nt * 8 + (lane & 7)) * SAB
                          + (uint32_t)(((lane >> 3) & 3) * 8) * 2;
            uint32_t bfh[4], bfl[4];
            ldsm_x4(bfh, bb + GOFF_BH + boff);
            ldsm_x4(bfl, bb + GOFF_BL + boff);
#pragma unroll
            for (int kss = 0; kss < 2; kss++)
#pragma unroll
                for (int mt = 0; mt < 2; mt++) {
                    mma_f16(acc[mt][nt], af[mt][kss], bfh[kss * 2], bfh[kss * 2 + 1]);
                    mma_f16(acc[mt][nt], af[mt][kss], bfl[kss * 2], bfl[kss * 2 + 1]);
                }
        }
    }

    // ----- epilogue -----
    int nwb = n0 + warp_n * 64;
    if (MODE == 1) {
#pragma unroll
        for (int mt = 0; mt < 2; mt++) {
            int r0 = m0 + warp_m * 32 + mt * 16 + g;
#pragma unroll
            for (int nt = 0; nt < 8; nt++) {
                int ncol = nwb + nt * 8 + t2;
                float b0 = sbias[warp_n * 64 + nt * 8 + t2];
                float b1 = sbias[warp_n * 64 + nt * 8 + t2 + 1];
                float2 w0 = make_float2(acc[mt][nt][0] + b0, acc[mt][nt][1] + b1);
                float2 w1 = make_float2(acc[mt][nt][2] + b0, acc[mt][nt][3] + b1);
                *(float2*)(outp + (size_t)r0 * DMODEL + ncol) = w0;
                *(float2*)(outp + (size_t)(r0 + 8) * DMODEL + ncol) = w1;
            }
        }
    } else {
        int which = nwb >> 10;                 // 0=q,1=k,2=v
        int h = (nwb & 1023) >> 6;
#pragma unroll
        for (int mt = 0; mt < 2; mt++) {
            int m_g = m0 + warp_m * 32 + mt * 16 + g;
#pragma unroll
            for (int rr = 0; rr < 2; rr++) {
                int mrow = m_g + rr * 8;
                int b = mrow >> 11;
                int s = mrow & 2047;
                int bh = b * NHEADS + h;
                if (which == 2) {
#pragma unroll
                    for (int nt = 0; nt < 8; nt++) {
#pragma unroll
                        for (int dd = 0; dd < 2; dd++) {
                            int d = nt * 8 + t2 + dd;
                            float v = acc[mt][nt][rr * 2 + dd] + sbias[warp_n * 64 + d];
                            g_Vt[((size_t)bh * 64 + d) * SEQ + s] = __float2half_rn(v);
                        }
                    }
                } else {
                    size_t rowbase = ((size_t)bh * SEQ + s) * 64;
                    float qs = (which == 0) ? (0.125f * LOG2E) : 1.0f;
                    __half* dst = (which == 0) ? g_Q : g_K;
#pragma unroll
                    for (int nt = 0; nt < 4; nt++) {
                        int d = nt * 8 + t2;            // even, 0..30
                        float x1a = acc[mt][nt][rr * 2]         + sbias[warp_n * 64 + d];
                        float x1b = acc[mt][nt][rr * 2 + 1]     + sbias[warp_n * 64 + d + 1];
                        float x2a = acc[mt][nt + 4][rr * 2]     + sbias[warp_n * 64 + d + 32];
                        float x2b = acc[mt][nt + 4][rr * 2 + 1] + sbias[warp_n * 64 + d + 33];
                        float csa = g_rope_cos[s * 32 + d],   sna = g_rope_sin[s * 32 + d];
                        float csb = g_rope_cos[s * 32 + d+1], snb = g_rope_sin[s * 32 + d+1];
                        float y1a = (x1a * csa - x2a * sna) * qs;
                        float y1b = (x1b * csb - x2b * snb) * qs;
                        float y2a = (x2a * csa + x1a * sna) * qs;
                        float y2b = (x2b * csb + x1b * snb) * qs;
                        *(uint32_t*)(dst + rowbase + d)      = pack_h2(y1a, y1b);
                        *(uint32_t*)(dst + rowbase + d + 32) = pack_h2(y2a, y2b);
                    }
                }
            }
        }
    }
}

// ---------------------------------------------------------------------------
// Flash attention: scores = Q·K (single term), PV = P·V (fp16 P via HEX2).
// 3-stage KV ring, one barrier per tile.
// Grid (32 qtiles, 64 bh), 128 threads (4 warps x 16 q-rows).
// smem: Q 0 (9216); KV stages at 9216 (K +0, V +9216), stride 18432 x3.
// ---------------------------------------------------------------------------
#define SR 144
static constexpr uint32_t AQ = 0, AKV = 9216, KVSZ = 18432;
static constexpr uint32_t ATTN_SMEM = AKV + 3 * KVSZ;   // 64512

__global__ __launch_bounds__(128, 3) void attn_mma_kernel()
{
    extern __shared__ char smch[];
    uint32_t sb = smem_to_u32(smch);
    int tid = threadIdx.x;
    int wid = tid >> 5;
    int lane = tid & 31;
    int g = lane >> 2;
    int t2 = (lane & 3) * 2;
    int bh = blockIdx.y;
    int qt = blockIdx.x;

    auto kv_fill = [&](int stage, int kt) {
        uint32_t kb = sb + AKV + (uint32_t)stage * KVSZ;
#pragma unroll
        for (int i = 0; i < 4; i++) {
            int c = i * 128 + tid;
            int row = c >> 3;
            int c8 = c & 7;
            uint32_t doff = (uint32_t)row * SR + c8 * 16;
            CP_ASYNC16(kb + doff, g_K + ((size_t)bh * SEQ + kt * 64 + row) * 64 + c8 * 8);
            CP_ASYNC16(kb + 9216 + doff,
                       g_Vt + ((size_t)bh * 64 + row) * SEQ + kt * 64 + c8 * 8);
        }
    };

    // Q fill (single fp16): 512 16B chunks / 128 threads = 4 each
#pragma unroll
    for (int i = 0; i < 4; i++) {
        int c = i * 128 + tid;
        int row = c >> 3;
        int c8 = c & 7;
        uint32_t doff = (uint32_t)row * SR + c8 * 16;
        CP_ASYNC16(sb + AQ + doff,
                   g_Q + ((size_t)bh * SEQ + qt * 64 + row) * 64 + c8 * 8);
    }
    CP_COMMIT();
    kv_fill(0, 0); CP_COMMIT();
    kv_fill(1, 1); CP_COMMIT();
    CP_WAIT2();
    __syncthreads();

    uint32_t qf[4][4];
    {
        int rb = wid * 16;
#pragma unroll
        for (int ks = 0; ks < 4; ks++) {
            uint32_t addr = sb + AQ + (uint32_t)(rb + (lane & 15)) * SR
                          + (uint32_t)(ks * 16 + (lane >> 4) * 8) * 2;
            ldsm_x4(qf[ks], addr);
        }
    }

    float o[8][4];
#pragma unroll
    for (int nt = 0; nt < 8; nt++)
#pragma unroll
        for (int r = 0; r < 4; r++) o[nt][r] = 0.f;
    float mrow0 = -1e30f, mrow1 = -1e30f, lrow0 = 0.f, lrow1 = 0.f;

#pragma unroll 1
    for (int kt = 0; kt < 32; kt++) {
        if (kt < 31) CP_WAIT1(); else CP_WAIT0();
        __syncthreads();
        if (kt < 30) {
            kv_fill((kt + 2) % 3, kt + 2);
            CP_COMMIT();
        }

        uint32_t kb = sb + AKV + (uint32_t)(kt % 3) * KVSZ;

        // scores: Q x K (single term)
        float sacc[8][4];
#pragma unroll
        for (int nt = 0; nt < 8; nt++)
#pragma unroll
            for (int r = 0; r < 4; r++) sacc[nt][r] = 0.f;
#pragma unroll
        for (int kh = 0; kh < 2; kh++) {
#pragma unroll
            for (int nt = 0; nt < 8; nt++) {
                uint32_t boff = (uint32_t)(nt * 8 + (lane & 7)) * SR
                              + (uint32_t)(kh * 32 + ((lane >> 3) & 3) * 8) * 2;
                uint32_t bf[4];
                ldsm_x4(bf, kb + boff);
#pragma unroll
                for (int kss = 0; kss < 2; kss++) {
                    int ks = kh * 2 + kss;
                    mma_f16(sacc[nt], qf[ks], bf[kss * 2], bf[kss * 2 + 1]);
                }
            }
        }

        // online softmax in log2 domain (rows g, g+8)
        float mx0 = sacc[0][0], mx1 = sacc[0][2];
#pragma unroll
        for (int nt = 0; nt < 8; nt++) {
            mx0 = fmaxf(mx0, fmaxf(sacc[nt][0], sacc[nt][1]));
            mx1 = fmaxf(mx1, fmaxf(sacc[nt][2], sacc[nt][3]));
        }
        mx0 = fmaxf(mx0, __shfl_xor_sync(0xffffffffu, mx0, 1));
        mx0 = fmaxf(mx0, __shfl_xor_sync(0xffffffffu, mx0, 2));
        mx1 = fmaxf(mx1, __shfl_xor_sync(0xffffffffu, mx1, 1));
        mx1 = fmaxf(mx1, __shfl_xor_sync(0xffffffffu, mx1, 2));
        float mn0 = fmaxf(mrow0, mx0);
        float mn1 = fmaxf(mrow1, mx1);
        float cr0 = exp2f(mrow0 - mn0);
        float cr1 = exp2f(mrow1 - mn1);
        mrow0 = mn0; mrow1 = mn1;

        uint32_t ph[8][2];
        float ps0 = 0.f, ps1 = 0.f;
#pragma unroll
        for (int nt = 0; nt < 8; nt++) {
            ph[nt][0] = hexp2_x2(pack_h2(sacc[nt][0] - mn0, sacc[nt][1] - mn0));
            ph[nt][1] = hexp2_x2(pack_h2(sacc[nt][2] - mn1, sacc[nt][3] - mn1));
            float2 f0 = __half22float2(*(__half2*)&ph[nt][0]);
            float2 f1 = __half22float2(*(__half2*)&ph[nt][1]);
            ps0 += f0.x + f0.y;
            ps1 += f1.x + f1.y;
        }
        ps0 += __shfl_xor_sync(0xffffffffu, ps0, 1);
        ps0 += __shfl_xor_sync(0xffffffffu, ps0, 2);
        ps1 += __shfl_xor_sync(0xffffffffu, ps1, 1);
        ps1 += __shfl_xor_sync(0xffffffffu, ps1, 2);
        lrow0 = lrow0 * cr0 + ps0;
        lrow1 = lrow1 * cr1 + ps1;
        // skip the 32-FMUL rescale when no new running max appeared
        if (cr0 < 1.f || cr1 < 1.f) {
#pragma unroll
            for (int nt = 0; nt < 8; nt++) {
                o[nt][0] *= cr0; o[nt][1] *= cr0;
                o[nt][2] *= cr1; o[nt][3] *= cr1;
            }
        }

        // O += P x V (single term)
#pragma unroll
        for (int kh = 0; kh < 2; kh++) {
#pragma unroll
            for (int nt = 0; nt < 8; nt++) {
                uint32_t boff = (uint32_t)(nt * 8 + (lane & 7)) * SR
                              + (uint32_t)(kh * 32 + ((lane >> 3) & 3) * 8) * 2;
                uint32_t vf[4];
                ldsm_x4(vf, kb + 9216 + boff);
#pragma unroll
                for (int kss = 0; kss < 2; kss++) {
                    int ks = kh * 2 + kss;
                    uint32_t aPh[4] = {ph[2 * ks][0], ph[2 * ks][1],
                                       ph[2 * ks + 1][0], ph[2 * ks + 1][1]};
                    mma_f16(o[nt], aPh, vf[kss * 2], vf[kss * 2 + 1]);
                }
            }
        }
    }

    float inv0 = 1.f / lrow0;
    float inv1 = 1.f / lrow1;
    int b = bh >> 4, h = bh & 15;
    int s0 = qt * 64 + wid * 16 + g;
    int s1 = s0 + 8;
    size_t r0 = ((size_t)b * SEQ + s0) * DMODEL + h * 64;
    size_t r1 = ((size_t)b * SEQ + s1) * DMODEL + h * 64;
#pragma unroll
    for (int nt = 0; nt < 8; nt++) {
        int d0 = nt * 8 + t2;
        *(uint32_t*)(g_attn + r0 + d0) = pack_h2(o[nt][0] * inv0, o[nt][1] * inv0);
        *(uint32_t*)(g_attn + r1 + d0) = pack_h2(o[nt][2] * inv1, o[nt][3] * inv1);
    }
}

// ---------------------------------------------------------------------------
extern "C" void kernel_launch(void* const* d_in, const int* in_sizes, int n_in,
                              void* d_out, int out_size)
{
    const float* query = (const float*)d_in[0];
    const float* W_qkv = (const float*)d_in[1];
    const float* b_qkv = (const float*)d_in[2];
    const float* W_out = (const float*)d_in[3];
    const float* b_out = (const float*)d_in[4];
    float* out = (float*)d_out;

    cudaFuncSetAttribute(mma_gemm_kernel<0>, cudaFuncAttributeMaxDynamicSharedMemorySize, GEMM_SMEM);
    cudaFuncSetAttribute(mma_gemm_kernel<1>, cudaFuncAttributeMaxDynamicSharedMemorySize, GEMM_SMEM);
    cudaFuncSetAttribute(attn_mma_kernel, cudaFuncAttributeMaxDynamicSharedMemorySize, ATTN_SMEM);

    prep_w_kernel<<<(PREPW_THREADS + 255) / 256, 256>>>(W_qkv, W_out);
    prep_x_kernel<<<(X_THREADS + ROPE_ENTRIES + 255) / 256, 256>>>(query);
    {
        dim3 grid(NROWS / 128, QKV_N / 128);   // 64 x 24
        mma_gemm_kernel<0><<<grid, 256, GEMM_SMEM>>>(b_qkv, nullptr);
    }
    // attention (launch #4 -> ncu capture slot)
    {
        dim3 grid(SEQ / 64, BATCH * NHEADS);   // 32 x 64
        attn_mma_kernel<<<grid, 128, ATTN_SMEM>>>();
    }
    {
        dim3 grid(NROWS / 128, DMODEL / 128);  // 64 x 8
        mma_gemm_kernel<1><<<grid, 256, GEMM_SMEM>>>(b_out, out);
    }
}

// round 13
// speedup vs baseline: 5.9433x; 1.0097x over previous
#include <cuda_runtime.h>
#include <cuda_fp16.h>
#include <math.h>
#include <stdint.h>

#define BATCH 4
#define SEQ 2048
#define DMODEL 1024
#define NHEADS 16
#define HDIM 64
#define NROWS (BATCH * SEQ)          // 8192
#define QKV_N (3 * DMODEL)           // 3072
#define LOG2E 1.4426950408889634f

// ---------------------------------------------------------------------------
// PTX helpers
// ---------------------------------------------------------------------------
__device__ __forceinline__ uint32_t smem_to_u32(const void* p) {
    uint32_t a;
    asm("{ .reg .u64 t; cvta.to.shared.u64 t, %1; cvt.u32.u64 %0, t; }" : "=r"(a) : "l"(p));
    return a;
}

__device__ __forceinline__ void mma_f16(float* d, const uint32_t* a,
                                        uint32_t b0, uint32_t b1) {
    asm volatile(
        "mma.sync.aligned.m16n8k16.row.col.f32.f16.f16.f32 "
        "{%0,%1,%2,%3}, {%4,%5,%6,%7}, {%8,%9}, {%0,%1,%2,%3};"
        : "+f"(d[0]), "+f"(d[1]), "+f"(d[2]), "+f"(d[3])
        : "r"(a[0]), "r"(a[1]), "r"(a[2]), "r"(a[3]), "r"(b0), "r"(b1));
}

__device__ __forceinline__ void ldsm_x4(uint32_t* r, uint32_t addr) {
    asm volatile("ldmatrix.sync.aligned.m8n8.x4.shared.b16 {%0,%1,%2,%3}, [%4];"
                 : "=r"(r[0]), "=r"(r[1]), "=r"(r[2]), "=r"(r[3]) : "r"(addr));
}

#define CP_ASYNC16(dst, src) \
    asm volatile("cp.async.cg.shared.global [%0], [%1], 16;" :: "r"(dst), "l"(src))
#define CP_COMMIT() asm volatile("cp.async.commit_group;" ::: "memory")
#define CP_WAIT2()  asm volatile("cp.async.wait_group 2;" ::: "memory")
#define CP_WAIT1()  asm volatile("cp.async.wait_group 1;" ::: "memory")
#define CP_WAIT0()  asm volatile("cp.async.wait_group 0;" ::: "memory")

__device__ __forceinline__ uint32_t pack_h2(float lo, float hi) {
    __half2 h = __floats2half2_rn(lo, hi);
    return *(uint32_t*)&h;
}
__device__ __forceinline__ uint32_t hexp2_x2(uint32_t x) {
    uint32_t r;
    asm("ex2.approx.f16x2 %0, %1;" : "=r"(r) : "r"(x));
    return r;
}
__device__ __forceinline__ uint32_t hmax2(uint32_t a, uint32_t b) {
    uint32_t r;
    asm("max.f16x2 %0, %1, %2;" : "=r"(r) : "r"(a), "r"(b));
    return r;
}
__device__ __forceinline__ void split_f16(float v, float& hf, float& lf) {
    __half h = __float2half_rn(v);
    hf = __half2float(h);
    lf = v - hf;
}

// ---------------------------------------------------------------------------
// Scratch
// ---------------------------------------------------------------------------
__device__ float g_rope_cos[SEQ * 32];
__device__ float g_rope_sin[SEQ * 32];

__device__ __half g_X[NROWS * DMODEL];
__device__ __half g_Wqkv_h[QKV_N * DMODEL];
__device__ __half g_Wqkv_l[QKV_N * DMODEL];
__device__ __half g_Wout_h[DMODEL * DMODEL];
__device__ __half g_Wout_l[DMODEL * DMODEL];

__device__ __half g_Q[64 * SEQ * HDIM];
__device__ __half g_K[64 * SEQ * HDIM];
__device__ __half g_Vt[64 * HDIM * SEQ];

__device__ __half g_attn[NROWS * DMODEL];

// ---------------------------------------------------------------------------
// prep_w
// ---------------------------------------------------------------------------
static constexpr int WQKV_ELEMS = QKV_N * DMODEL;
static constexpr int WOUT_ELEMS = DMODEL * DMODEL;
static constexpr int PREPW_THREADS = (WQKV_ELEMS + WOUT_ELEMS) / 4;

__global__ void prep_w_kernel(const float* __restrict__ W_qkv,
                              const float* __restrict__ W_out) {
    int gid = blockIdx.x * blockDim.x + threadIdx.x;
    if (gid >= PREPW_THREADS) return;
    int i = gid * 4;
    const float* src;
    __half *hp, *lp;
    if (i < WQKV_ELEMS) {
        src = W_qkv + i; hp = g_Wqkv_h + i; lp = g_Wqkv_l + i;
    } else {
        int j = i - WQKV_ELEMS;
        src = W_out + j; hp = g_Wout_h + j; lp = g_Wout_l + j;
    }
    float4 v = *(const float4*)src;
    float vv[4] = {v.x, v.y, v.z, v.w};
    float hh[4], ll[4];
#pragma unroll
    for (int j = 0; j < 4; j++) split_f16(vv[j], hh[j], ll[j]);
    uint2 wh, wl;
    wh.x = pack_h2(hh[0], hh[1]); wh.y = pack_h2(hh[2], hh[3]);
    wl.x = pack_h2(ll[0], ll[1]); wl.y = pack_h2(ll[2], ll[3]);
    *(uint2*)hp = wh;
    *(uint2*)lp = wl;
}

// ---------------------------------------------------------------------------
// prep_x
// ---------------------------------------------------------------------------
static constexpr int X_THREADS = NROWS * DMODEL / 4;
static constexpr int ROPE_ENTRIES = SEQ * 32;

__global__ void prep_x_kernel(const float* __restrict__ src) {
    int gid = blockIdx.x * blockDim.x + threadIdx.x;
    if (gid < X_THREADS) {
        int i = gid * 4;
        float4 v = *(const float4*)(src + i);
        uint2 w;
        w.x = pack_h2(v.x, v.y);
        w.y = pack_h2(v.z, v.w);
        *(uint2*)(g_X + i) = w;
    } else {
        int idx = gid - X_THREADS;
        if (idx >= ROPE_ENTRIES) return;
        int s = idx >> 5;
        int i = idx & 31;
        float inv_freq = powf(10000.0f, -(float)i / 32.0f);
        float ang = (float)s * inv_freq;
        float sn, cs;
        sincosf(ang, &sn, &cs);
        g_rope_cos[idx] = cs;
        g_rope_sin[idx] = sn;
    }
}

// ---------------------------------------------------------------------------
// GEMM (unchanged from R12)
// ---------------------------------------------------------------------------
#define SAB 80
static constexpr uint32_t GOFF_A = 0, GOFF_BH = 10240, GOFF_BL = 20480;
static constexpr uint32_t GBUFSZ = 30720;
static constexpr uint32_t GOFF_BIAS = 92160;
static constexpr uint32_t GEMM_SMEM = 92672;

template <int MODE>
__global__ __launch_bounds__(256, 2) void mma_gemm_kernel(
    const float* __restrict__ bias, float* __restrict__ outp)
{
    extern __shared__ char smch[];
    uint32_t sb = smem_to_u32(smch);
    int tid = threadIdx.x;
    int wid = tid >> 5;
    int lane = tid & 31;
    int g = lane >> 2;
    int t2 = (lane & 3) * 2;
    int warp_m = wid >> 1;
    int warp_n = wid & 1;
    int m0 = blockIdx.x * 128;
    int n0 = blockIdx.y * 128;

    const __half* A  = (MODE == 0) ? g_X : g_attn;
    const __half* Bh = (MODE == 0) ? g_Wqkv_h : g_Wout_h;
    const __half* Bl = (MODE == 0) ? g_Wqkv_l : g_Wout_l;

    float* sbias = (float*)(smch + GOFF_BIAS);
    if (tid < 128) sbias[tid] = bias[n0 + tid];

    float acc[2][8][4];
#pragma unroll
    for (int mt = 0; mt < 2; mt++)
#pragma unroll
        for (int nt = 0; nt < 8; nt++)
#pragma unroll
            for (int r = 0; r < 4; r++) acc[mt][nt][r] = 0.f;

    auto fill = [&](int stage, int k0) {
        uint32_t bofs = sb + (uint32_t)stage * GBUFSZ;
#pragma unroll
        for (int i = 0; i < 2; i++) {
            int c = i * 256 + tid;
            int row = c >> 2;
            int c8 = c & 3;
            uint32_t doff = (uint32_t)row * SAB + c8 * 16;
            CP_ASYNC16(bofs + GOFF_A  + doff, A  + (size_t)(m0 + row) * DMODEL + k0 + c8 * 8);
            CP_ASYNC16(bofs + GOFF_BH + doff, Bh + (size_t)(n0 + row) * DMODEL + k0 + c8 * 8);
            CP_ASYNC16(bofs + GOFF_BL + doff, Bl + (size_t)(n0 + row) * DMODEL + k0 + c8 * 8);
        }
    };

    fill(0, 0);  CP_COMMIT();
    fill(1, 32); CP_COMMIT();

#pragma unroll 1
    for (int ck = 0; ck < 32; ck++) {
        if (ck < 31) CP_WAIT1(); else CP_WAIT0();
        __syncthreads();
        if (ck < 30) {
            fill((ck + 2) % 3, (ck + 2) * 32);
            CP_COMMIT();
        }

        uint32_t bb = sb + (uint32_t)(ck % 3) * GBUFSZ;
        uint32_t af[2][2][4];
#pragma unroll
        for (int mt = 0; mt < 2; mt++)
#pragma unroll
            for (int kss = 0; kss < 2; kss++) {
                uint32_t addr = bb + GOFF_A
                    + (uint32_t)(warp_m * 32 + mt * 16 + (lane & 15)) * SAB
                    + (uint32_t)(kss * 16 + (lane >> 4) * 8) * 2;
                ldsm_x4(af[mt][kss], addr);
            }
#pragma unroll
        for (int nt = 0; nt < 8; nt++) {
            uint32_t boff = (uint32_t)(warp_n * 64 + nt * 8 + (lane & 7)) * SAB
                          + (uint32_t)(((lane >> 3) & 3) * 8) * 2;
            uint32_t bfh[4], bfl[4];
            ldsm_x4(bfh, bb + GOFF_BH + boff);
            ldsm_x4(bfl, bb + GOFF_BL + boff);
#pragma unroll
            for (int kss = 0; kss < 2; kss++)
#pragma unroll
                for (int mt = 0; mt < 2; mt++) {
                    mma_f16(acc[mt][nt], af[mt][kss], bfh[kss * 2], bfh[kss * 2 + 1]);
                    mma_f16(acc[mt][nt], af[mt][kss], bfl[kss * 2], bfl[kss * 2 + 1]);
                }
        }
    }

    int nwb = n0 + warp_n * 64;
    if (MODE == 1) {
#pragma unroll
        for (int mt = 0; mt < 2; mt++) {
            int r0 = m0 + warp_m * 32 + mt * 16 + g;
#pragma unroll
            for (int nt = 0; nt < 8; nt++) {
                int ncol = nwb + nt * 8 + t2;
                float b0 = sbias[warp_n * 64 + nt * 8 + t2];
                float b1 = sbias[warp_n * 64 + nt * 8 + t2 + 1];
                float2 w0 = make_float2(acc[mt][nt][0] + b0, acc[mt][nt][1] + b1);
                float2 w1 = make_float2(acc[mt][nt][2] + b0, acc[mt][nt][3] + b1);
                *(float2*)(outp + (size_t)r0 * DMODEL + ncol) = w0;
                *(float2*)(outp + (size_t)(r0 + 8) * DMODEL + ncol) = w1;
            }
        }
    } else {
        int which = nwb >> 10;
        int h = (nwb & 1023) >> 6;
#pragma unroll
        for (int mt = 0; mt < 2; mt++) {
            int m_g = m0 + warp_m * 32 + mt * 16 + g;
#pragma unroll
            for (int rr = 0; rr < 2; rr++) {
                int mrow = m_g + rr * 8;
                int b = mrow >> 11;
                int s = mrow & 2047;
                int bh = b * NHEADS + h;
                if (which == 2) {
#pragma unroll
                    for (int nt = 0; nt < 8; nt++) {
#pragma unroll
                        for (int dd = 0; dd < 2; dd++) {
                            int d = nt * 8 + t2 + dd;
                            float v = acc[mt][nt][rr * 2 + dd] + sbias[warp_n * 64 + d];
                            g_Vt[((size_t)bh * 64 + d) * SEQ + s] = __float2half_rn(v);
                        }
                    }
                } else {
                    size_t rowbase = ((size_t)bh * SEQ + s) * 64;
                    float qs = (which == 0) ? (0.125f * LOG2E) : 1.0f;
                    __half* dst = (which == 0) ? g_Q : g_K;
#pragma unroll
                    for (int nt = 0; nt < 4; nt++) {
                        int d = nt * 8 + t2;
                        float x1a = acc[mt][nt][rr * 2]         + sbias[warp_n * 64 + d];
                        float x1b = acc[mt][nt][rr * 2 + 1]     + sbias[warp_n * 64 + d + 1];
                        float x2a = acc[mt][nt + 4][rr * 2]     + sbias[warp_n * 64 + d + 32];
                        float x2b = acc[mt][nt + 4][rr * 2 + 1] + sbias[warp_n * 64 + d + 33];
                        float csa = g_rope_cos[s * 32 + d],   sna = g_rope_sin[s * 32 + d];
                        float csb = g_rope_cos[s * 32 + d+1], snb = g_rope_sin[s * 32 + d+1];
                        float y1a = (x1a * csa - x2a * sna) * qs;
                        float y1b = (x1b * csb - x2b * snb) * qs;
                        float y2a = (x2a * csa + x1a * sna) * qs;
                        float y2b = (x2b * csb + x1b * snb) * qs;
                        *(uint32_t*)(dst + rowbase + d)      = pack_h2(y1a, y1b);
                        *(uint32_t*)(dst + rowbase + d + 32) = pack_h2(y2a, y2b);
                    }
                }
            }
        }
    }
}

// ---------------------------------------------------------------------------
// Flash attention: Q·K single, P·V single; shortened softmax critical path:
// balanced max tree + packed-half2 max butterfly (2 shfl/tile) + deferred
// per-thread l accumulation (no l shuffles in loop).
// ---------------------------------------------------------------------------
#define SR 144
static constexpr uint32_t AQ = 0, AKV = 9216, KVSZ = 18432;
static constexpr uint32_t ATTN_SMEM = AKV + 3 * KVSZ;   // 64512

__global__ __launch_bounds__(128, 3) void attn_mma_kernel()
{
    extern __shared__ char smch[];
    uint32_t sb = smem_to_u32(smch);
    int tid = threadIdx.x;
    int wid = tid >> 5;
    int lane = tid & 31;
    int g = lane >> 2;
    int t2 = (lane & 3) * 2;
    int bh = blockIdx.y;
    int qt = blockIdx.x;

    auto kv_fill = [&](int stage, int kt) {
        uint32_t kb = sb + AKV + (uint32_t)stage * KVSZ;
#pragma unroll
        for (int i = 0; i < 4; i++) {
            int c = i * 128 + tid;
            int row = c >> 3;
            int c8 = c & 7;
            uint32_t doff = (uint32_t)row * SR + c8 * 16;
            CP_ASYNC16(kb + doff, g_K + ((size_t)bh * SEQ + kt * 64 + row) * 64 + c8 * 8);
            CP_ASYNC16(kb + 9216 + doff,
                       g_Vt + ((size_t)bh * 64 + row) * SEQ + kt * 64 + c8 * 8);
        }
    };

#pragma unroll
    for (int i = 0; i < 4; i++) {
        int c = i * 128 + tid;
        int row = c >> 3;
        int c8 = c & 7;
        uint32_t doff = (uint32_t)row * SR + c8 * 16;
        CP_ASYNC16(sb + AQ + doff,
                   g_Q + ((size_t)bh * SEQ + qt * 64 + row) * 64 + c8 * 8);
    }
    CP_COMMIT();
    kv_fill(0, 0); CP_COMMIT();
    kv_fill(1, 1); CP_COMMIT();
    CP_WAIT2();
    __syncthreads();

    uint32_t qf[4][4];
    {
        int rb = wid * 16;
#pragma unroll
        for (int ks = 0; ks < 4; ks++) {
            uint32_t addr = sb + AQ + (uint32_t)(rb + (lane & 15)) * SR
                          + (uint32_t)(ks * 16 + (lane >> 4) * 8) * 2;
            ldsm_x4(qf[ks], addr);
        }
    }

    float o[8][4];
#pragma unroll
    for (int nt = 0; nt < 8; nt++)
#pragma unroll
        for (int r = 0; r < 4; r++) o[nt][r] = 0.f;
    float mrow0 = -1e30f, mrow1 = -1e30f;
    float lrow0 = 0.f, lrow1 = 0.f;       // per-thread partial (quad-deferred)

#pragma unroll 1
    for (int kt = 0; kt < 32; kt++) {
        if (kt < 31) CP_WAIT1(); else CP_WAIT0();
        __syncthreads();
        if (kt < 30) {
            kv_fill((kt + 2) % 3, kt + 2);
            CP_COMMIT();
        }

        uint32_t kb = sb + AKV + (uint32_t)(kt % 3) * KVSZ;

        // scores: Q x K
        float sacc[8][4];
#pragma unroll
        for (int nt = 0; nt < 8; nt++)
#pragma unroll
            for (int r = 0; r < 4; r++) sacc[nt][r] = 0.f;
#pragma unroll
        for (int kh = 0; kh < 2; kh++) {
#pragma unroll
            for (int nt = 0; nt < 8; nt++) {
                uint32_t boff = (uint32_t)(nt * 8 + (lane & 7)) * SR
                              + (uint32_t)(kh * 32 + ((lane >> 3) & 3) * 8) * 2;
                uint32_t bf[4];
                ldsm_x4(bf, kb + boff);
#pragma unroll
                for (int kss = 0; kss < 2; kss++) {
                    int ks = kh * 2 + kss;
                    mma_f16(sacc[nt], qf[ks], bf[kss * 2], bf[kss * 2 + 1]);
                }
            }
        }

        // max: balanced tree (depth ~4) then packed-half2 quad butterfly
        float a0[8], a1[8];
#pragma unroll
        for (int nt = 0; nt < 8; nt++) {
            a0[nt] = fmaxf(sacc[nt][0], sacc[nt][1]);
            a1[nt] = fmaxf(sacc[nt][2], sacc[nt][3]);
        }
#pragma unroll
        for (int st = 4; st >= 1; st >>= 1)
#pragma unroll
            for (int j = 0; j < st; j++) {
                a0[j] = fmaxf(a0[j], a0[j + st]);
                a1[j] = fmaxf(a1[j], a1[j + st]);
            }
        uint32_t mpk = pack_h2(a0[0], a1[0]);
        mpk = hmax2(mpk, __shfl_xor_sync(0xffffffffu, mpk, 1));
        mpk = hmax2(mpk, __shfl_xor_sync(0xffffffffu, mpk, 2));
        float2 mxf = __half22float2(*(__half2*)&mpk);
        float mn0 = fmaxf(mrow0, mxf.x);
        float mn1 = fmaxf(mrow1, mxf.y);
        float cr0 = exp2f(mrow0 - mn0);
        float cr1 = exp2f(mrow1 - mn1);
        mrow0 = mn0; mrow1 = mn1;

        // P = exp2(s - m) packed fp16; per-thread partial row sums (no shfl)
        uint32_t ph[8][2];
        float ps0 = 0.f, ps1 = 0.f;
#pragma unroll
        for (int nt = 0; nt < 8; nt++) {
            ph[nt][0] = hexp2_x2(pack_h2(sacc[nt][0] - mn0, sacc[nt][1] - mn0));
            ph[nt][1] = hexp2_x2(pack_h2(sacc[nt][2] - mn1, sacc[nt][3] - mn1));
            float2 f0 = __half22float2(*(__half2*)&ph[nt][0]);
            float2 f1 = __half22float2(*(__half2*)&ph[nt][1]);
            ps0 += f0.x + f0.y;
            ps1 += f1.x + f1.y;
        }
        lrow0 = lrow0 * cr0 + ps0;
        lrow1 = lrow1 * cr1 + ps1;
        if (cr0 < 1.f || cr1 < 1.f) {
#pragma unroll
            for (int nt = 0; nt < 8; nt++) {
                o[nt][0] *= cr0; o[nt][1] *= cr0;
                o[nt][2] *= cr1; o[nt][3] *= cr1;
            }
        }

        // O += P x V
#pragma unroll
        for (int kh = 0; kh < 2; kh++) {
#pragma unroll
            for (int nt = 0; nt < 8; nt++) {
                uint32_t boff = (uint32_t)(nt * 8 + (lane & 7)) * SR
                              + (uint32_t)(kh * 32 + ((lane >> 3) & 3) * 8) * 2;
                uint32_t vf[4];
                ldsm_x4(vf, kb + 9216 + boff);
#pragma unroll
                for (int kss = 0; kss < 2; kss++) {
                    int ks = kh * 2 + kss;
                    uint32_t aPh[4] = {ph[2 * ks][0], ph[2 * ks][1],
                                       ph[2 * ks + 1][0], ph[2 * ks + 1][1]};
                    mma_f16(o[nt], aPh, vf[kss * 2], vf[kss * 2 + 1]);
                }
            }
        }
    }

    // reduce deferred l across the quad, then normalize+store
    lrow0 += __shfl_xor_sync(0xffffffffu, lrow0, 1);
    lrow0 += __shfl_xor_sync(0xffffffffu, lrow0, 2);
    lrow1 += __shfl_xor_sync(0xffffffffu, lrow1, 1);
    lrow1 += __shfl_xor_sync(0xffffffffu, lrow1, 2);
    float inv0 = 1.f / lrow0;
    float inv1 = 1.f / lrow1;
    int b = bh >> 4, h = bh & 15;
    int s0 = qt * 64 + wid * 16 + g;
    int s1 = s0 + 8;
    size_t r0 = ((size_t)b * SEQ + s0) * DMODEL + h * 64;
    size_t r1 = ((size_t)b * SEQ + s1) * DMODEL + h * 64;
#pragma unroll
    for (int nt = 0; nt < 8; nt++) {
        int d0 = nt * 8 + t2;
        *(uint32_t*)(g_attn + r0 + d0) = pack_h2(o[nt][0] * inv0, o[nt][1] * inv0);
        *(uint32_t*)(g_attn + r1 + d0) = pack_h2(o[nt][2] * inv1, o[nt][3] * inv1);
    }
}

// ---------------------------------------------------------------------------
extern "C" void kernel_launch(void* const* d_in, const int* in_sizes, int n_in,
                              void* d_out, int out_size)
{
    const float* query = (const float*)d_in[0];
    const float* W_qkv = (const float*)d_in[1];
    const float* b_qkv = (const float*)d_in[2];
    const float* W_out = (const float*)d_in[3];
    const float* b_out = (const float*)d_in[4];
    float* out = (float*)d_out;

    cudaFuncSetAttribute(mma_gemm_kernel<0>, cudaFuncAttributeMaxDynamicSharedMemorySize, GEMM_SMEM);
    cudaFuncSetAttribute(mma_gemm_kernel<1>, cudaFuncAttributeMaxDynamicSharedMemorySize, GEMM_SMEM);
    cudaFuncSetAttribute(attn_mma_kernel, cudaFuncAttributeMaxDynamicSharedMemorySize, ATTN_SMEM);

    prep_w_kernel<<<(PREPW_THREADS + 255) / 256, 256>>>(W_qkv, W_out);
    prep_x_kernel<<<(X_THREADS + ROPE_ENTRIES + 255) / 256, 256>>>(query);
    {
        dim3 grid(NROWS / 128, QKV_N / 128);   // 64 x 24
        mma_gemm_kernel<0><<<grid, 256, GEMM_SMEM>>>(b_qkv, nullptr);
    }
    // attention (launch #4 -> ncu capture slot)
    {
        dim3 grid(SEQ / 64, BATCH * NHEADS);   // 32 x 64
        attn_mma_kernel<<<grid, 128, ATTN_SMEM>>>();
    }
    {
        dim3 grid(NROWS / 128, DMODEL / 128);  // 64 x 8
        mma_gemm_kernel<1><<<grid, 256, GEMM_SMEM>>>(b_out, out);
    }
}

// round 15
// speedup vs baseline: 8.2131x; 1.3819x over previous
#include <cuda_runtime.h>
#include <cuda_fp16.h>
#include <math.h>
#include <stdint.h>

#define BATCH 4
#define SEQ 2048
#define DMODEL 1024
#define NHEADS 16
#define HDIM 64
#define NROWS (BATCH * SEQ)          // 8192
#define QKV_N (3 * DMODEL)           // 3072
#define LOG2E 1.4426950408889634f

// ---------------------------------------------------------------------------
// PTX helpers
// ---------------------------------------------------------------------------
__device__ __forceinline__ uint32_t smem_to_u32(const void* p) {
    uint32_t a;
    asm("{ .reg .u64 t; cvta.to.shared.u64 t, %1; cvt.u32.u64 %0, t; }" : "=r"(a) : "l"(p));
    return a;
}

__device__ __forceinline__ void mma_f16(float* d, const uint32_t* a,
                                        uint32_t b0, uint32_t b1) {
    asm volatile(
        "mma.sync.aligned.m16n8k16.row.col.f32.f16.f16.f32 "
        "{%0,%1,%2,%3}, {%4,%5,%6,%7}, {%8,%9}, {%0,%1,%2,%3};"
        : "+f"(d[0]), "+f"(d[1]), "+f"(d[2]), "+f"(d[3])
        : "r"(a[0]), "r"(a[1]), "r"(a[2]), "r"(a[3]), "r"(b0), "r"(b1));
}

__device__ __forceinline__ void ldsm_x4(uint32_t* r, uint32_t addr) {
    asm volatile("ldmatrix.sync.aligned.m8n8.x4.shared.b16 {%0,%1,%2,%3}, [%4];"
                 : "=r"(r[0]), "=r"(r[1]), "=r"(r[2]), "=r"(r[3]) : "r"(addr));
}

#define CP_ASYNC16(dst, src) \
    asm volatile("cp.async.cg.shared.global [%0], [%1], 16;" :: "r"(dst), "l"(src))
#define CP_COMMIT() asm volatile("cp.async.commit_group;" ::: "memory")
#define CP_WAIT2()  asm volatile("cp.async.wait_group 2;" ::: "memory")
#define CP_WAIT1()  asm volatile("cp.async.wait_group 1;" ::: "memory")
#define CP_WAIT0()  asm volatile("cp.async.wait_group 0;" ::: "memory")

__device__ __forceinline__ uint32_t pack_h2(float lo, float hi) {
    __half2 h = __floats2half2_rn(lo, hi);
    return *(uint32_t*)&h;
}
__device__ __forceinline__ uint32_t hexp2_x2(uint32_t x) {
    uint32_t r;
    asm("ex2.approx.f16x2 %0, %1;" : "=r"(r) : "r"(x));
    return r;
}
__device__ __forceinline__ uint32_t hmax2(uint32_t a, uint32_t b) {
    uint32_t r;
    asm("max.f16x2 %0, %1, %2;" : "=r"(r) : "r"(a), "r"(b));
    return r;
}

// ---------------------------------------------------------------------------
// Scratch
// ---------------------------------------------------------------------------
__device__ float g_rope_cos[SEQ * 32];
__device__ float g_rope_sin[SEQ * 32];

__device__ __half g_X[NROWS * DMODEL];            // fp16(query)
__device__ __half g_Wqkv[QKV_N * DMODEL];         // fp16 single
__device__ __half g_Wout[DMODEL * DMODEL];        // fp16 single

__device__ __half g_Q[64 * SEQ * HDIM];
__device__ __half g_K[64 * SEQ * HDIM];
__device__ __half g_Vt[64 * HDIM * SEQ];

__device__ __half g_attn[NROWS * DMODEL];

// ---------------------------------------------------------------------------
// prep_w: fp32 -> fp16 convert of BOTH weight matrices (no split)
// ---------------------------------------------------------------------------
static constexpr int WQKV_ELEMS = QKV_N * DMODEL;
static constexpr int WOUT_ELEMS = DMODEL * DMODEL;
static constexpr int PREPW_THREADS = (WQKV_ELEMS + WOUT_ELEMS) / 4;

__global__ void prep_w_kernel(const float* __restrict__ W_qkv,
                              const float* __restrict__ W_out) {
    int gid = blockIdx.x * blockDim.x + threadIdx.x;
    if (gid >= PREPW_THREADS) return;
    int i = gid * 4;
    const float* src;
    __half* hp;
    if (i < WQKV_ELEMS) {
        src = W_qkv + i; hp = g_Wqkv + i;
    } else {
        int j = i - WQKV_ELEMS;
        src = W_out + j; hp = g_Wout + j;
    }
    float4 v = *(const float4*)src;
    uint2 w;
    w.x = pack_h2(v.x, v.y);
    w.y = pack_h2(v.z, v.w);
    *(uint2*)hp = w;
}

// ---------------------------------------------------------------------------
// prep_x
// ---------------------------------------------------------------------------
static constexpr int X_THREADS = NROWS * DMODEL / 4;
static constexpr int ROPE_ENTRIES = SEQ * 32;

__global__ void prep_x_kernel(const float* __restrict__ src) {
    int gid = blockIdx.x * blockDim.x + threadIdx.x;
    if (gid < X_THREADS) {
        int i = gid * 4;
        float4 v = *(const float4*)(src + i);
        uint2 w;
        w.x = pack_h2(v.x, v.y);
        w.y = pack_h2(v.z, v.w);
        *(uint2*)(g_X + i) = w;
    } else {
        int idx = gid - X_THREADS;
        if (idx >= ROPE_ENTRIES) return;
        int s = idx >> 5;
        int i = idx & 31;
        float inv_freq = powf(10000.0f, -(float)i / 32.0f);
        float ang = (float)s * inv_freq;
        float sn, cs;
        sincosf(ang, &sn, &cs);
        g_rope_cos[idx] = cs;
        g_rope_sin[idx] = sn;
    }
}

// ---------------------------------------------------------------------------
// GEMM: C[m,n] = sum_k A[m,k]*B[n,k] (+bias); single fp16 both operands.
// BM=128 BN=128 BK=32; 256 threads (8 warps 4x2); 3-stage cp.async ring.
// MODE 0: A=g_X, B=g_Wqkv; epilogue bias+RoPE -> Q, K, Vt
// MODE 1: A=g_attn, B=g_Wout; epilogue bias -> out fp32
// ---------------------------------------------------------------------------
#define SAB 80
static constexpr uint32_t GOFF_A = 0, GOFF_B = 10240;
static constexpr uint32_t GBUFSZ = 20480;
static constexpr uint32_t GOFF_BIAS = 61440;
static constexpr uint32_t GEMM_SMEM = 61952;

template <int MODE>
__global__ __launch_bounds__(256, 2) void mma_gemm_kernel(
    const float* __restrict__ bias, float* __restrict__ outp)
{
    extern __shared__ char smch[];
    uint32_t sb = smem_to_u32(smch);
    int tid = threadIdx.x;
    int wid = tid >> 5;
    int lane = tid & 31;
    int g = lane >> 2;
    int t2 = (lane & 3) * 2;
    int warp_m = wid >> 1;
    int warp_n = wid & 1;
    int m0 = blockIdx.x * 128;
    int n0 = blockIdx.y * 128;

    const __half* A = (MODE == 0) ? g_X : g_attn;
    const __half* B = (MODE == 0) ? g_Wqkv : g_Wout;

    float* sbias = (float*)(smch + GOFF_BIAS);
    if (tid < 128) sbias[tid] = bias[n0 + tid];

    float acc[2][8][4];
#pragma unroll
    for (int mt = 0; mt < 2; mt++)
#pragma unroll
        for (int nt = 0; nt < 8; nt++)
#pragma unroll
            for (int r = 0; r < 4; r++) acc[mt][nt][r] = 0.f;

    auto fill = [&](int stage, int k0) {
        uint32_t bofs = sb + (uint32_t)stage * GBUFSZ;
#pragma unroll
        for (int i = 0; i < 2; i++) {
            int c = i * 256 + tid;
            int row = c >> 2;
            int c8 = c & 3;
            uint32_t doff = (uint32_t)row * SAB + c8 * 16;
            CP_ASYNC16(bofs + GOFF_A + doff, A + (size_t)(m0 + row) * DMODEL + k0 + c8 * 8);
            CP_ASYNC16(bofs + GOFF_B + doff, B + (size_t)(n0 + row) * DMODEL + k0 + c8 * 8);
        }
    };

    fill(0, 0);  CP_COMMIT();
    fill(1, 32); CP_COMMIT();

#pragma unroll 1
    for (int ck = 0; ck < 32; ck++) {
        if (ck < 31) CP_WAIT1(); else CP_WAIT0();
        __syncthreads();
        if (ck < 30) {
            fill((ck + 2) % 3, (ck + 2) * 32);
            CP_COMMIT();
        }

        uint32_t bb = sb + (uint32_t)(ck % 3) * GBUFSZ;
        uint32_t af[2][2][4];
#pragma unroll
        for (int mt = 0; mt < 2; mt++)
#pragma unroll
            for (int kss = 0; kss < 2; kss++) {
                uint32_t addr = bb + GOFF_A
                    + (uint32_t)(warp_m * 32 + mt * 16 + (lane & 15)) * SAB
                    + (uint32_t)(kss * 16 + (lane >> 4) * 8) * 2;
                ldsm_x4(af[mt][kss], addr);
            }
#pragma unroll
        for (int nt = 0; nt < 8; nt++) {
            uint32_t boff = (uint32_t)(warp_n * 64 + nt * 8 + (lane & 7)) * SAB
                          + (uint32_t)(((lane >> 3) & 3) * 8) * 2;
            uint32_t bf[4];
            ldsm_x4(bf, bb + GOFF_B + boff);
#pragma unroll
            for (int kss = 0; kss < 2; kss++)
#pragma unroll
                for (int mt = 0; mt < 2; mt++)
                    mma_f16(acc[mt][nt], af[mt][kss], bf[kss * 2], bf[kss * 2 + 1]);
        }
    }

    // ----- epilogue -----
    int nwb = n0 + warp_n * 64;
    if (MODE == 1) {
#pragma unroll
        for (int mt = 0; mt < 2; mt++) {
            int r0 = m0 + warp_m * 32 + mt * 16 + g;
#pragma unroll
            for (int nt = 0; nt < 8; nt++) {
                int ncol = nwb + nt * 8 + t2;
                float b0 = sbias[warp_n * 64 + nt * 8 + t2];
                float b1 = sbias[warp_n * 64 + nt * 8 + t2 + 1];
                float2 w0 = make_float2(acc[mt][nt][0] + b0, acc[mt][nt][1] + b1);
                float2 w1 = make_float2(acc[mt][nt][2] + b0, acc[mt][nt][3] + b1);
                *(float2*)(outp + (size_t)r0 * DMODEL + ncol) = w0;
                *(float2*)(outp + (size_t)(r0 + 8) * DMODEL + ncol) = w1;
            }
        }
    } else {
        int which = nwb >> 10;                 // 0=q,1=k,2=v
        int h = (nwb & 1023) >> 6;
#pragma unroll
        for (int mt = 0; mt < 2; mt++) {
            int m_g = m0 + warp_m * 32 + mt * 16 + g;
#pragma unroll
            for (int rr = 0; rr < 2; rr++) {
                int mrow = m_g + rr * 8;
                int b = mrow >> 11;
                int s = mrow & 2047;
                int bh = b * NHEADS + h;
                if (which == 2) {
#pragma unroll
                    for (int nt = 0; nt < 8; nt++) {
#pragma unroll
                        for (int dd = 0; dd < 2; dd++) {
                            int d = nt * 8 + t2 + dd;
                            float v = acc[mt][nt][rr * 2 + dd] + sbias[warp_n * 64 + d];
                            g_Vt[((size_t)bh * 64 + d) * SEQ + s] = __float2half_rn(v);
                        }
                    }
                } else {
                    size_t rowbase = ((size_t)bh * SEQ + s) * 64;
                    float qs = (which == 0) ? (0.125f * LOG2E) : 1.0f;
                    __half* dst = (which == 0) ? g_Q : g_K;
#pragma unroll
                    for (int nt = 0; nt < 4; nt++) {
                        int d = nt * 8 + t2;
                        float x1a = acc[mt][nt][rr * 2]         + sbias[warp_n * 64 + d];
                        float x1b = acc[mt][nt][rr * 2 + 1]     + sbias[warp_n * 64 + d + 1];
                        float x2a = acc[mt][nt + 4][rr * 2]     + sbias[warp_n * 64 + d + 32];
                        float x2b = acc[mt][nt + 4][rr * 2 + 1] + sbias[warp_n * 64 + d + 33];
                        float csa = g_rope_cos[s * 32 + d],   sna = g_rope_sin[s * 32 + d];
                        float csb = g_rope_cos[s * 32 + d+1], snb = g_rope_sin[s * 32 + d+1];
                        float y1a = (x1a * csa - x2a * sna) * qs;
                        float y1b = (x1b * csb - x2b * snb) * qs;
                        float y2a = (x2a * csa + x1a * sna) * qs;
                        float y2b = (x2b * csb + x1b * snb) * qs;
                        *(uint32_t*)(dst + rowbase + d)      = pack_h2(y1a, y1b);
                        *(uint32_t*)(dst + rowbase + d + 32) = pack_h2(y2a, y2b);
                    }
                }
            }
        }
    }
}

// ---------------------------------------------------------------------------
// Flash attention (unchanged from R13)
// ---------------------------------------------------------------------------
#define SR 144
static constexpr uint32_t AQ = 0, AKV = 9216, KVSZ = 18432;
static constexpr uint32_t ATTN_SMEM = AKV + 3 * KVSZ;   // 64512

__global__ __launch_bounds__(128, 3) void attn_mma_kernel()
{
    extern __shared__ char smch[];
    uint32_t sb = smem_to_u32(smch);
    int tid = threadIdx.x;
    int wid = tid >> 5;
    int lane = tid & 31;
    int g = lane >> 2;
    int t2 = (lane & 3) * 2;
    int bh = blockIdx.y;
    int qt = blockIdx.x;

    auto kv_fill = [&](int stage, int kt) {
        uint32_t kb = sb + AKV + (uint32_t)stage * KVSZ;
#pragma unroll
        for (int i = 0; i < 4; i++) {
            int c = i * 128 + tid;
            int row = c >> 3;
            int c8 = c & 7;
            uint32_t doff = (uint32_t)row * SR + c8 * 16;
            CP_ASYNC16(kb + doff, g_K + ((size_t)bh * SEQ + kt * 64 + row) * 64 + c8 * 8);
            CP_ASYNC16(kb + 9216 + doff,
                       g_Vt + ((size_t)bh * 64 + row) * SEQ + kt * 64 + c8 * 8);
        }
    };

#pragma unroll
    for (int i = 0; i < 4; i++) {
        int c = i * 128 + tid;
        int row = c >> 3;
        int c8 = c & 7;
        uint32_t doff = (uint32_t)row * SR + c8 * 16;
        CP_ASYNC16(sb + AQ + doff,
                   g_Q + ((size_t)bh * SEQ + qt * 64 + row) * 64 + c8 * 8);
    }
    CP_COMMIT();
    kv_fill(0, 0); CP_COMMIT();
    kv_fill(1, 1); CP_COMMIT();
    CP_WAIT2();
    __syncthreads();

    uint32_t qf[4][4];
    {
        int rb = wid * 16;
#pragma unroll
        for (int ks = 0; ks < 4; ks++) {
            uint32_t addr = sb + AQ + (uint32_t)(rb + (lane & 15)) * SR
                          + (uint32_t)(ks * 16 + (lane >> 4) * 8) * 2;
            ldsm_x4(qf[ks], addr);
        }
    }

    float o[8][4];
#pragma unroll
    for (int nt = 0; nt < 8; nt++)
#pragma unroll
        for (int r = 0; r < 4; r++) o[nt][r] = 0.f;
    float mrow0 = -1e30f, mrow1 = -1e30f;
    float lrow0 = 0.f, lrow1 = 0.f;

#pragma unroll 1
    for (int kt = 0; kt < 32; kt++) {
        if (kt < 31) CP_WAIT1(); else CP_WAIT0();
        __syncthreads();
        if (kt < 30) {
            kv_fill((kt + 2) % 3, kt + 2);
            CP_COMMIT();
        }

        uint32_t kb = sb + AKV + (uint32_t)(kt % 3) * KVSZ;

        float sacc[8][4];
#pragma unroll
        for (int nt = 0; nt < 8; nt++)
#pragma unroll
            for (int r = 0; r < 4; r++) sacc[nt][r] = 0.f;
#pragma unroll
        for (int kh = 0; kh < 2; kh++) {
#pragma unroll
            for (int nt = 0; nt < 8; nt++) {
                uint32_t boff = (uint32_t)(nt * 8 + (lane & 7)) * SR
                              + (uint32_t)(kh * 32 + ((lane >> 3) & 3) * 8) * 2;
                uint32_t bf[4];
                ldsm_x4(bf, kb + boff);
#pragma unroll
                for (int kss = 0; kss < 2; kss++) {
                    int ks = kh * 2 + kss;
                    mma_f16(sacc[nt], qf[ks], bf[kss * 2], bf[kss * 2 + 1]);
                }
            }
        }

        float a0[8], a1[8];
#pragma unroll
        for (int nt = 0; nt < 8; nt++) {
            a0[nt] = fmaxf(sacc[nt][0], sacc[nt][1]);
            a1[nt] = fmaxf(sacc[nt][2], sacc[nt][3]);
        }
#pragma unroll
        for (int st = 4; st >= 1; st >>= 1)
#pragma unroll
            for (int j = 0; j < st; j++) {
                a0[j] = fmaxf(a0[j], a0[j + st]);
                a1[j] = fmaxf(a1[j], a1[j + st]);
            }
        uint32_t mpk = pack_h2(a0[0], a1[0]);
        mpk = hmax2(mpk, __shfl_xor_sync(0xffffffffu, mpk, 1));
        mpk = hmax2(mpk, __shfl_xor_sync(0xffffffffu, mpk, 2));
        float2 mxf = __half22float2(*(__half2*)&mpk);
        float mn0 = fmaxf(mrow0, mxf.x);
        float mn1 = fmaxf(mrow1, mxf.y);
        float cr0 = exp2f(mrow0 - mn0);
        float cr1 = exp2f(mrow1 - mn1);
        mrow0 = mn0; mrow1 = mn1;

        uint32_t ph[8][2];
        float ps0 = 0.f, ps1 = 0.f;
#pragma unroll
        for (int nt = 0; nt < 8; nt++) {
            ph[nt][0] = hexp2_x2(pack_h2(sacc[nt][0] - mn0, sacc[nt][1] - mn0));
            ph[nt][1] = hexp2_x2(pack_h2(sacc[nt][2] - mn1, sacc[nt][3] - mn1));
            float2 f0 = __half22float2(*(__half2*)&ph[nt][0]);
            float2 f1 = __half22float2(*(__half2*)&ph[nt][1]);
            ps0 += f0.x + f0.y;
            ps1 += f1.x + f1.y;
        }
        lrow0 = lrow0 * cr0 + ps0;
        lrow1 = lrow1 * cr1 + ps1;
        if (cr0 < 1.f || cr1 < 1.f) {
#pragma unroll
            for (int nt = 0; nt < 8; nt++) {
                o[nt][0] *= cr0; o[nt][1] *= cr0;
                o[nt][2] *= cr1; o[nt][3] *= cr1;
            }
        }

#pragma unroll
        for (int kh = 0; kh < 2; kh++) {
#pragma unroll
            for (int nt = 0; nt < 8; nt++) {
                uint32_t boff = (uint32_t)(nt * 8 + (lane & 7)) * SR
                              + (uint32_t)(kh * 32 + ((lane >> 3) & 3) * 8) * 2;
                uint32_t vf[4];
                ldsm_x4(vf, kb + 9216 + boff);
#pragma unroll
                for (int kss = 0; kss < 2; kss++) {
                    int ks = kh * 2 + kss;
                    uint32_t aPh[4] = {ph[2 * ks][0], ph[2 * ks][1],
                                       ph[2 * ks + 1][0], ph[2 * ks + 1][1]};
                    mma_f16(o[nt], aPh, vf[kss * 2], vf[kss * 2 + 1]);
                }
            }
        }
    }

    lrow0 += __shfl_xor_sync(0xffffffffu, lrow0, 1);
    lrow0 += __shfl_xor_sync(0xffffffffu, lrow0, 2);
    lrow1 += __shfl_xor_sync(0xffffffffu, lrow1, 1);
    lrow1 += __shfl_xor_sync(0xffffffffu, lrow1, 2);
    float inv0 = 1.f / lrow0;
    float inv1 = 1.f / lrow1;
    int b = bh >> 4, h = bh & 15;
    int s0 = qt * 64 + wid * 16 + g;
    int s1 = s0 + 8;
    size_t r0 = ((size_t)b * SEQ + s0) * DMODEL + h * 64;
    size_t r1 = ((size_t)b * SEQ + s1) * DMODEL + h * 64;
#pragma unroll
    for (int nt = 0; nt < 8; nt++) {
        int d0 = nt * 8 + t2;
        *(uint32_t*)(g_attn + r0 + d0) = pack_h2(o[nt][0] * inv0, o[nt][1] * inv0);
        *(uint32_t*)(g_attn + r1 + d0) = pack_h2(o[nt][2] * inv1, o[nt][3] * inv1);
    }
}

// ---------------------------------------------------------------------------
extern "C" void kernel_launch(void* const* d_in, const int* in_sizes, int n_in,
                              void* d_out, int out_size)
{
    const float* query = (const float*)d_in[0];
    const float* W_qkv = (const float*)d_in[1];
    const float* b_qkv = (const float*)d_in[2];
    const float* W_out = (const float*)d_in[3];
    const float* b_out = (const float*)d_in[4];
    float* out = (float*)d_out;

    cudaFuncSetAttribute(mma_gemm_kernel<0>, cudaFuncAttributeMaxDynamicSharedMemorySize, GEMM_SMEM);
    cudaFuncSetAttribute(mma_gemm_kernel<1>, cudaFuncAttributeMaxDynamicSharedMemorySize, GEMM_SMEM);
    cudaFuncSetAttribute(attn_mma_kernel, cudaFuncAttributeMaxDynamicSharedMemorySize, ATTN_SMEM);

    prep_w_kernel<<<(PREPW_THREADS + 255) / 256, 256>>>(W_qkv, W_out);
    prep_x_kernel<<<(X_THREADS + ROPE_ENTRIES + 255) / 256, 256>>>(query);
    {
        dim3 grid(NROWS / 128, QKV_N / 128);   // 64 x 24
        mma_gemm_kernel<0><<<grid, 256, GEMM_SMEM>>>(b_qkv, nullptr);
    }
    // attention (launch #4 -> ncu capture slot)
    {
        dim3 grid(SEQ / 64, BATCH * NHEADS);   // 32 x 64
        attn_mma_kernel<<<grid, 128, ATTN_SMEM>>>();
    }
    {
        dim3 grid(NROWS / 128, DMODEL / 128);  // 64 x 8
        mma_gemm_kernel<1><<<grid, 256, GEMM_SMEM>>>(b_out, out);
    }
}

// round 16
// speedup vs baseline: 8.3305x; 1.0143x over previous
#include <cuda_runtime.h>
#include <cuda_fp16.h>
#include <math.h>
#include <stdint.h>

#define BATCH 4
#define SEQ 2048
#define DMODEL 1024
#define NHEADS 16
#define HDIM 64
#define NROWS (BATCH * SEQ)          // 8192
#define QKV_N (3 * DMODEL)           // 3072
#define LOG2E 1.4426950408889634f

// ---------------------------------------------------------------------------
// PTX helpers
// ---------------------------------------------------------------------------
__device__ __forceinline__ uint32_t smem_to_u32(const void* p) {
    uint32_t a;
    asm("{ .reg .u64 t; cvta.to.shared.u64 t, %1; cvt.u32.u64 %0, t; }" : "=r"(a) : "l"(p));
    return a;
}

__device__ __forceinline__ void mma_f16(float* d, const uint32_t* a,
                                        uint32_t b0, uint32_t b1) {
    asm volatile(
        "mma.sync.aligned.m16n8k16.row.col.f32.f16.f16.f32 "
        "{%0,%1,%2,%3}, {%4,%5,%6,%7}, {%8,%9}, {%0,%1,%2,%3};"
        : "+f"(d[0]), "+f"(d[1]), "+f"(d[2]), "+f"(d[3])
        : "r"(a[0]), "r"(a[1]), "r"(a[2]), "r"(a[3]), "r"(b0), "r"(b1));
}

__device__ __forceinline__ void ldsm_x4(uint32_t* r, uint32_t addr) {
    asm volatile("ldmatrix.sync.aligned.m8n8.x4.shared.b16 {%0,%1,%2,%3}, [%4];"
                 : "=r"(r[0]), "=r"(r[1]), "=r"(r[2]), "=r"(r[3]) : "r"(addr));
}

#define CP_ASYNC16(dst, src) \
    asm volatile("cp.async.cg.shared.global [%0], [%1], 16;" :: "r"(dst), "l"(src))
#define CP_COMMIT() asm volatile("cp.async.commit_group;" ::: "memory")
#define CP_WAIT2()  asm volatile("cp.async.wait_group 2;" ::: "memory")
#define CP_WAIT1()  asm volatile("cp.async.wait_group 1;" ::: "memory")
#define CP_WAIT0()  asm volatile("cp.async.wait_group 0;" ::: "memory")

#define SW128(off) ((off) ^ (((off) >> 3) & 0x70))

__device__ __forceinline__ uint32_t pack_h2(float lo, float hi) {
    __half2 h = __floats2half2_rn(lo, hi);
    return *(uint32_t*)&h;
}
__device__ __forceinline__ uint32_t hexp2_x2(uint32_t x) {
    uint32_t r;
    asm("ex2.approx.f16x2 %0, %1;" : "=r"(r) : "r"(x));
    return r;
}
__device__ __forceinline__ uint32_t hmax2(uint32_t a, uint32_t b) {
    uint32_t r;
    asm("max.f16x2 %0, %1, %2;" : "=r"(r) : "r"(a), "r"(b));
    return r;
}

// ---------------------------------------------------------------------------
// Scratch
// ---------------------------------------------------------------------------
__device__ float g_rope_cos[SEQ * 32];
__device__ float g_rope_sin[SEQ * 32];

__device__ __half g_X[NROWS * DMODEL];
__device__ __half g_Wqkv[QKV_N * DMODEL];
__device__ __half g_Wout[DMODEL * DMODEL];

__device__ __half g_Q[64 * SEQ * HDIM];
__device__ __half g_K[64 * SEQ * HDIM];
__device__ __half g_Vt[64 * HDIM * SEQ];

__device__ __half g_attn[NROWS * DMODEL];

// ---------------------------------------------------------------------------
// prep: weights fp16 convert + X convert + rope tables, one launch
// ---------------------------------------------------------------------------
static constexpr int WQKV_ELEMS = QKV_N * DMODEL;
static constexpr int WOUT_ELEMS = DMODEL * DMODEL;
static constexpr int PREPW_THREADS = (WQKV_ELEMS + WOUT_ELEMS) / 4;   // 1048576
static constexpr int X_THREADS = NROWS * DMODEL / 4;                  // 2097152
static constexpr int ROPE_ENTRIES = SEQ * 32;                         // 65536
static constexpr int PREP_TOTAL = PREPW_THREADS + X_THREADS + ROPE_ENTRIES;

__global__ void prep_kernel(const float* __restrict__ query,
                            const float* __restrict__ W_qkv,
                            const float* __restrict__ W_out) {
    int gid = blockIdx.x * blockDim.x + threadIdx.x;
    if (gid < PREPW_THREADS) {
        int i = gid * 4;
        const float* src;
        __half* hp;
        if (i < WQKV_ELEMS) { src = W_qkv + i; hp = g_Wqkv + i; }
        else { int j = i - WQKV_ELEMS; src = W_out + j; hp = g_Wout + j; }
        float4 v = *(const float4*)src;
        uint2 w;
        w.x = pack_h2(v.x, v.y);
        w.y = pack_h2(v.z, v.w);
        *(uint2*)hp = w;
    } else if (gid < PREPW_THREADS + X_THREADS) {
        int i = (gid - PREPW_THREADS) * 4;
        float4 v = *(const float4*)(query + i);
        uint2 w;
        w.x = pack_h2(v.x, v.y);
        w.y = pack_h2(v.z, v.w);
        *(uint2*)(g_X + i) = w;
    } else {
        int idx = gid - PREPW_THREADS - X_THREADS;
        if (idx >= ROPE_ENTRIES) return;
        int s = idx >> 5;
        int i = idx & 31;
        float inv_freq = powf(10000.0f, -(float)i / 32.0f);
        float ang = (float)s * inv_freq;
        float sn, cs;
        sincosf(ang, &sn, &cs);
        g_rope_cos[idx] = cs;
        g_rope_sin[idx] = sn;
    }
}

// ---------------------------------------------------------------------------
// GEMM (unchanged from R14): single fp16 operands, BK=32, 3-stage ring.
// ---------------------------------------------------------------------------
#define SAB 80
static constexpr uint32_t GOFF_A = 0, GOFF_B = 10240;
static constexpr uint32_t GBUFSZ = 20480;
static constexpr uint32_t GOFF_BIAS = 61440;
static constexpr uint32_t GEMM_SMEM = 61952;

template <int MODE>
__global__ __launch_bounds__(256, 2) void mma_gemm_kernel(
    const float* __restrict__ bias, float* __restrict__ outp)
{
    extern __shared__ char smch[];
    uint32_t sb = smem_to_u32(smch);
    int tid = threadIdx.x;
    int wid = tid >> 5;
    int lane = tid & 31;
    int g = lane >> 2;
    int t2 = (lane & 3) * 2;
    int warp_m = wid >> 1;
    int warp_n = wid & 1;
    int m0 = blockIdx.x * 128;
    int n0 = blockIdx.y * 128;

    const __half* A = (MODE == 0) ? g_X : g_attn;
    const __half* B = (MODE == 0) ? g_Wqkv : g_Wout;

    float* sbias = (float*)(smch + GOFF_BIAS);
    if (tid < 128) sbias[tid] = bias[n0 + tid];

    float acc[2][8][4];
#pragma unroll
    for (int mt = 0; mt < 2; mt++)
#pragma unroll
        for (int nt = 0; nt < 8; nt++)
#pragma unroll
            for (int r = 0; r < 4; r++) acc[mt][nt][r] = 0.f;

    auto fill = [&](int stage, int k0) {
        uint32_t bofs = sb + (uint32_t)stage * GBUFSZ;
#pragma unroll
        for (int i = 0; i < 2; i++) {
            int c = i * 256 + tid;
            int row = c >> 2;
            int c8 = c & 3;
            uint32_t doff = (uint32_t)row * SAB + c8 * 16;
            CP_ASYNC16(bofs + GOFF_A + doff, A + (size_t)(m0 + row) * DMODEL + k0 + c8 * 8);
            CP_ASYNC16(bofs + GOFF_B + doff, B + (size_t)(n0 + row) * DMODEL + k0 + c8 * 8);
        }
    };

    fill(0, 0);  CP_COMMIT();
    fill(1, 32); CP_COMMIT();

#pragma unroll 1
    for (int ck = 0; ck < 32; ck++) {
        if (ck < 31) CP_WAIT1(); else CP_WAIT0();
        __syncthreads();
        if (ck < 30) {
            fill((ck + 2) % 3, (ck + 2) * 32);
            CP_COMMIT();
        }

        uint32_t bb = sb + (uint32_t)(ck % 3) * GBUFSZ;
        uint32_t af[2][2][4];
#pragma unroll
        for (int mt = 0; mt < 2; mt++)
#pragma unroll
            for (int kss = 0; kss < 2; kss++) {
                uint32_t addr = bb + GOFF_A
                    + (uint32_t)(warp_m * 32 + mt * 16 + (lane & 15)) * SAB
                    + (uint32_t)(kss * 16 + (lane >> 4) * 8) * 2;
                ldsm_x4(af[mt][kss], addr);
            }
#pragma unroll
        for (int nt = 0; nt < 8; nt++) {
            uint32_t boff = (uint32_t)(warp_n * 64 + nt * 8 + (lane & 7)) * SAB
                          + (uint32_t)(((lane >> 3) & 3) * 8) * 2;
            uint32_t bf[4];
            ldsm_x4(bf, bb + GOFF_B + boff);
#pragma unroll
            for (int kss = 0; kss < 2; kss++)
#pragma unroll
                for (int mt = 0; mt < 2; mt++)
                    mma_f16(acc[mt][nt], af[mt][kss], bf[kss * 2], bf[kss * 2 + 1]);
        }
    }

    int nwb = n0 + warp_n * 64;
    if (MODE == 1) {
#pragma unroll
        for (int mt = 0; mt < 2; mt++) {
            int r0 = m0 + warp_m * 32 + mt * 16 + g;
#pragma unroll
            for (int nt = 0; nt < 8; nt++) {
                int ncol = nwb + nt * 8 + t2;
                float b0 = sbias[warp_n * 64 + nt * 8 + t2];
                float b1 = sbias[warp_n * 64 + nt * 8 + t2 + 1];
                float2 w0 = make_float2(acc[mt][nt][0] + b0, acc[mt][nt][1] + b1);
                float2 w1 = make_float2(acc[mt][nt][2] + b0, acc[mt][nt][3] + b1);
                *(float2*)(outp + (size_t)r0 * DMODEL + ncol) = w0;
                *(float2*)(outp + (size_t)(r0 + 8) * DMODEL + ncol) = w1;
            }
        }
    } else {
        int which = nwb >> 10;
        int h = (nwb & 1023) >> 6;
#pragma unroll
        for (int mt = 0; mt < 2; mt++) {
            int m_g = m0 + warp_m * 32 + mt * 16 + g;
#pragma unroll
            for (int rr = 0; rr < 2; rr++) {
                int mrow = m_g + rr * 8;
                int b = mrow >> 11;
                int s = mrow & 2047;
                int bh = b * NHEADS + h;
                if (which == 2) {
#pragma unroll
                    for (int nt = 0; nt < 8; nt++) {
#pragma unroll
                        for (int dd = 0; dd < 2; dd++) {
                            int d = nt * 8 + t2 + dd;
                            float v = acc[mt][nt][rr * 2 + dd] + sbias[warp_n * 64 + d];
                            g_Vt[((size_t)bh * 64 + d) * SEQ + s] = __float2half_rn(v);
                        }
                    }
                } else {
                    size_t rowbase = ((size_t)bh * SEQ + s) * 64;
                    float qs = (which == 0) ? (0.125f * LOG2E) : 1.0f;
                    __half* dst = (which == 0) ? g_Q : g_K;
#pragma unroll
                    for (int nt = 0; nt < 4; nt++) {
                        int d = nt * 8 + t2;
                        float x1a = acc[mt][nt][rr * 2]         + sbias[warp_n * 64 + d];
                        float x1b = acc[mt][nt][rr * 2 + 1]     + sbias[warp_n * 64 + d + 1];
                        float x2a = acc[mt][nt + 4][rr * 2]     + sbias[warp_n * 64 + d + 32];
                        float x2b = acc[mt][nt + 4][rr * 2 + 1] + sbias[warp_n * 64 + d + 33];
                        float csa = g_rope_cos[s * 32 + d],   sna = g_rope_sin[s * 32 + d];
                        float csb = g_rope_cos[s * 32 + d+1], snb = g_rope_sin[s * 32 + d+1];
                        float y1a = (x1a * csa - x2a * sna) * qs;
                        float y1b = (x1b * csb - x2b * snb) * qs;
                        float y2a = (x2a * csa + x1a * sna) * qs;
                        float y2b = (x2b * csb + x1b * snb) * qs;
                        *(uint32_t*)(dst + rowbase + d)      = pack_h2(y1a, y1b);
                        *(uint32_t*)(dst + rowbase + d + 32) = pack_h2(y2a, y2b);
                    }
                }
            }
        }
    }
}

// ---------------------------------------------------------------------------
// Flash attention: SW128 swizzled smem (no pad), Q fragments reloaded per use,
// P aliased into score registers; target 4 CTAs/SM.
// smem: Q [0,8192); KV stages at 8192, stride 16384 (K +0, V +8192), x3.
// ---------------------------------------------------------------------------
static constexpr uint32_t AQ = 0, AKV = 8192, KVSZ = 16384;
static constexpr uint32_t ATTN_SMEM = AKV + 3 * KVSZ;   // 57344

__global__ __launch_bounds__(128, 4) void attn_mma_kernel()
{
    extern __shared__ char smch[];
    uint32_t sb = smem_to_u32(smch);
    int tid = threadIdx.x;
    int wid = tid >> 5;
    int lane = tid & 31;
    int g = lane >> 2;
    int t2 = (lane & 3) * 2;
    int bh = blockIdx.y;
    int qt = blockIdx.x;

    auto kv_fill = [&](int stage, int kt) {
        uint32_t kb = sb + AKV + (uint32_t)stage * KVSZ;
#pragma unroll
        for (int i = 0; i < 4; i++) {
            int c = i * 128 + tid;
            int row = c >> 3;
            int c8 = c & 7;
            uint32_t doff = SW128((uint32_t)(row * 128 + c8 * 16));
            CP_ASYNC16(kb + doff, g_K + ((size_t)bh * SEQ + kt * 64 + row) * 64 + c8 * 8);
            CP_ASYNC16(kb + 8192 + doff,
                       g_Vt + ((size_t)bh * 64 + row) * SEQ + kt * 64 + c8 * 8);
        }
    };

    // Q fill
#pragma unroll
    for (int i = 0; i < 4; i++) {
        int c = i * 128 + tid;
        int row = c >> 3;
        int c8 = c & 7;
        uint32_t doff = SW128((uint32_t)(row * 128 + c8 * 16));
        CP_ASYNC16(sb + AQ + doff,
                   g_Q + ((size_t)bh * SEQ + qt * 64 + row) * 64 + c8 * 8);
    }
    CP_COMMIT();
    kv_fill(0, 0); CP_COMMIT();
    kv_fill(1, 1); CP_COMMIT();
    CP_WAIT2();
    __syncthreads();

    float o[8][4];
#pragma unroll
    for (int nt = 0; nt < 8; nt++)
#pragma unroll
        for (int r = 0; r < 4; r++) o[nt][r] = 0.f;
    float mrow0 = -1e30f, mrow1 = -1e30f;
    float lrow0 = 0.f, lrow1 = 0.f;
    int qrb = wid * 16;

#pragma unroll 1
    for (int kt = 0; kt < 32; kt++) {
        if (kt < 31) CP_WAIT1(); else CP_WAIT0();
        __syncthreads();
        if (kt < 30) {
            kv_fill((kt + 2) % 3, kt + 2);
            CP_COMMIT();
        }

        uint32_t kb = sb + AKV + (uint32_t)(kt % 3) * KVSZ;

        // scores: Q x K (Q fragments from smem each half)
        float sacc[8][4];
#pragma unroll
        for (int nt = 0; nt < 8; nt++)
#pragma unroll
            for (int r = 0; r < 4; r++) sacc[nt][r] = 0.f;
#pragma unroll
        for (int kh = 0; kh < 2; kh++) {
            uint32_t qtmp[2][4];
#pragma unroll
            for (int kss = 0; kss < 2; kss++) {
                uint32_t qoff = SW128((uint32_t)((qrb + (lane & 15)) * 128
                               + kh * 64 + kss * 32 + (lane >> 4) * 16));
                ldsm_x4(qtmp[kss], sb + AQ + qoff);
            }
#pragma unroll
            for (int nt = 0; nt < 8; nt++) {
                uint32_t boff = SW128((uint32_t)((nt * 8 + (lane & 7)) * 128
                              + kh * 64 + ((lane >> 3) & 3) * 16));
                uint32_t bf[4];
                ldsm_x4(bf, kb + boff);
#pragma unroll
                for (int kss = 0; kss < 2; kss++)
                    mma_f16(sacc[nt], qtmp[kss], bf[kss * 2], bf[kss * 2 + 1]);
            }
        }

        // max: balanced tree + packed-half2 quad butterfly
        float a0[8], a1[8];
#pragma unroll
        for (int nt = 0; nt < 8; nt++) {
            a0[nt] = fmaxf(sacc[nt][0], sacc[nt][1]);
            a1[nt] = fmaxf(sacc[nt][2], sacc[nt][3]);
        }
#pragma unroll
        for (int st = 4; st >= 1; st >>= 1)
#pragma unroll
            for (int j = 0; j < st; j++) {
                a0[j] = fmaxf(a0[j], a0[j + st]);
                a1[j] = fmaxf(a1[j], a1[j + st]);
            }
        uint32_t mpk = pack_h2(a0[0], a1[0]);
        mpk = hmax2(mpk, __shfl_xor_sync(0xffffffffu, mpk, 1));
        mpk = hmax2(mpk, __shfl_xor_sync(0xffffffffu, mpk, 2));
        float2 mxf = __half22float2(*(__half2*)&mpk);
        float mn0 = fmaxf(mrow0, mxf.x);
        float mn1 = fmaxf(mrow1, mxf.y);
        float cr0 = exp2f(mrow0 - mn0);
        float cr1 = exp2f(mrow1 - mn1);
        mrow0 = mn0; mrow1 = mn1;

        // P = exp2(s - m) packed fp16, stored back INTO sacc[.][0..1]
        float ps0 = 0.f, ps1 = 0.f;
#pragma unroll
        for (int nt = 0; nt < 8; nt++) {
            uint32_t p0 = hexp2_x2(pack_h2(sacc[nt][0] - mn0, sacc[nt][1] - mn0));
            uint32_t p1 = hexp2_x2(pack_h2(sacc[nt][2] - mn1, sacc[nt][3] - mn1));
            float2 f0 = __half22float2(*(__half2*)&p0);
            float2 f1 = __half22float2(*(__half2*)&p1);
            ps0 += f0.x + f0.y;
            ps1 += f1.x + f1.y;
            sacc[nt][0] = __uint_as_float(p0);
            sacc[nt][1] = __uint_as_float(p1);
        }
        lrow0 = lrow0 * cr0 + ps0;
        lrow1 = lrow1 * cr1 + ps1;
        if (cr0 < 1.f || cr1 < 1.f) {
#pragma unroll
            for (int nt = 0; nt < 8; nt++) {
                o[nt][0] *= cr0; o[nt][1] *= cr0;
                o[nt][2] *= cr1; o[nt][3] *= cr1;
            }
        }

        // O += P x V
#pragma unroll
        for (int kh = 0; kh < 2; kh++) {
#pragma unroll
            for (int nt = 0; nt < 8; nt++) {
                uint32_t boff = SW128((uint32_t)((nt * 8 + (lane & 7)) * 128
                              + kh * 64 + ((lane >> 3) & 3) * 16));
                uint32_t vf[4];
                ldsm_x4(vf, kb + 8192 + boff);
#pragma unroll
                for (int kss = 0; kss < 2; kss++) {
                    int ks = kh * 2 + kss;
                    uint32_t aPh[4] = {__float_as_uint(sacc[2 * ks][0]),
                                       __float_as_uint(sacc[2 * ks][1]),
                                       __float_as_uint(sacc[2 * ks + 1][0]),
                                       __float_as_uint(sacc[2 * ks + 1][1])};
                    mma_f16(o[nt], aPh, vf[kss * 2], vf[kss * 2 + 1]);
                }
            }
        }
    }

    lrow0 += __shfl_xor_sync(0xffffffffu, lrow0, 1);
    lrow0 += __shfl_xor_sync(0xffffffffu, lrow0, 2);
    lrow1 += __shfl_xor_sync(0xffffffffu, lrow1, 1);
    lrow1 += __shfl_xor_sync(0xffffffffu, lrow1, 2);
    float inv0 = 1.f / lrow0;
    float inv1 = 1.f / lrow1;
    int b = bh >> 4, h = bh & 15;
    int s0 = qt * 64 + wid * 16 + g;
    int s1 = s0 + 8;
    size_t r0 = ((size_t)b * SEQ + s0) * DMODEL + h * 64;
    size_t r1 = ((size_t)b * SEQ + s1) * DMODEL + h * 64;
#pragma unroll
    for (int nt = 0; nt < 8; nt++) {
        int d0 = nt * 8 + t2;
        *(uint32_t*)(g_attn + r0 + d0) = pack_h2(o[nt][0] * inv0, o[nt][1] * inv0);
        *(uint32_t*)(g_attn + r1 + d0) = pack_h2(o[nt][2] * inv1, o[nt][3] * inv1);
    }
}

// ---------------------------------------------------------------------------
extern "C" void kernel_launch(void* const* d_in, const int* in_sizes, int n_in,
                              void* d_out, int out_size)
{
    const float* query = (const float*)d_in[0];
    const float* W_qkv = (const float*)d_in[1];
    const float* b_qkv = (const float*)d_in[2];
    const float* W_out = (const float*)d_in[3];
    const float* b_out = (const float*)d_in[4];
    float* out = (float*)d_out;

    cudaFuncSetAttribute(mma_gemm_kernel<0>, cudaFuncAttributeMaxDynamicSharedMemorySize, GEMM_SMEM);
    cudaFuncSetAttribute(mma_gemm_kernel<1>, cudaFuncAttributeMaxDynamicSharedMemorySize, GEMM_SMEM);
    cudaFuncSetAttribute(attn_mma_kernel, cudaFuncAttributeMaxDynamicSharedMemorySize, ATTN_SMEM);

    // 1: prep (weights + X + rope, merged)
    prep_kernel<<<(PREP_TOTAL + 255) / 256, 256>>>(query, W_qkv, W_out);
    // 2: QKV projection + RoPE + scatter  (<- ncu capture slot next round)
    {
        dim3 grid(NROWS / 128, QKV_N / 128);   // 64 x 24
        mma_gemm_kernel<0><<<grid, 256, GEMM_SMEM>>>(b_qkv, nullptr);
    }
    // 3: attention
    {
        dim3 grid(SEQ / 64, BATCH * NHEADS);   // 32 x 64
        attn_mma_kernel<<<grid, 128, ATTN_SMEM>>>();
    }
    // 4: output projection
    {
        dim3 grid(NROWS / 128, DMODEL / 128);  // 64 x 8
        mma_gemm_kernel<1><<<grid, 256, GEMM_SMEM>>>(b_out, out);
    }
}

// round 17
// speedup vs baseline: 8.9358x; 1.0727x over previous
#include <cuda_runtime.h>
#include <cuda_fp16.h>
#include <math.h>
#include <stdint.h>

#define BATCH 4
#define SEQ 2048
#define DMODEL 1024
#define NHEADS 16
#define HDIM 64
#define NROWS (BATCH * SEQ)          // 8192
#define QKV_N (3 * DMODEL)           // 3072
#define LOG2E 1.4426950408889634f

// ---------------------------------------------------------------------------
// PTX helpers
// ---------------------------------------------------------------------------
__device__ __forceinline__ uint32_t smem_to_u32(const void* p) {
    uint32_t a;
    asm("{ .reg .u64 t; cvta.to.shared.u64 t, %1; cvt.u32.u64 %0, t; }" : "=r"(a) : "l"(p));
    return a;
}

__device__ __forceinline__ void mma_f16(float* d, const uint32_t* a,
                                        uint32_t b0, uint32_t b1) {
    asm volatile(
        "mma.sync.aligned.m16n8k16.row.col.f32.f16.f16.f32 "
        "{%0,%1,%2,%3}, {%4,%5,%6,%7}, {%8,%9}, {%0,%1,%2,%3};"
        : "+f"(d[0]), "+f"(d[1]), "+f"(d[2]), "+f"(d[3])
        : "r"(a[0]), "r"(a[1]), "r"(a[2]), "r"(a[3]), "r"(b0), "r"(b1));
}

__device__ __forceinline__ void ldsm_x4(uint32_t* r, uint32_t addr) {
    asm volatile("ldmatrix.sync.aligned.m8n8.x4.shared.b16 {%0,%1,%2,%3}, [%4];"
                 : "=r"(r[0]), "=r"(r[1]), "=r"(r[2]), "=r"(r[3]) : "r"(addr));
}

#define CP_ASYNC16(dst, src) \
    asm volatile("cp.async.cg.shared.global [%0], [%1], 16;" :: "r"(dst), "l"(src))
#define CP_COMMIT() asm volatile("cp.async.commit_group;" ::: "memory")
#define CP_WAIT2()  asm volatile("cp.async.wait_group 2;" ::: "memory")
#define CP_WAIT1()  asm volatile("cp.async.wait_group 1;" ::: "memory")
#define CP_WAIT0()  asm volatile("cp.async.wait_group 0;" ::: "memory")

#define SW128(off) ((off) ^ (((off) >> 3) & 0x70))

__device__ __forceinline__ uint32_t pack_h2(float lo, float hi) {
    __half2 h = __floats2half2_rn(lo, hi);
    return *(uint32_t*)&h;
}
__device__ __forceinline__ uint32_t hexp2_x2(uint32_t x) {
    uint32_t r;
    asm("ex2.approx.f16x2 %0, %1;" : "=r"(r) : "r"(x));
    return r;
}
__device__ __forceinline__ uint32_t hmax2(uint32_t a, uint32_t b) {
    uint32_t r;
    asm("max.f16x2 %0, %1, %2;" : "=r"(r) : "r"(a), "r"(b));
    return r;
}

// ---------------------------------------------------------------------------
// Scratch
// ---------------------------------------------------------------------------
__device__ float g_rope_cos[SEQ * 32];
__device__ float g_rope_sin[SEQ * 32];

__device__ __half g_X[NROWS * DMODEL];
__device__ __half g_Wqkv[QKV_N * DMODEL];
__device__ __half g_Wout[DMODEL * DMODEL];

__device__ __half g_Q[64 * SEQ * HDIM];
__device__ __half g_K[64 * SEQ * HDIM];
__device__ __half g_Vt[64 * HDIM * SEQ];

__device__ __half g_attn[NROWS * DMODEL];

// ---------------------------------------------------------------------------
// prep: weights fp16 convert + X convert + rope tables, one launch
// ---------------------------------------------------------------------------
static constexpr int WQKV_ELEMS = QKV_N * DMODEL;
static constexpr int WOUT_ELEMS = DMODEL * DMODEL;
static constexpr int PREPW_THREADS = (WQKV_ELEMS + WOUT_ELEMS) / 4;
static constexpr int X_THREADS = NROWS * DMODEL / 4;
static constexpr int ROPE_ENTRIES = SEQ * 32;
static constexpr int PREP_TOTAL = PREPW_THREADS + X_THREADS + ROPE_ENTRIES;

__global__ void prep_kernel(const float* __restrict__ query,
                            const float* __restrict__ W_qkv,
                            const float* __restrict__ W_out) {
    int gid = blockIdx.x * blockDim.x + threadIdx.x;
    if (gid < PREPW_THREADS) {
        int i = gid * 4;
        const float* src;
        __half* hp;
        if (i < WQKV_ELEMS) { src = W_qkv + i; hp = g_Wqkv + i; }
        else { int j = i - WQKV_ELEMS; src = W_out + j; hp = g_Wout + j; }
        float4 v = *(const float4*)src;
        uint2 w;
        w.x = pack_h2(v.x, v.y);
        w.y = pack_h2(v.z, v.w);
        *(uint2*)hp = w;
    } else if (gid < PREPW_THREADS + X_THREADS) {
        int i = (gid - PREPW_THREADS) * 4;
        float4 v = *(const float4*)(query + i);
        uint2 w;
        w.x = pack_h2(v.x, v.y);
        w.y = pack_h2(v.z, v.w);
        *(uint2*)(g_X + i) = w;
    } else {
        int idx = gid - PREPW_THREADS - X_THREADS;
        if (idx >= ROPE_ENTRIES) return;
        int s = idx >> 5;
        int i = idx & 31;
        float inv_freq = powf(10000.0f, -(float)i / 32.0f);
        float ang = (float)s * inv_freq;
        float sn, cs;
        sincosf(ang, &sn, &cs);
        g_rope_cos[idx] = cs;
        g_rope_sin[idx] = sn;
    }
}

// ---------------------------------------------------------------------------
// GEMM: single fp16 operands; BM=128 BN=128 BK=64; 3-stage cp.async ring;
// one barrier per 64-deep K chunk (16 barriers total).
// MODE 0: A=g_X, B=g_Wqkv; epilogue bias+RoPE -> Q, K, Vt
// MODE 1: A=g_attn, B=g_Wout; epilogue bias -> out fp32
// ---------------------------------------------------------------------------
#define SAB 144     // smem row stride bytes (64 halves + 8 pad)
static constexpr uint32_t GOFF_A = 0, GOFF_B = 18432;
static constexpr uint32_t GBUFSZ = 36864;
static constexpr uint32_t GOFF_BIAS = 110592;
static constexpr uint32_t GEMM_SMEM = 111104;

template <int MODE>
__global__ __launch_bounds__(256, 2) void mma_gemm_kernel(
    const float* __restrict__ bias, float* __restrict__ outp)
{
    extern __shared__ char smch[];
    uint32_t sb = smem_to_u32(smch);
    int tid = threadIdx.x;
    int wid = tid >> 5;
    int lane = tid & 31;
    int g = lane >> 2;
    int t2 = (lane & 3) * 2;
    int warp_m = wid >> 1;
    int warp_n = wid & 1;
    int m0 = blockIdx.x * 128;
    int n0 = blockIdx.y * 128;

    const __half* A = (MODE == 0) ? g_X : g_attn;
    const __half* B = (MODE == 0) ? g_Wqkv : g_Wout;

    float* sbias = (float*)(smch + GOFF_BIAS);
    if (tid < 128) sbias[tid] = bias[n0 + tid];

    float acc[2][8][4];
#pragma unroll
    for (int mt = 0; mt < 2; mt++)
#pragma unroll
        for (int nt = 0; nt < 8; nt++)
#pragma unroll
            for (int r = 0; r < 4; r++) acc[mt][nt][r] = 0.f;

    // fill one stage (BK=64): 1024 chunks/array, 4 per thread per array
    auto fill = [&](int stage, int k0) {
        uint32_t bofs = sb + (uint32_t)stage * GBUFSZ;
#pragma unroll
        for (int i = 0; i < 4; i++) {
            int c = i * 256 + tid;
            int row = c >> 3;
            int c8 = c & 7;
            uint32_t doff = (uint32_t)row * SAB + c8 * 16;
            CP_ASYNC16(bofs + GOFF_A + doff, A + (size_t)(m0 + row) * DMODEL + k0 + c8 * 8);
            CP_ASYNC16(bofs + GOFF_B + doff, B + (size_t)(n0 + row) * DMODEL + k0 + c8 * 8);
        }
    };

    fill(0, 0);  CP_COMMIT();
    fill(1, 64); CP_COMMIT();

#pragma unroll 1
    for (int ck = 0; ck < 16; ck++) {
        if (ck < 15) CP_WAIT1(); else CP_WAIT0();
        __syncthreads();
        if (ck < 14) {
            fill((ck + 2) % 3, (ck + 2) * 64);
            CP_COMMIT();
        }

        uint32_t bb = sb + (uint32_t)(ck % 3) * GBUFSZ;
#pragma unroll
        for (int kh = 0; kh < 2; kh++) {
            uint32_t af[2][2][4];
#pragma unroll
            for (int mt = 0; mt < 2; mt++)
#pragma unroll
                for (int kss = 0; kss < 2; kss++) {
                    uint32_t addr = bb + GOFF_A
                        + (uint32_t)(warp_m * 32 + mt * 16 + (lane & 15)) * SAB
                        + (uint32_t)(kh * 64 + kss * 32 + (lane >> 4) * 16);
                    ldsm_x4(af[mt][kss], addr);
                }
#pragma unroll
            for (int nt = 0; nt < 8; nt++) {
                uint32_t boff = (uint32_t)(warp_n * 64 + nt * 8 + (lane & 7)) * SAB
                              + (uint32_t)(kh * 64 + ((lane >> 3) & 3) * 16);
                uint32_t bf[4];
                ldsm_x4(bf, bb + GOFF_B + boff);
#pragma unroll
                for (int kss = 0; kss < 2; kss++)
#pragma unroll
                    for (int mt = 0; mt < 2; mt++)
                        mma_f16(acc[mt][nt], af[mt][kss], bf[kss * 2], bf[kss * 2 + 1]);
            }
        }
    }

    // ----- epilogue -----
    int nwb = n0 + warp_n * 64;
    if (MODE == 1) {
#pragma unroll
        for (int mt = 0; mt < 2; mt++) {
            int r0 = m0 + warp_m * 32 + mt * 16 + g;
#pragma unroll
            for (int nt = 0; nt < 8; nt++) {
                int ncol = nwb + nt * 8 + t2;
                float b0 = sbias[warp_n * 64 + nt * 8 + t2];
                float b1 = sbias[warp_n * 64 + nt * 8 + t2 + 1];
                float2 w0 = make_float2(acc[mt][nt][0] + b0, acc[mt][nt][1] + b1);
                float2 w1 = make_float2(acc[mt][nt][2] + b0, acc[mt][nt][3] + b1);
                *(float2*)(outp + (size_t)r0 * DMODEL + ncol) = w0;
                *(float2*)(outp + (size_t)(r0 + 8) * DMODEL + ncol) = w1;
            }
        }
    } else {
        int which = nwb >> 10;
        int h = (nwb & 1023) >> 6;
#pragma unroll
        for (int mt = 0; mt < 2; mt++) {
            int m_g = m0 + warp_m * 32 + mt * 16 + g;
#pragma unroll
            for (int rr = 0; rr < 2; rr++) {
                int mrow = m_g + rr * 8;
                int b = mrow >> 11;
                int s = mrow & 2047;
                int bh = b * NHEADS + h;
                if (which == 2) {
#pragma unroll
                    for (int nt = 0; nt < 8; nt++) {
#pragma unroll
                        for (int dd = 0; dd < 2; dd++) {
                            int d = nt * 8 + t2 + dd;
                            float v = acc[mt][nt][rr * 2 + dd] + sbias[warp_n * 64 + d];
                            g_Vt[((size_t)bh * 64 + d) * SEQ + s] = __float2half_rn(v);
                        }
                    }
                } else {
                    size_t rowbase = ((size_t)bh * SEQ + s) * 64;
                    float qs = (which == 0) ? (0.125f * LOG2E) : 1.0f;
                    __half* dst = (which == 0) ? g_Q : g_K;
#pragma unroll
                    for (int nt = 0; nt < 4; nt++) {
                        int d = nt * 8 + t2;
                        float x1a = acc[mt][nt][rr * 2]         + sbias[warp_n * 64 + d];
                        float x1b = acc[mt][nt][rr * 2 + 1]     + sbias[warp_n * 64 + d + 1];
                        float x2a = acc[mt][nt + 4][rr * 2]     + sbias[warp_n * 64 + d + 32];
                        float x2b = acc[mt][nt + 4][rr * 2 + 1] + sbias[warp_n * 64 + d + 33];
                        float csa = g_rope_cos[s * 32 + d],   sna = g_rope_sin[s * 32 + d];
                        float csb = g_rope_cos[s * 32 + d+1], snb = g_rope_sin[s * 32 + d+1];
                        float y1a = (x1a * csa - x2a * sna) * qs;
                        float y1b = (x1b * csb - x2b * snb) * qs;
                        float y2a = (x2a * csa + x1a * sna) * qs;
                        float y2b = (x2b * csb + x1b * snb) * qs;
                        *(uint32_t*)(dst + rowbase + d)      = pack_h2(y1a, y1b);
                        *(uint32_t*)(dst + rowbase + d + 32) = pack_h2(y2a, y2b);
                    }
                }
            }
        }
    }
}

// ---------------------------------------------------------------------------
// Flash attention (unchanged from R16): SW128 smem, Q reload, P aliased.
// ---------------------------------------------------------------------------
static constexpr uint32_t AQ = 0, AKV = 8192, KVSZ = 16384;
static constexpr uint32_t ATTN_SMEM = AKV + 3 * KVSZ;   // 57344

__global__ __launch_bounds__(128, 4) void attn_mma_kernel()
{
    extern __shared__ char smch[];
    uint32_t sb = smem_to_u32(smch);
    int tid = threadIdx.x;
    int wid = tid >> 5;
    int lane = tid & 31;
    int g = lane >> 2;
    int t2 = (lane & 3) * 2;
    int bh = blockIdx.y;
    int qt = blockIdx.x;

    auto kv_fill = [&](int stage, int kt) {
        uint32_t kb = sb + AKV + (uint32_t)stage * KVSZ;
#pragma unroll
        for (int i = 0; i < 4; i++) {
            int c = i * 128 + tid;
            int row = c >> 3;
            int c8 = c & 7;
            uint32_t doff = SW128((uint32_t)(row * 128 + c8 * 16));
            CP_ASYNC16(kb + doff, g_K + ((size_t)bh * SEQ + kt * 64 + row) * 64 + c8 * 8);
            CP_ASYNC16(kb + 8192 + doff,
                       g_Vt + ((size_t)bh * 64 + row) * SEQ + kt * 64 + c8 * 8);
        }
    };

#pragma unroll
    for (int i = 0; i < 4; i++) {
        int c = i * 128 + tid;
        int row = c >> 3;
        int c8 = c & 7;
        uint32_t doff = SW128((uint32_t)(row * 128 + c8 * 16));
        CP_ASYNC16(sb + AQ + doff,
                   g_Q + ((size_t)bh * SEQ + qt * 64 + row) * 64 + c8 * 8);
    }
    CP_COMMIT();
    kv_fill(0, 0); CP_COMMIT();
    kv_fill(1, 1); CP_COMMIT();
    CP_WAIT2();
    __syncthreads();

    float o[8][4];
#pragma unroll
    for (int nt = 0; nt < 8; nt++)
#pragma unroll
        for (int r = 0; r < 4; r++) o[nt][r] = 0.f;
    float mrow0 = -1e30f, mrow1 = -1e30f;
    float lrow0 = 0.f, lrow1 = 0.f;
    int qrb = wid * 16;

#pragma unroll 1
    for (int kt = 0; kt < 32; kt++) {
        if (kt < 31) CP_WAIT1(); else CP_WAIT0();
        __syncthreads();
        if (kt < 30) {
            kv_fill((kt + 2) % 3, kt + 2);
            CP_COMMIT();
        }

        uint32_t kb = sb + AKV + (uint32_t)(kt % 3) * KVSZ;

        float sacc[8][4];
#pragma unroll
        for (int nt = 0; nt < 8; nt++)
#pragma unroll
            for (int r = 0; r < 4; r++) sacc[nt][r] = 0.f;
#pragma unroll
        for (int kh = 0; kh < 2; kh++) {
            uint32_t qtmp[2][4];
#pragma unroll
            for (int kss = 0; kss < 2; kss++) {
                uint32_t qoff = SW128((uint32_t)((qrb + (lane & 15)) * 128
                               + kh * 64 + kss * 32 + (lane >> 4) * 16));
                ldsm_x4(qtmp[kss], sb + AQ + qoff);
            }
#pragma unroll
            for (int nt = 0; nt < 8; nt++) {
                uint32_t boff = SW128((uint32_t)((nt * 8 + (lane & 7)) * 128
                              + kh * 64 + ((lane >> 3) & 3) * 16));
                uint32_t bf[4];
                ldsm_x4(bf, kb + boff);
#pragma unroll
                for (int kss = 0; kss < 2; kss++)
                    mma_f16(sacc[nt], qtmp[kss], bf[kss * 2], bf[kss * 2 + 1]);
            }
        }

        float a0[8], a1[8];
#pragma unroll
        for (int nt = 0; nt < 8; nt++) {
            a0[nt] = fmaxf(sacc[nt][0], sacc[nt][1]);
            a1[nt] = fmaxf(sacc[nt][2], sacc[nt][3]);
        }
#pragma unroll
        for (int st = 4; st >= 1; st >>= 1)
#pragma unroll
            for (int j = 0; j < st; j++) {
                a0[j] = fmaxf(a0[j], a0[j + st]);
                a1[j] = fmaxf(a1[j], a1[j + st]);
            }
        uint32_t mpk = pack_h2(a0[0], a1[0]);
        mpk = hmax2(mpk, __shfl_xor_sync(0xffffffffu, mpk, 1));
        mpk = hmax2(mpk, __shfl_xor_sync(0xffffffffu, mpk, 2));
        float2 mxf = __half22float2(*(__half2*)&mpk);
        float mn0 = fmaxf(mrow0, mxf.x);
        float mn1 = fmaxf(mrow1, mxf.y);
        float cr0 = exp2f(mrow0 - mn0);
        float cr1 = exp2f(mrow1 - mn1);
        mrow0 = mn0; mrow1 = mn1;

        float ps0 = 0.f, ps1 = 0.f;
#pragma unroll
        for (int nt = 0; nt < 8; nt++) {
            uint32_t p0 = hexp2_x2(pack_h2(sacc[nt][0] - mn0, sacc[nt][1] - mn0));
            uint32_t p1 = hexp2_x2(pack_h2(sacc[nt][2] - mn1, sacc[nt][3] - mn1));
            float2 f0 = __half22float2(*(__half2*)&p0);
            float2 f1 = __half22float2(*(__half2*)&p1);
            ps0 += f0.x + f0.y;
            ps1 += f1.x + f1.y;
            sacc[nt][0] = __uint_as_float(p0);
            sacc[nt][1] = __uint_as_float(p1);
        }
        lrow0 = lrow0 * cr0 + ps0;
        lrow1 = lrow1 * cr1 + ps1;
        if (cr0 < 1.f || cr1 < 1.f) {
#pragma unroll
            for (int nt = 0; nt < 8; nt++) {
                o[nt][0] *= cr0; o[nt][1] *= cr0;
                o[nt][2] *= cr1; o[nt][3] *= cr1;
            }
        }

#pragma unroll
        for (int kh = 0; kh < 2; kh++) {
#pragma unroll
            for (int nt = 0; nt < 8; nt++) {
                uint32_t boff = SW128((uint32_t)((nt * 8 + (lane & 7)) * 128
                              + kh * 64 + ((lane >> 3) & 3) * 16));
                uint32_t vf[4];
                ldsm_x4(vf, kb + 8192 + boff);
#pragma unroll
                for (int kss = 0; kss < 2; kss++) {
                    int ks = kh * 2 + kss;
                    uint32_t aPh[4] = {__float_as_uint(sacc[2 * ks][0]),
                                       __float_as_uint(sacc[2 * ks][1]),
                                       __float_as_uint(sacc[2 * ks + 1][0]),
                                       __float_as_uint(sacc[2 * ks + 1][1])};
                    mma_f16(o[nt], aPh, vf[kss * 2], vf[kss * 2 + 1]);
                }
            }
        }
    }

    lrow0 += __shfl_xor_sync(0xffffffffu, lrow0, 1);
    lrow0 += __shfl_xor_sync(0xffffffffu, lrow0, 2);
    lrow1 += __shfl_xor_sync(0xffffffffu, lrow1, 1);
    lrow1 += __shfl_xor_sync(0xffffffffu, lrow1, 2);
    float inv0 = 1.f / lrow0;
    float inv1 = 1.f / lrow1;
    int b = bh >> 4, h = bh & 15;
    int s0 = qt * 64 + wid * 16 + g;
    int s1 = s0 + 8;
    size_t r0 = ((size_t)b * SEQ + s0) * DMODEL + h * 64;
    size_t r1 = ((size_t)b * SEQ + s1) * DMODEL + h * 64;
#pragma unroll
    for (int nt = 0; nt < 8; nt++) {
        int d0 = nt * 8 + t2;
        *(uint32_t*)(g_attn + r0 + d0) = pack_h2(o[nt][0] * inv0, o[nt][1] * inv0);
        *(uint32_t*)(g_attn + r1 + d0) = pack_h2(o[nt][2] * inv1, o[nt][3] * inv1);
    }
}

// ---------------------------------------------------------------------------
extern "C" void kernel_launch(void* const* d_in, const int* in_sizes, int n_in,
                              void* d_out, int out_size)
{
    const float* query = (const float*)d_in[0];
    const float* W_qkv = (const float*)d_in[1];
    const float* b_qkv = (const float*)d_in[2];
    const float* W_out = (const float*)d_in[3];
    const float* b_out = (const float*)d_in[4];
    float* out = (float*)d_out;

    cudaFuncSetAttribute(mma_gemm_kernel<0>, cudaFuncAttributeMaxDynamicSharedMemorySize, GEMM_SMEM);
    cudaFuncSetAttribute(mma_gemm_kernel<1>, cudaFuncAttributeMaxDynamicSharedMemorySize, GEMM_SMEM);
    cudaFuncSetAttribute(attn_mma_kernel, cudaFuncAttributeMaxDynamicSharedMemorySize, ATTN_SMEM);

    prep_kernel<<<(PREP_TOTAL + 255) / 256, 256>>>(query, W_qkv, W_out);
    {
        dim3 grid(NROWS / 128, QKV_N / 128);   // 64 x 24
        mma_gemm_kernel<0><<<grid, 256, GEMM_SMEM>>>(b_qkv, nullptr);
    }
    {
        dim3 grid(SEQ / 64, BATCH * NHEADS);   // 32 x 64
        attn_mma_kernel<<<grid, 128, ATTN_SMEM>>>();
    }
    // out-projection (launch #4 -> ncu capture slot, clean A/B on BK=64)
    {
        dim3 grid(NROWS / 128, DMODEL / 128);  // 64 x 8
        mma_gemm_kernel<1><<<grid, 256, GEMM_SMEM>>>(b_out, out);
    }
}